// round 4
// baseline (speedup 1.0000x reference)
#include <cuda_runtime.h>
#include <math.h>

#define BB 16
#define NN 1024
#define CC 64
#define CIN 16
#define PADW 132
#define PADN 68

typedef unsigned long long u64;

__device__ __forceinline__ u64 splat2(float v) {
    u64 r; asm("mov.b64 %0, {%1, %1};" : "=l"(r) : "f"(v)); return r;
}
__device__ __forceinline__ void ffma2(u64& d, u64 a, u64 b) {
    asm("fma.rn.f32x2 %0, %1, %2, %0;" : "+l"(d) : "l"(a), "l"(b));
}
__device__ __forceinline__ float2 unpack2(u64 v) {
    float2 r; asm("mov.b64 {%0, %1}, %2;" : "=f"(r.x), "=f"(r.y) : "l"(v)); return r;
}

// 8M x 8N inner step: acc[4][8], A pairs av0/av1, G float4 g0/g1
#define INNER_STEP(ASP, GSP)                                                   \
    {                                                                          \
        ulonglong2 av0 = *(const ulonglong2*)(ASP);                            \
        ulonglong2 av1 = *(const ulonglong2*)((ASP) + 4);                      \
        float4 g0 = *(const float4*)(GSP);                                     \
        float4 g1 = *(const float4*)((GSP) + 4);                               \
        u64 s0=splat2(g0.x), s1=splat2(g0.y), s2=splat2(g0.z), s3=splat2(g0.w);\
        u64 s4=splat2(g1.x), s5=splat2(g1.y), s6=splat2(g1.z), s7=splat2(g1.w);\
        ffma2(acc[0][0],av0.x,s0); ffma2(acc[0][1],av0.x,s1);                  \
        ffma2(acc[0][2],av0.x,s2); ffma2(acc[0][3],av0.x,s3);                  \
        ffma2(acc[0][4],av0.x,s4); ffma2(acc[0][5],av0.x,s5);                  \
        ffma2(acc[0][6],av0.x,s6); ffma2(acc[0][7],av0.x,s7);                  \
        ffma2(acc[1][0],av0.y,s0); ffma2(acc[1][1],av0.y,s1);                  \
        ffma2(acc[1][2],av0.y,s2); ffma2(acc[1][3],av0.y,s3);                  \
        ffma2(acc[1][4],av0.y,s4); ffma2(acc[1][5],av0.y,s5);                  \
        ffma2(acc[1][6],av0.y,s6); ffma2(acc[1][7],av0.y,s7);                  \
        ffma2(acc[2][0],av1.x,s0); ffma2(acc[2][1],av1.x,s1);                  \
        ffma2(acc[2][2],av1.x,s2); ffma2(acc[2][3],av1.x,s3);                  \
        ffma2(acc[2][4],av1.x,s4); ffma2(acc[2][5],av1.x,s5);                  \
        ffma2(acc[2][6],av1.x,s6); ffma2(acc[2][7],av1.x,s7);                  \
        ffma2(acc[3][0],av1.y,s0); ffma2(acc[3][1],av1.y,s1);                  \
        ffma2(acc[3][2],av1.y,s2); ffma2(acc[3][3],av1.y,s3);                  \
        ffma2(acc[3][4],av1.y,s4); ffma2(acc[3][5],av1.y,s5);                  \
        ffma2(acc[3][6],av1.y,s6); ffma2(acc[3][7],av1.y,s7);                  \
    }

// ---------------- static device scratch ----------------
__device__ float g_att [BB*NN*NN];
__device__ float g_gl  [BB*NN*NN];   // unnormalized exp values
__device__ float g_g1  [NN*NN];
__device__ float g_g2  [NN*NN];
__device__ float g_d   [2*NN];
__device__ float g_h0a [BB*CC*NN];
__device__ float g_hT  [BB*CC*NN];
__device__ float g_xuai[BB*CC*NN];
__device__ float g_pa  [BB*CC*NN];   // K-split partial 0
__device__ float g_pb  [BB*CC*NN];   // K-split partial 1
__device__ float g_l12 [BB*2*CC*NN];
__device__ float g_t12 [BB*2*CC*NN];
__device__ float g_u12 [BB*2*CC*NN];
__device__ float g_a12 [BB*2*CC*NN];
__device__ float g_s12x[BB*2*CC*NN];
__device__ float g_s1  [BB*NN];
__device__ float g_s2  [BB*NN];
__device__ float g_sq  [BB*NN];
__device__ float g_part[BB*8*NN];    // gram row-sum partials [b][jblk][i]
__device__ float g_rsinv[BB*NN];
__device__ float g_stats[2*BB*2];

// ---------------- laplacian prep ----------------
__global__ void k_lap_d(const float* __restrict__ graph) {
    int i = blockIdx.x, k = blockIdx.y, t = threadIdx.x;
    const float* row = graph + (size_t)k*NN*NN + (size_t)i*NN;
    float s = 0.f;
    for (int j = t; j < NN; j += 256) s += row[j];
    __shared__ float sh[256];
    sh[t] = s; __syncthreads();
    for (int o = 128; o > 0; o >>= 1) { if (t < o) sh[t] += sh[t+o]; __syncthreads(); }
    if (t == 0) g_d[k*NN + i] = rsqrtf(sh[0] + 1.0f);
}

__global__ void k_lap_scale(const float* __restrict__ graph) {
    __shared__ float tile[32][33];
    int k = blockIdx.z;
    int bx = blockIdx.x * 32, by = blockIdx.y * 32;
    const float* gsrc = graph + (size_t)k*NN*NN;
    for (int r = threadIdx.y; r < 32; r += 8) {
        int row = by + r, col = bx + threadIdx.x;
        float v = gsrc[(size_t)row*NN + col];
        if (row == col) v += 1.f;
        tile[r][threadIdx.x] = v;
    }
    __syncthreads();
    float* gout = (k == 0) ? g_g1 : g_g2;
    const float* d = g_d + k*NN;
    for (int r = threadIdx.y; r < 32; r += 8) {
        int a = bx + r, b_ = by + threadIdx.x;
        gout[(size_t)a*NN + b_] = tile[threadIdx.x][r] * d[a] * d[b_];
    }
}

// ---------------- embedding stage 1 ----------------
__global__ void k_emb1(const float* __restrict__ x, const float* __restrict__ emb_w,
                       const float* __restrict__ emb_b) {
    __shared__ float w[CC*CIN];
    __shared__ float bsm[CC];
    int t = threadIdx.x;
    for (int i = t; i < CC*CIN; i += 256) w[i] = emb_w[i];
    if (t < CC) bsm[t] = emb_b[t];
    __syncthreads();
    int b = blockIdx.x;
    int n = blockIdx.y * 256 + t;
    float xv[CIN];
    const float* xp = x + (size_t)b*CIN*NN + n;
#pragma unroll
    for (int c = 0; c < CIN; c++) xv[c] = xp[(size_t)c*NN];
    float* out = g_h0a + (size_t)b*CC*NN + n;
    for (int e = 0; e < CC; e++) {
        float s = bsm[e];
#pragma unroll
        for (int c = 0; c < CIN; c++) s = fmaf(w[e*CIN + c], xv[c], s);
        out[(size_t)e*NN] = (s > 0.f) ? s : 0.01f*s;
    }
}

// ============ gemmBig: C_z[b,0..127,n] = sum_k A[b,c,k]*G_z[k,n]*rs(k) (+ add) ===
// tile 128M x 64N, 128 threads, 8x8/thread, K=1024. z selects (G0,C0[,rs,add]) / (G1,C1)
__global__ void __launch_bounds__(128)
gemmBig(const float* __restrict__ A,
        const float* __restrict__ G0, size_t gs0, const float* __restrict__ rs0,
        const float* __restrict__ add0,
        const float* __restrict__ G1, size_t gs1,
        float* __restrict__ C0, float* __restrict__ C1) {
    const int b  = blockIdx.y;
    const int n0 = blockIdx.x * 64;
    const int z  = blockIdx.z;
    const float* G = z ? G1 : G0;
    const size_t gs = z ? gs1 : gs0;
    const float* rsb = (!z && rs0) ? rs0 + (size_t)b*NN : nullptr;
    const float* Ab = A + (size_t)b*(2*CC)*NN;
    const float* Gb = G + (size_t)b*gs;
    __shared__ float As[2][16*PADW];
    __shared__ float Gs[2][16*PADN];
    const int tid = threadIdx.x;
    const int tx = tid & 7, ty = tid >> 3;

    const float* Aptr = Ab + (size_t)tid*NN;
    const int gr = tid >> 3, gn = (tid & 7) * 8;
    const float* Gptr = Gb + (size_t)gr*NN + n0 + gn;

    float4 ra0 = *(const float4*)(Aptr);
    float4 ra1 = *(const float4*)(Aptr + 4);
    float4 ra2 = *(const float4*)(Aptr + 8);
    float4 ra3 = *(const float4*)(Aptr + 12);
    float4 rg0 = *(const float4*)(Gptr);
    float4 rg1 = *(const float4*)(Gptr + 4);
    float prs = rsb ? rsb[gr] : 1.f;
    {
        float* as = &As[0][tid];
        as[0*PADW]=ra0.x;  as[1*PADW]=ra0.y;  as[2*PADW]=ra0.z;  as[3*PADW]=ra0.w;
        as[4*PADW]=ra1.x;  as[5*PADW]=ra1.y;  as[6*PADW]=ra1.z;  as[7*PADW]=ra1.w;
        as[8*PADW]=ra2.x;  as[9*PADW]=ra2.y;  as[10*PADW]=ra2.z; as[11*PADW]=ra2.w;
        as[12*PADW]=ra3.x; as[13*PADW]=ra3.y; as[14*PADW]=ra3.z; as[15*PADW]=ra3.w;
        float4 s0 = {rg0.x*prs, rg0.y*prs, rg0.z*prs, rg0.w*prs};
        float4 s1 = {rg1.x*prs, rg1.y*prs, rg1.z*prs, rg1.w*prs};
        *(float4*)&Gs[0][gr*PADN + gn]     = s0;
        *(float4*)&Gs[0][gr*PADN + gn + 4] = s1;
    }
    __syncthreads();

    u64 acc[4][8] = {};
    for (int t = 0; t < 64; ++t) {
        int cur = t & 1;
        if (t < 63) {
            const float* ap = Aptr + (t+1)*16;
            ra0 = *(const float4*)(ap);
            ra1 = *(const float4*)(ap + 4);
            ra2 = *(const float4*)(ap + 8);
            ra3 = *(const float4*)(ap + 12);
            const float* gp = Gptr + (size_t)(t+1)*16*NN;
            rg0 = *(const float4*)(gp);
            rg1 = *(const float4*)(gp + 4);
            if (rsb) prs = rsb[(t+1)*16 + gr];
        }
#pragma unroll
        for (int kk = 0; kk < 16; kk++) {
            const float* arow = &As[cur][kk*PADW + ty*8];
            const float* grow = &Gs[cur][kk*PADN + tx*8];
            INNER_STEP(arow, grow)
        }
        if (t < 63) {
            int nxt = cur ^ 1;
            float* as = &As[nxt][tid];
            as[0*PADW]=ra0.x;  as[1*PADW]=ra0.y;  as[2*PADW]=ra0.z;  as[3*PADW]=ra0.w;
            as[4*PADW]=ra1.x;  as[5*PADW]=ra1.y;  as[6*PADW]=ra1.z;  as[7*PADW]=ra1.w;
            as[8*PADW]=ra2.x;  as[9*PADW]=ra2.y;  as[10*PADW]=ra2.z; as[11*PADW]=ra2.w;
            as[12*PADW]=ra3.x; as[13*PADW]=ra3.y; as[14*PADW]=ra3.z; as[15*PADW]=ra3.w;
            float4 s0 = {rg0.x*prs, rg0.y*prs, rg0.z*prs, rg0.w*prs};
            float4 s1 = {rg1.x*prs, rg1.y*prs, rg1.z*prs, rg1.w*prs};
            *(float4*)&Gs[nxt][gr*PADN + gn]     = s0;
            *(float4*)&Gs[nxt][gr*PADN + gn + 4] = s1;
        }
        __syncthreads();
    }

    float* C = z ? C1 : C0;
    float* Cb = C + (size_t)b*(2*CC)*NN + n0;
    const float* Db = (!z && add0) ? add0 + (size_t)b*(2*CC)*NN + n0 : nullptr;
#pragma unroll
    for (int i = 0; i < 4; i++) {
        int m = ty*8 + 2*i;
        float2 u[8];
#pragma unroll
        for (int j = 0; j < 8; j++) u[j] = unpack2(acc[i][j]);
        float4 lo0 = {u[0].x,u[1].x,u[2].x,u[3].x};
        float4 lo1 = {u[4].x,u[5].x,u[6].x,u[7].x};
        float4 hi0 = {u[0].y,u[1].y,u[2].y,u[3].y};
        float4 hi1 = {u[4].y,u[5].y,u[6].y,u[7].y};
        if (Db) {
            float4 d0 = *(const float4*)(Db + (size_t)m*NN + tx*8);
            float4 d1 = *(const float4*)(Db + (size_t)m*NN + tx*8 + 4);
            float4 d2 = *(const float4*)(Db + (size_t)(m+1)*NN + tx*8);
            float4 d3 = *(const float4*)(Db + (size_t)(m+1)*NN + tx*8 + 4);
            lo0.x+=d0.x; lo0.y+=d0.y; lo0.z+=d0.z; lo0.w+=d0.w;
            lo1.x+=d1.x; lo1.y+=d1.y; lo1.z+=d1.z; lo1.w+=d1.w;
            hi0.x+=d2.x; hi0.y+=d2.y; hi0.z+=d2.z; hi0.w+=d2.w;
            hi1.x+=d3.x; hi1.y+=d3.y; hi1.z+=d3.z; hi1.w+=d3.w;
        }
        *(float4*)(Cb + (size_t)m*NN + tx*8)         = lo0;
        *(float4*)(Cb + (size_t)m*NN + tx*8 + 4)     = lo1;
        *(float4*)(Cb + (size_t)(m+1)*NN + tx*8)     = hi0;
        *(float4*)(Cb + (size_t)(m+1)*NN + tx*8 + 4) = hi1;
    }
}

// ============ gemmT128 (emb2): C_z[bp,c,m] = sum_{n in half z} A[bp,c,n]*W[m,n] (+bias z0)
// M=128 (two stacked batches), tile 128M x 64N, K-split 512 per z.
__global__ void __launch_bounds__(128)
gemmT128(const float* __restrict__ A, const float* __restrict__ W,
         const float* __restrict__ bias, float* __restrict__ C0, float* __restrict__ C1) {
    const int bp = blockIdx.y;
    const int m0 = blockIdx.x * 64;
    const int z  = blockIdx.z;
    const float* Ab = A + (size_t)bp*(2*CC)*NN + z*512;
    __shared__ float As[2][16*PADW];
    __shared__ float Gs[2][16*PADN];
    const int tid = threadIdx.x;
    const int tx = tid & 7, ty = tid >> 3;

    const float* Aptr = Ab + (size_t)tid*NN;
    const int gr = tid >> 1, gk = (tid & 1) * 8;
    const float* Gptr = W + (size_t)(m0 + gr)*NN + z*512 + gk;

    float4 ra0 = *(const float4*)(Aptr);
    float4 ra1 = *(const float4*)(Aptr + 4);
    float4 ra2 = *(const float4*)(Aptr + 8);
    float4 ra3 = *(const float4*)(Aptr + 12);
    float4 rg0 = *(const float4*)(Gptr);
    float4 rg1 = *(const float4*)(Gptr + 4);
    {
        float* as = &As[0][tid];
        as[0*PADW]=ra0.x;  as[1*PADW]=ra0.y;  as[2*PADW]=ra0.z;  as[3*PADW]=ra0.w;
        as[4*PADW]=ra1.x;  as[5*PADW]=ra1.y;  as[6*PADW]=ra1.z;  as[7*PADW]=ra1.w;
        as[8*PADW]=ra2.x;  as[9*PADW]=ra2.y;  as[10*PADW]=ra2.z; as[11*PADW]=ra2.w;
        as[12*PADW]=ra3.x; as[13*PADW]=ra3.y; as[14*PADW]=ra3.z; as[15*PADW]=ra3.w;
        float* gsp = &Gs[0][gk*PADN + gr];
        gsp[0*PADN]=rg0.x; gsp[1*PADN]=rg0.y; gsp[2*PADN]=rg0.z; gsp[3*PADN]=rg0.w;
        gsp[4*PADN]=rg1.x; gsp[5*PADN]=rg1.y; gsp[6*PADN]=rg1.z; gsp[7*PADN]=rg1.w;
    }
    __syncthreads();

    u64 acc[4][8] = {};
    for (int t = 0; t < 32; ++t) {
        int cur = t & 1;
        if (t < 31) {
            const float* ap = Aptr + (t+1)*16;
            ra0 = *(const float4*)(ap);
            ra1 = *(const float4*)(ap + 4);
            ra2 = *(const float4*)(ap + 8);
            ra3 = *(const float4*)(ap + 12);
            const float* gp = Gptr + (t+1)*16;
            rg0 = *(const float4*)(gp);
            rg1 = *(const float4*)(gp + 4);
        }
#pragma unroll
        for (int kk = 0; kk < 16; kk++) {
            const float* arow = &As[cur][kk*PADW + ty*8];
            const float* grow = &Gs[cur][kk*PADN + tx*8];
            INNER_STEP(arow, grow)
        }
        if (t < 31) {
            int nxt = cur ^ 1;
            float* as = &As[nxt][tid];
            as[0*PADW]=ra0.x;  as[1*PADW]=ra0.y;  as[2*PADW]=ra0.z;  as[3*PADW]=ra0.w;
            as[4*PADW]=ra1.x;  as[5*PADW]=ra1.y;  as[6*PADW]=ra1.z;  as[7*PADW]=ra1.w;
            as[8*PADW]=ra2.x;  as[9*PADW]=ra2.y;  as[10*PADW]=ra2.z; as[11*PADW]=ra2.w;
            as[12*PADW]=ra3.x; as[13*PADW]=ra3.y; as[14*PADW]=ra3.z; as[15*PADW]=ra3.w;
            float* gsp = &Gs[nxt][gk*PADN + gr];
            gsp[0*PADN]=rg0.x; gsp[1*PADN]=rg0.y; gsp[2*PADN]=rg0.z; gsp[3*PADN]=rg0.w;
            gsp[4*PADN]=rg1.x; gsp[5*PADN]=rg1.y; gsp[6*PADN]=rg1.z; gsp[7*PADN]=rg1.w;
        }
        __syncthreads();
    }

    float4 bv0 = {0.f,0.f,0.f,0.f}, bv1 = {0.f,0.f,0.f,0.f};
    if (z == 0 && bias) {
        bv0 = *(const float4*)(bias + m0 + tx*8);
        bv1 = *(const float4*)(bias + m0 + tx*8 + 4);
    }
    float* C = z ? C1 : C0;
    float* Cb = C + (size_t)bp*(2*CC)*NN + m0;
#pragma unroll
    for (int i = 0; i < 4; i++) {
        int m = ty*8 + 2*i;
        float2 u[8];
#pragma unroll
        for (int j = 0; j < 8; j++) u[j] = unpack2(acc[i][j]);
        float4 lo0 = {u[0].x+bv0.x, u[1].x+bv0.y, u[2].x+bv0.z, u[3].x+bv0.w};
        float4 lo1 = {u[4].x+bv1.x, u[5].x+bv1.y, u[6].x+bv1.z, u[7].x+bv1.w};
        float4 hi0 = {u[0].y+bv0.x, u[1].y+bv0.y, u[2].y+bv0.z, u[3].y+bv0.w};
        float4 hi1 = {u[4].y+bv1.x, u[5].y+bv1.y, u[6].y+bv1.z, u[7].y+bv1.w};
        *(float4*)(Cb + (size_t)m*NN + tx*8)         = lo0;
        *(float4*)(Cb + (size_t)m*NN + tx*8 + 4)     = lo1;
        *(float4*)(Cb + (size_t)(m+1)*NN + tx*8)     = hi0;
        *(float4*)(Cb + (size_t)(m+1)*NN + tx*8 + 4) = hi1;
    }
}

// ============ gemmT64 (attention): C_z[b,c,n] = sum_{k in half z} hT[b,c,k]*att[b,n,k]
// M=64, tile 64M x 128N, K-split 512 per z.
__global__ void __launch_bounds__(128)
gemmT64(const float* __restrict__ A, const float* __restrict__ G,
        float* __restrict__ C0, float* __restrict__ C1) {
    const int b  = blockIdx.y;
    const int n0 = blockIdx.x * 128;
    const int z  = blockIdx.z;
    const float* Ab = A + (size_t)b*CC*NN + z*512;
    const float* Gb = G + (size_t)b*NN*NN + z*512;
    __shared__ float As[2][16*PADN];
    __shared__ float Gs[2][16*PADW];
    const int tid = threadIdx.x;
    const int tx = tid & 15, ty = tid >> 4;

    const int ar = tid >> 1, ak = (tid & 1) * 8;
    const float* Aptr = Ab + (size_t)ar*NN + ak;
    const float* Gptr = Gb + (size_t)(n0 + tid)*NN;

    float4 ra0 = *(const float4*)(Aptr);
    float4 ra1 = *(const float4*)(Aptr + 4);
    float4 rg0 = *(const float4*)(Gptr);
    float4 rg1 = *(const float4*)(Gptr + 4);
    float4 rg2 = *(const float4*)(Gptr + 8);
    float4 rg3 = *(const float4*)(Gptr + 12);
    {
        float* as = &As[0][ak*PADN + ar];
        as[0*PADN]=ra0.x; as[1*PADN]=ra0.y; as[2*PADN]=ra0.z; as[3*PADN]=ra0.w;
        as[4*PADN]=ra1.x; as[5*PADN]=ra1.y; as[6*PADN]=ra1.z; as[7*PADN]=ra1.w;
        float* gsp = &Gs[0][tid];
        gsp[0*PADW]=rg0.x;  gsp[1*PADW]=rg0.y;  gsp[2*PADW]=rg0.z;  gsp[3*PADW]=rg0.w;
        gsp[4*PADW]=rg1.x;  gsp[5*PADW]=rg1.y;  gsp[6*PADW]=rg1.z;  gsp[7*PADW]=rg1.w;
        gsp[8*PADW]=rg2.x;  gsp[9*PADW]=rg2.y;  gsp[10*PADW]=rg2.z; gsp[11*PADW]=rg2.w;
        gsp[12*PADW]=rg3.x; gsp[13*PADW]=rg3.y; gsp[14*PADW]=rg3.z; gsp[15*PADW]=rg3.w;
    }
    __syncthreads();

    u64 acc[4][8] = {};
    for (int t = 0; t < 32; ++t) {
        int cur = t & 1;
        if (t < 31) {
            const float* ap = Aptr + (t+1)*16;
            ra0 = *(const float4*)(ap);
            ra1 = *(const float4*)(ap + 4);
            const float* gp = Gptr + (t+1)*16;
            rg0 = *(const float4*)(gp);
            rg1 = *(const float4*)(gp + 4);
            rg2 = *(const float4*)(gp + 8);
            rg3 = *(const float4*)(gp + 12);
        }
#pragma unroll
        for (int kk = 0; kk < 16; kk++) {
            const float* arow = &As[cur][kk*PADN + ty*8];
            const float* grow = &Gs[cur][kk*PADW + tx*8];
            INNER_STEP(arow, grow)
        }
        if (t < 31) {
            int nxt = cur ^ 1;
            float* as = &As[nxt][ak*PADN + ar];
            as[0*PADN]=ra0.x; as[1*PADN]=ra0.y; as[2*PADN]=ra0.z; as[3*PADN]=ra0.w;
            as[4*PADN]=ra1.x; as[5*PADN]=ra1.y; as[6*PADN]=ra1.z; as[7*PADN]=ra1.w;
            float* gsp = &Gs[nxt][tid];
            gsp[0*PADW]=rg0.x;  gsp[1*PADW]=rg0.y;  gsp[2*PADW]=rg0.z;  gsp[3*PADW]=rg0.w;
            gsp[4*PADW]=rg1.x;  gsp[5*PADW]=rg1.y;  gsp[6*PADW]=rg1.z;  gsp[7*PADW]=rg1.w;
            gsp[8*PADW]=rg2.x;  gsp[9*PADW]=rg2.y;  gsp[10*PADW]=rg2.z; gsp[11*PADW]=rg2.w;
            gsp[12*PADW]=rg3.x; gsp[13*PADW]=rg3.y; gsp[14*PADW]=rg3.z; gsp[15*PADW]=rg3.w;
        }
        __syncthreads();
    }

    float* C = z ? C1 : C0;
    float* Cb = C + (size_t)b*CC*NN + n0;
#pragma unroll
    for (int i = 0; i < 4; i++) {
        int m = ty*8 + 2*i;
        float2 u[8];
#pragma unroll
        for (int j = 0; j < 8; j++) u[j] = unpack2(acc[i][j]);
        float4 lo0 = {u[0].x,u[1].x,u[2].x,u[3].x};
        float4 lo1 = {u[4].x,u[5].x,u[6].x,u[7].x};
        float4 hi0 = {u[0].y,u[1].y,u[2].y,u[3].y};
        float4 hi1 = {u[4].y,u[5].y,u[6].y,u[7].y};
        *(float4*)(Cb + (size_t)m*NN + tx*8)         = lo0;
        *(float4*)(Cb + (size_t)m*NN + tx*8 + 4)     = lo1;
        *(float4*)(Cb + (size_t)(m+1)*NN + tx*8)     = hi0;
        *(float4*)(Cb + (size_t)(m+1)*NN + tx*8 + 4) = hi1;
    }
}

// ---------------- 64x64 channel mix (dual weight via z, optional 2nd input + relu) ---
__global__ void __launch_bounds__(128)
chanmixD(const float* __restrict__ in, const float* __restrict__ in2, int reluIn,
         size_t inBstride, size_t inZoff,
         const float* __restrict__ Wa, const float* __restrict__ ba,
         const float* __restrict__ Wb, const float* __restrict__ bb_,
         int trans, float* __restrict__ out, size_t outBstride) {
    const int z = blockIdx.z;
    const float* W    = z ? Wb  : Wa;
    const float* bias = z ? bb_ : ba;
    const int b = blockIdx.y, n0 = blockIdx.x * 64;
    __shared__ float Ms[64*PADN];
    __shared__ float Xs[64*PADN];
    const int tid = threadIdx.x;
    for (int i = tid; i < 64*64; i += 128) {
        int o = i >> 6, k = i & 63;
        Ms[k*PADN + o] = trans ? W[k*64 + o] : W[o*64 + k];
    }
    const float* inb  = in + (size_t)b*inBstride + (size_t)z*inZoff + n0;
    const float* inb2 = in2 ? in2 + (size_t)b*inBstride + (size_t)z*inZoff + n0 : nullptr;
    for (int i = tid; i < 64*16; i += 128) {
        int k = i >> 4, n4 = (i & 15) * 4;
        float4 v = *(const float4*)(inb + (size_t)k*NN + n4);
        if (inb2) {
            float4 w2 = *(const float4*)(inb2 + (size_t)k*NN + n4);
            v.x += w2.x; v.y += w2.y; v.z += w2.z; v.w += w2.w;
        }
        if (reluIn) {
            v.x = fmaxf(v.x, 0.f); v.y = fmaxf(v.y, 0.f);
            v.z = fmaxf(v.z, 0.f); v.w = fmaxf(v.w, 0.f);
        }
        *(float4*)&Xs[k*PADN + n4] = v;
    }
    __syncthreads();
    const int tx = tid & 15, ty = tid >> 4;
    u64 acc[4][4] = {};
#pragma unroll 8
    for (int k = 0; k < 64; k++) {
        const float* mrow = &Ms[k*PADN + ty*8];
        ulonglong2 av0 = *(const ulonglong2*)(mrow);
        ulonglong2 av1 = *(const ulonglong2*)(mrow + 4);
        float4 xv = *(const float4*)&Xs[k*PADN + tx*4];
        u64 gs0 = splat2(xv.x), gs1 = splat2(xv.y), gs2 = splat2(xv.z), gs3 = splat2(xv.w);
        ffma2(acc[0][0], av0.x, gs0); ffma2(acc[0][1], av0.x, gs1);
        ffma2(acc[0][2], av0.x, gs2); ffma2(acc[0][3], av0.x, gs3);
        ffma2(acc[1][0], av0.y, gs0); ffma2(acc[1][1], av0.y, gs1);
        ffma2(acc[1][2], av0.y, gs2); ffma2(acc[1][3], av0.y, gs3);
        ffma2(acc[2][0], av1.x, gs0); ffma2(acc[2][1], av1.x, gs1);
        ffma2(acc[2][2], av1.x, gs2); ffma2(acc[2][3], av1.x, gs3);
        ffma2(acc[3][0], av1.y, gs0); ffma2(acc[3][1], av1.y, gs1);
        ffma2(acc[3][2], av1.y, gs2); ffma2(acc[3][3], av1.y, gs3);
    }
    float* outb = out + (size_t)b*outBstride + (size_t)z*CC*NN + n0;
#pragma unroll
    for (int i = 0; i < 4; i++) {
        int o = ty*8 + 2*i;
        float b0 = bias ? bias[o]   : 0.f;
        float b1 = bias ? bias[o+1] : 0.f;
        float2 v0 = unpack2(acc[i][0]), v1 = unpack2(acc[i][1]);
        float2 v2 = unpack2(acc[i][2]), v3 = unpack2(acc[i][3]);
        float4 lo = {v0.x + b0, v1.x + b0, v2.x + b0, v3.x + b0};
        float4 hi = {v0.y + b1, v1.y + b1, v2.y + b1, v3.y + b1};
        *(float4*)(outb + (size_t)o*NN + tx*4) = lo;
        *(float4*)(outb + (size_t)(o+1)*NN + tx*4) = hi;
    }
}

// ---------------- attention scores (rank-1) ----------------
__global__ void k_s12(const float* __restrict__ att_a) {
    __shared__ float a1[64], a2[64];
    int t = threadIdx.x;
    if (t < 64) a1[t] = att_a[t];
    else if (t < 128) a2[t-64] = att_a[t];
    __syncthreads();
    int b = blockIdx.x;
    int i = blockIdx.y * 256 + t;
    const float* h = g_hT + (size_t)b*CC*NN + i;
    float v1 = 0.f, v2 = 0.f;
#pragma unroll 8
    for (int c = 0; c < 64; c++) {
        float hv = h[(size_t)c*NN];
        v1 = fmaf(hv, a1[c], v1);
        v2 = fmaf(hv, a2[c], v2);
    }
    g_s1[b*NN + i] = v1;
    g_s2[b*NN + i] = v2;
}

__global__ void k_attrow() {
    int b = blockIdx.y, i = blockIdx.x, t = threadIdx.x;
    float s1 = g_s1[b*NN + i];
    const float* s2 = g_s2 + b*NN;
    float v[4];
    float mx = -1e30f;
#pragma unroll
    for (int q = 0; q < 4; q++) {
        float e = s1 + s2[t + 256*q];
        e = (e > 0.f) ? e : 0.01f*e;
        v[q] = e;
        mx = fmaxf(mx, e);
    }
    __shared__ float sh[256];
    sh[t] = mx; __syncthreads();
    for (int o = 128; o > 0; o >>= 1) { if (t < o) sh[t] = fmaxf(sh[t], sh[t+o]); __syncthreads(); }
    mx = sh[0]; __syncthreads();
    float sm = 0.f;
#pragma unroll
    for (int q = 0; q < 4; q++) { v[q] = __expf(v[q] - mx); sm += v[q]; }
    sh[t] = sm; __syncthreads();
    for (int o = 128; o > 0; o >>= 1) { if (t < o) sh[t] += sh[t+o]; __syncthreads(); }
    float inv = 1.f / sh[0];
    float* arow = g_att + ((size_t)b*NN + i)*NN;
#pragma unroll
    for (int q = 0; q < 4; q++) arow[t + 256*q] = v[q] * inv;
}

// ---------------- learned adjacency (gram + rbf), with fused row partial sums ------
__global__ void k_sq() {
    int b = blockIdx.x, n = blockIdx.y * 256 + threadIdx.x;
    const float* xp = g_xuai + (size_t)b*CC*NN + n;
    float s = 0.f;
#pragma unroll 8
    for (int c = 0; c < CC; c++) { float v = xp[(size_t)c*NN]; s = fmaf(v, v, s); }
    g_sq[b*NN + n] = s;
}

// tile 64 i x 128 j over K=64 channels. Writes gl (unnormalized) + row partial sums.
__global__ void __launch_bounds__(128)
k_gram() {
    const int b  = blockIdx.z;
    const int i0 = blockIdx.x * 64;
    const int jb = blockIdx.y;
    const int j0 = jb * 128;
    __shared__ float Xi[64*PADN];
    __shared__ float Xj[64*PADW];
    const float* X = g_xuai + (size_t)b*CC*NN;
    const int tid = threadIdx.x;
    {
        int c = tid >> 1, o = (tid & 1) * 32;
        const float* src = X + (size_t)c*NN + i0 + o;
        float* dst = &Xi[c*PADN + o];
#pragma unroll
        for (int q = 0; q < 32; q += 4) *(float4*)(dst+q) = *(const float4*)(src+q);
    }
    {
        int c = tid >> 1, o = (tid & 1) * 64;
        const float* src = X + (size_t)c*NN + j0 + o;
        float* dst = &Xj[c*PADW + o];
#pragma unroll
        for (int q = 0; q < 64; q += 4) *(float4*)(dst+q) = *(const float4*)(src+q);
    }
    __syncthreads();
    const int tx = tid & 15, ty = tid >> 4;
    u64 acc[4][8] = {};
#pragma unroll 8
    for (int kk = 0; kk < 64; kk++) {
        const float* arow = &Xi[kk*PADN + ty*8];
        const float* grow = &Xj[kk*PADW + tx*8];
        INNER_STEP(arow, grow)
    }
    const float* sq = g_sq + b*NN;
    float* glb = g_gl + (size_t)b*NN*NN;
    float rowpart[8];
#pragma unroll
    for (int p = 0; p < 4; p++) {
        int i = i0 + ty*8 + 2*p;
        float sqa = sq[i], sqb = sq[i+1];
        float2 u[8];
#pragma unroll
        for (int j = 0; j < 8; j++) u[j] = unpack2(acc[p][j]);
        float oa[8], ob[8];
        float s0 = 0.f, s1 = 0.f;
#pragma unroll
        for (int q = 0; q < 8; q++) {
            int j = j0 + tx*8 + q;
            float pr0 = u[q].x, pr1 = u[q].y;
            float d2a = fmaxf(sqa + sq[j] - 2.f*pr0, 0.f);
            float va = __expf(__expf(-d2a * (1.f/128.f)) + ((i == j) ? 1.f : 0.f));
            oa[q] = va; s0 += va;
            float d2b = fmaxf(sqb + sq[j] - 2.f*pr1, 0.f);
            float vb = __expf(__expf(-d2b * (1.f/128.f)) + ((i+1 == j) ? 1.f : 0.f));
            ob[q] = vb; s1 += vb;
        }
        rowpart[2*p]   = s0;
        rowpart[2*p+1] = s1;
        float4 a0 = {oa[0],oa[1],oa[2],oa[3]}, a1v = {oa[4],oa[5],oa[6],oa[7]};
        float4 b0 = {ob[0],ob[1],ob[2],ob[3]}, b1v = {ob[4],ob[5],ob[6],ob[7]};
        *(float4*)(glb + (size_t)i*NN + j0 + tx*8)         = a0;
        *(float4*)(glb + (size_t)i*NN + j0 + tx*8 + 4)     = a1v;
        *(float4*)(glb + (size_t)(i+1)*NN + j0 + tx*8)     = b0;
        *(float4*)(glb + (size_t)(i+1)*NN + j0 + tx*8 + 4) = b1v;
    }
    // reduce row partials across the 16 tx lanes (width-16 shuffles)
#pragma unroll
    for (int r = 0; r < 8; r++) {
        float v = rowpart[r];
        v += __shfl_down_sync(0xffffffffu, v, 8, 16);
        v += __shfl_down_sync(0xffffffffu, v, 4, 16);
        v += __shfl_down_sync(0xffffffffu, v, 2, 16);
        v += __shfl_down_sync(0xffffffffu, v, 1, 16);
        if (tx == 0)
            g_part[((size_t)b*8 + jb)*NN + i0 + ty*8 + r] = v;
    }
}

__global__ void k_rsfin() {
    int b = blockIdx.x, i = threadIdx.x;
    float s = 0.f;
#pragma unroll
    for (int j = 0; j < 8; j++) s += g_part[((size_t)b*8 + j)*NN + i];
    g_rsinv[b*NN + i] = 1.f / s;
}

// ---------------- layernorm stats + final fuse ----------------
__global__ void k_lnstats() {
    int b = blockIdx.x, path = blockIdx.y, t = threadIdx.x;
    const float* z = g_s12x + (size_t)b*(2*CC)*NN + (size_t)path*CC*NN;
    float s = 0.f, ss = 0.f;
    for (int i = t; i < CC*NN; i += 1024) { float v = z[i]; s += v; ss = fmaf(v, v, ss); }
    __shared__ float shs[1024], shq[1024];
    shs[t] = s; shq[t] = ss; __syncthreads();
    for (int o = 512; o > 0; o >>= 1) {
        if (t < o) { shs[t] += shs[t+o]; shq[t] += shq[t+o]; }
        __syncthreads();
    }
    if (t == 0) {
        float mean = shs[0] * (1.f/65536.f);
        float var  = shq[0] * (1.f/65536.f) - mean*mean;
        g_stats[(path*BB + b)*2 + 0] = mean;
        g_stats[(path*BB + b)*2 + 1] = rsqrtf(var + 1e-5f);
    }
}

__global__ void k_final(const float* __restrict__ ct, const float* __restrict__ ln_w,
                        const float* __restrict__ ln_b, float* __restrict__ out) {
    size_t idx = (size_t)blockIdx.x * 256 + threadIdx.x;
    int b  = (int)(idx / (CC*NN));
    int cn = (int)(idx % (CC*NN));
    float m1 = g_stats[b*2 + 0],            r1 = g_stats[b*2 + 1];
    float m2 = g_stats[(BB + b)*2 + 0],     r2 = g_stats[(BB + b)*2 + 1];
    float w = ln_w[cn], bb = ln_b[cn];
    size_t base = (size_t)b*(2*CC)*NN + cn;
    float xnew = (g_s12x[base]                 - m1) * r1 * w + bb;
    float z2   = (g_s12x[base + (size_t)CC*NN] - m2) * r2 * w + bb;
    float ft = 0.5f * z2 * (1.f + erff(z2 * 0.70710678118654752f));
    float ctv = ct[idx];
    float ctn = xnew + ft * (ctv - xnew);
    float el  = (ctn > 0.f) ? ctn : expm1f(ctn);
    float xu  = g_xuai[idx];
    float ht  = xu + ft * (el - xu);
    out[idx] = ht;
    out[(size_t)BB*CC*NN + idx] = ctn;
}

// ---------------- host launch ----------------
struct DevPtrs {
    float *att, *gl, *g1, *g2, *h0a, *hT, *xuai, *pa, *pb;
    float *l12, *t12, *u12, *a12, *s12x, *rsinv;
    bool init;
};
static DevPtrs P = {};

static void init_ptrs() {
    if (P.init) return;
    void* p;
#define GET(sym, field) cudaGetSymbolAddress(&p, sym); P.field = (float*)p;
    GET(g_att, att)  GET(g_gl, gl)   GET(g_g1, g1)   GET(g_g2, g2)
    GET(g_h0a, h0a)  GET(g_hT, hT)   GET(g_xuai, xuai)
    GET(g_pa, pa)    GET(g_pb, pb)
    GET(g_l12, l12)  GET(g_t12, t12) GET(g_u12, u12)
    GET(g_a12, a12)  GET(g_s12x, s12x) GET(g_rsinv, rsinv)
#undef GET
    P.init = true;
}

extern "C" void kernel_launch(void* const* d_in, const int* in_sizes, int n_in,
                              void* d_out, int out_size) {
    const float* x      = (const float*)d_in[0];
    const float* ct     = (const float*)d_in[1];
    const float* graph  = (const float*)d_in[2];
    const float* emb_w  = (const float*)d_in[3];
    const float* emb_b  = (const float*)d_in[4];
    const float* emb2_w = (const float*)d_in[5];
    const float* emb2_b = (const float*)d_in[6];
    const float* att_W  = (const float*)d_in[7];
    const float* att_a  = (const float*)d_in[8];
    // d_in[9] = att_GL : unused (softmax output strictly positive => mask no-op)
    const float* uai_w  = (const float*)d_in[10];
    const float* uai_b  = (const float*)d_in[11];
    const float* lin1_w = (const float*)d_in[12];
    const float* lin2_w = (const float*)d_in[13];
    const float* lin2_b = (const float*)d_in[14];
    const float* ln_w   = (const float*)d_in[15];
    const float* ln_b   = (const float*)d_in[16];
    float* out = (float*)d_out;

    init_ptrs();

    const size_t GSTRIDE = (size_t)NN * NN;
    const size_t SB = (size_t)CC*NN;
    const size_t DB = (size_t)2*CC*NN;
    const dim3 gridC1(NN/64, BB, 1);
    const dim3 gridC2(NN/64, BB, 2);

    // graph laplacians
    k_lap_d    <<<dim3(NN, 2), 256>>>(graph);
    k_lap_scale<<<dim3(32, 32, 2), dim3(32, 8)>>>(graph);

    // embedding: conv1d+leakyrelu, then node-linear (M-stacked, K-split -> pa/pb)
    k_emb1  <<<dim3(BB, NN/256), 256>>>(x, emb_w, emb_b);
    gemmT128<<<dim3(NN/64, BB/2, 2), 128>>>(P.h0a, emb2_w, emb2_b, P.pa, P.pb);

    // attention: hT = attW^T @ (pa+pb), scores, softmax, att@h (K-split -> pa/pb)
    chanmixD<<<gridC1, 128>>>(P.pa, P.pb, 0, SB, 0, att_W, nullptr, att_W, nullptr, 1, P.hT, SB);
    k_s12   <<<dim3(BB, NN/256), 256>>>(att_a);
    k_attrow<<<dim3(NN, BB), 256>>>();
    gemmT64 <<<dim3(NN/128, BB, 2), 128>>>(P.hT, P.att, P.pa, P.pb);

    // UAI: xuai = uai_w @ relu(pa+pb) + uai_b
    chanmixD<<<gridC1, 128>>>(P.pa, P.pb, 1, SB, 0, uai_w, uai_b, uai_w, uai_b, 0, P.xuai, SB);

    // learned adjacency gl (unnormalized) + row-sum inverses (fused partials)
    k_sq   <<<dim3(BB, NN/256), 256>>>();
    k_gram <<<dim3(NN/64, NN/128, BB), 128>>>();
    k_rsfin<<<BB, 1024>>>();

    // l1/l2 stacked propagation
    chanmixD<<<gridC2, 128>>>(P.xuai, nullptr, 0, SB, 0, lin1_w, nullptr, lin2_w, lin2_b, 0, P.l12, DB);

    // pair: z=0 -> l12 @ (gl * rsinv) -> a12 ; z=1 -> l12 @ g1 -> t12
    gemmBig<<<dim3(NN/64, BB, 2), 128>>>(P.l12, P.gl, GSTRIDE, P.rsinv, nullptr,
                                         P.g1, 0, P.a12, P.t12);

    chanmixD<<<gridC2, 128>>>(P.t12, nullptr, 0, DB, SB, lin1_w, nullptr, lin2_w, lin2_b, 0, P.u12, DB);

    // final: u12 @ g2 + a12 -> s12x
    gemmBig<<<dim3(NN/64, BB, 1), 128>>>(P.u12, P.g2, 0, nullptr, P.a12,
                                         nullptr, 0, P.s12x, nullptr);

    // layernorm + gates + output
    k_lnstats<<<dim3(BB, 2), 1024>>>();
    k_final  <<<(BB*CC*NN)/256, 256>>>(ct, ln_w, ln_b, out);
}

// round 5
// speedup vs baseline: 1.0698x; 1.0698x over previous
#include <cuda_runtime.h>
#include <math.h>

#define BB 16
#define NN 1024
#define CC 64
#define CIN 16
#define PADW 132
#define PADN 68

typedef unsigned long long u64;

__device__ __forceinline__ u64 splat2(float v) {
    u64 r; asm("mov.b64 %0, {%1, %1};" : "=l"(r) : "f"(v)); return r;
}
__device__ __forceinline__ void ffma2(u64& d, u64 a, u64 b) {
    asm("fma.rn.f32x2 %0, %1, %2, %0;" : "+l"(d) : "l"(a), "l"(b));
}
__device__ __forceinline__ float2 unpack2(u64 v) {
    float2 r; asm("mov.b64 {%0, %1}, %2;" : "=f"(r.x), "=f"(r.y) : "l"(v)); return r;
}

// 8M x 8N inner step: acc[4][8]
#define INNER_STEP(ASP, GSP)                                                   \
    {                                                                          \
        ulonglong2 av0 = *(const ulonglong2*)(ASP);                            \
        ulonglong2 av1 = *(const ulonglong2*)((ASP) + 4);                      \
        float4 g0 = *(const float4*)(GSP);                                     \
        float4 g1 = *(const float4*)((GSP) + 4);                               \
        u64 s0=splat2(g0.x), s1=splat2(g0.y), s2=splat2(g0.z), s3=splat2(g0.w);\
        u64 s4=splat2(g1.x), s5=splat2(g1.y), s6=splat2(g1.z), s7=splat2(g1.w);\
        ffma2(acc[0][0],av0.x,s0); ffma2(acc[0][1],av0.x,s1);                  \
        ffma2(acc[0][2],av0.x,s2); ffma2(acc[0][3],av0.x,s3);                  \
        ffma2(acc[0][4],av0.x,s4); ffma2(acc[0][5],av0.x,s5);                  \
        ffma2(acc[0][6],av0.x,s6); ffma2(acc[0][7],av0.x,s7);                  \
        ffma2(acc[1][0],av0.y,s0); ffma2(acc[1][1],av0.y,s1);                  \
        ffma2(acc[1][2],av0.y,s2); ffma2(acc[1][3],av0.y,s3);                  \
        ffma2(acc[1][4],av0.y,s4); ffma2(acc[1][5],av0.y,s5);                  \
        ffma2(acc[1][6],av0.y,s6); ffma2(acc[1][7],av0.y,s7);                  \
        ffma2(acc[2][0],av1.x,s0); ffma2(acc[2][1],av1.x,s1);                  \
        ffma2(acc[2][2],av1.x,s2); ffma2(acc[2][3],av1.x,s3);                  \
        ffma2(acc[2][4],av1.x,s4); ffma2(acc[2][5],av1.x,s5);                  \
        ffma2(acc[2][6],av1.x,s6); ffma2(acc[2][7],av1.x,s7);                  \
        ffma2(acc[3][0],av1.y,s0); ffma2(acc[3][1],av1.y,s1);                  \
        ffma2(acc[3][2],av1.y,s2); ffma2(acc[3][3],av1.y,s3);                  \
        ffma2(acc[3][4],av1.y,s4); ffma2(acc[3][5],av1.y,s5);                  \
        ffma2(acc[3][6],av1.y,s6); ffma2(acc[3][7],av1.y,s7);                  \
    }

// ---------------- static device scratch ----------------
__device__ float g_att [BB*NN*NN];
__device__ float g_gl  [BB*NN*NN];
__device__ float g_g1  [NN*NN];
__device__ float g_g2  [NN*NN];
__device__ float g_d   [2*NN];
__device__ float g_h0a [BB*CC*NN];
__device__ float g_hT  [BB*CC*NN];
__device__ float g_xuai[BB*CC*NN];
__device__ float g_pa  [BB*CC*NN];
__device__ float g_pb  [BB*CC*NN];
__device__ float g_pc  [BB*CC*NN];
__device__ float g_pd  [BB*CC*NN];
__device__ float g_l12 [BB*2*CC*NN];
__device__ float g_t12a[BB*2*CC*NN];
__device__ float g_t12b[BB*2*CC*NN];
__device__ float g_u12 [BB*2*CC*NN];
__device__ float g_a12a[BB*2*CC*NN];
__device__ float g_a12b[BB*2*CC*NN];
__device__ float g_sxa [BB*2*CC*NN];
__device__ float g_sxb [BB*2*CC*NN];
__device__ float g_s1  [BB*NN];
__device__ float g_s2  [BB*NN];
__device__ float g_sq  [BB*NN];
__device__ float g_part[BB*8*NN];
__device__ float g_rsinv[BB*NN];
__device__ float g_stats[2*BB*2];

// ---------------- laplacian prep ----------------
__global__ void k_lap_d(const float* __restrict__ graph) {
    int i = blockIdx.x, k = blockIdx.y, t = threadIdx.x;
    const float* row = graph + (size_t)k*NN*NN + (size_t)i*NN;
    float s = 0.f;
    for (int j = t; j < NN; j += 256) s += row[j];
    __shared__ float sh[256];
    sh[t] = s; __syncthreads();
    for (int o = 128; o > 0; o >>= 1) { if (t < o) sh[t] += sh[t+o]; __syncthreads(); }
    if (t == 0) g_d[k*NN + i] = rsqrtf(sh[0] + 1.0f);
}

__global__ void k_lap_scale(const float* __restrict__ graph) {
    __shared__ float tile[32][33];
    int k = blockIdx.z;
    int bx = blockIdx.x * 32, by = blockIdx.y * 32;
    const float* gsrc = graph + (size_t)k*NN*NN;
    for (int r = threadIdx.y; r < 32; r += 8) {
        int row = by + r, col = bx + threadIdx.x;
        float v = gsrc[(size_t)row*NN + col];
        if (row == col) v += 1.f;
        tile[r][threadIdx.x] = v;
    }
    __syncthreads();
    float* gout = (k == 0) ? g_g1 : g_g2;
    const float* d = g_d + k*NN;
    for (int r = threadIdx.y; r < 32; r += 8) {
        int a = bx + r, b_ = by + threadIdx.x;
        gout[(size_t)a*NN + b_] = tile[threadIdx.x][r] * d[a] * d[b_];
    }
}

// ---------------- embedding stage 1 ----------------
__global__ void k_emb1(const float* __restrict__ x, const float* __restrict__ emb_w,
                       const float* __restrict__ emb_b) {
    __shared__ float w[CC*CIN];
    __shared__ float bsm[CC];
    int t = threadIdx.x;
    for (int i = t; i < CC*CIN; i += 256) w[i] = emb_w[i];
    if (t < CC) bsm[t] = emb_b[t];
    __syncthreads();
    int b = blockIdx.x;
    int n = blockIdx.y * 256 + t;
    float xv[CIN];
    const float* xp = x + (size_t)b*CIN*NN + n;
#pragma unroll
    for (int c = 0; c < CIN; c++) xv[c] = xp[(size_t)c*NN];
    float* out = g_h0a + (size_t)b*CC*NN + n;
    for (int e = 0; e < CC; e++) {
        float s = bsm[e];
#pragma unroll
        for (int c = 0; c < CIN; c++) s = fmaf(w[e*CIN + c], xv[c], s);
        out[(size_t)e*NN] = (s > 0.f) ? s : 0.01f*s;
    }
}

// ============ gemmBig: 128M x 64N tiles, K-split 2, up to 2 units =================
// blockIdx.z: unit = z>>1, ks = z&1 (K range ks*512..+512)
// unit0: G0 (opt rsinv row-scale, opt per-ks addend) -> C0a/C0b
// unit1: G1 -> C1a/C1b
__global__ void __launch_bounds__(128, 4)
gemmBig(const float* __restrict__ A,
        const float* __restrict__ G0, size_t gs0, const float* __restrict__ rs0,
        const float* __restrict__ add0a, const float* __restrict__ add0b,
        const float* __restrict__ G1, size_t gs1,
        float* __restrict__ C0a, float* __restrict__ C0b,
        float* __restrict__ C1a, float* __restrict__ C1b) {
    const int b  = blockIdx.y;
    const int n0 = blockIdx.x * 64;
    const int unit = blockIdx.z >> 1;
    const int ks   = blockIdx.z & 1;
    const int k0   = ks * 512;
    const float* G = unit ? G1 : G0;
    const size_t gs = unit ? gs1 : gs0;
    const float* rsb = (!unit && rs0) ? rs0 + (size_t)b*NN + k0 : nullptr;
    const float* Ab = A + (size_t)b*(2*CC)*NN + k0;
    const float* Gb = G + (size_t)b*gs + (size_t)k0*NN;
    __shared__ float As[2][16*PADW];
    __shared__ float Gs[2][16*PADN];
    const int tid = threadIdx.x;
    const int tx = tid & 7, ty = tid >> 3;

    const float* Aptr = Ab + (size_t)tid*NN;
    const int gr = tid >> 3, gn = (tid & 7) * 8;
    const float* Gptr = Gb + (size_t)gr*NN + n0 + gn;

    float4 ra0 = *(const float4*)(Aptr);
    float4 ra1 = *(const float4*)(Aptr + 4);
    float4 ra2 = *(const float4*)(Aptr + 8);
    float4 ra3 = *(const float4*)(Aptr + 12);
    float4 rg0 = *(const float4*)(Gptr);
    float4 rg1 = *(const float4*)(Gptr + 4);
    float prs = rsb ? rsb[gr] : 1.f;
    {
        float* as = &As[0][tid];
        as[0*PADW]=ra0.x;  as[1*PADW]=ra0.y;  as[2*PADW]=ra0.z;  as[3*PADW]=ra0.w;
        as[4*PADW]=ra1.x;  as[5*PADW]=ra1.y;  as[6*PADW]=ra1.z;  as[7*PADW]=ra1.w;
        as[8*PADW]=ra2.x;  as[9*PADW]=ra2.y;  as[10*PADW]=ra2.z; as[11*PADW]=ra2.w;
        as[12*PADW]=ra3.x; as[13*PADW]=ra3.y; as[14*PADW]=ra3.z; as[15*PADW]=ra3.w;
        float4 s0 = {rg0.x*prs, rg0.y*prs, rg0.z*prs, rg0.w*prs};
        float4 s1 = {rg1.x*prs, rg1.y*prs, rg1.z*prs, rg1.w*prs};
        *(float4*)&Gs[0][gr*PADN + gn]     = s0;
        *(float4*)&Gs[0][gr*PADN + gn + 4] = s1;
    }
    __syncthreads();

    u64 acc[4][8] = {};
    for (int t = 0; t < 32; ++t) {
        int cur = t & 1;
        if (t < 31) {
            const float* ap = Aptr + (t+1)*16;
            ra0 = *(const float4*)(ap);
            ra1 = *(const float4*)(ap + 4);
            ra2 = *(const float4*)(ap + 8);
            ra3 = *(const float4*)(ap + 12);
            const float* gp = Gptr + (size_t)(t+1)*16*NN;
            rg0 = *(const float4*)(gp);
            rg1 = *(const float4*)(gp + 4);
            if (rsb) prs = rsb[(t+1)*16 + gr];
        }
#pragma unroll
        for (int kk = 0; kk < 16; kk++) {
            const float* arow = &As[cur][kk*PADW + ty*8];
            const float* grow = &Gs[cur][kk*PADN + tx*8];
            INNER_STEP(arow, grow)
        }
        if (t < 31) {
            int nxt = cur ^ 1;
            float* as = &As[nxt][tid];
            as[0*PADW]=ra0.x;  as[1*PADW]=ra0.y;  as[2*PADW]=ra0.z;  as[3*PADW]=ra0.w;
            as[4*PADW]=ra1.x;  as[5*PADW]=ra1.y;  as[6*PADW]=ra1.z;  as[7*PADW]=ra1.w;
            as[8*PADW]=ra2.x;  as[9*PADW]=ra2.y;  as[10*PADW]=ra2.z; as[11*PADW]=ra2.w;
            as[12*PADW]=ra3.x; as[13*PADW]=ra3.y; as[14*PADW]=ra3.z; as[15*PADW]=ra3.w;
            float4 s0 = {rg0.x*prs, rg0.y*prs, rg0.z*prs, rg0.w*prs};
            float4 s1 = {rg1.x*prs, rg1.y*prs, rg1.z*prs, rg1.w*prs};
            *(float4*)&Gs[nxt][gr*PADN + gn]     = s0;
            *(float4*)&Gs[nxt][gr*PADN + gn + 4] = s1;
        }
        __syncthreads();
    }

    float* C = unit ? (ks ? C1b : C1a) : (ks ? C0b : C0a);
    const float* add = (!unit) ? (ks ? add0b : add0a) : nullptr;
    float* Cb = C + (size_t)b*(2*CC)*NN + n0;
    const float* Db = add ? add + (size_t)b*(2*CC)*NN + n0 : nullptr;
#pragma unroll
    for (int i = 0; i < 4; i++) {
        int m = ty*8 + 2*i;
        float2 u[8];
#pragma unroll
        for (int j = 0; j < 8; j++) u[j] = unpack2(acc[i][j]);
        float4 lo0 = {u[0].x,u[1].x,u[2].x,u[3].x};
        float4 lo1 = {u[4].x,u[5].x,u[6].x,u[7].x};
        float4 hi0 = {u[0].y,u[1].y,u[2].y,u[3].y};
        float4 hi1 = {u[4].y,u[5].y,u[6].y,u[7].y};
        if (Db) {
            float4 d0 = *(const float4*)(Db + (size_t)m*NN + tx*8);
            float4 d1 = *(const float4*)(Db + (size_t)m*NN + tx*8 + 4);
            float4 d2 = *(const float4*)(Db + (size_t)(m+1)*NN + tx*8);
            float4 d3 = *(const float4*)(Db + (size_t)(m+1)*NN + tx*8 + 4);
            lo0.x+=d0.x; lo0.y+=d0.y; lo0.z+=d0.z; lo0.w+=d0.w;
            lo1.x+=d1.x; lo1.y+=d1.y; lo1.z+=d1.z; lo1.w+=d1.w;
            hi0.x+=d2.x; hi0.y+=d2.y; hi0.z+=d2.z; hi0.w+=d2.w;
            hi1.x+=d3.x; hi1.y+=d3.y; hi1.z+=d3.z; hi1.w+=d3.w;
        }
        *(float4*)(Cb + (size_t)m*NN + tx*8)         = lo0;
        *(float4*)(Cb + (size_t)m*NN + tx*8 + 4)     = lo1;
        *(float4*)(Cb + (size_t)(m+1)*NN + tx*8)     = hi0;
        *(float4*)(Cb + (size_t)(m+1)*NN + tx*8 + 4) = hi1;
    }
}

// ============ gemmT128 (emb2): M=128 (2 stacked batches), K-split 4 ===============
__global__ void __launch_bounds__(128, 4)
gemmT128(const float* __restrict__ A, const float* __restrict__ W,
         const float* __restrict__ bias,
         float* __restrict__ C0, float* __restrict__ C1,
         float* __restrict__ C2, float* __restrict__ C3) {
    const int bp = blockIdx.y;
    const int m0 = blockIdx.x * 64;
    const int ks = blockIdx.z;
    const int k0 = ks * 256;
    const float* Ab = A + (size_t)bp*(2*CC)*NN + k0;
    __shared__ float As[2][16*PADW];
    __shared__ float Gs[2][16*PADN];
    const int tid = threadIdx.x;
    const int tx = tid & 7, ty = tid >> 3;

    const float* Aptr = Ab + (size_t)tid*NN;
    const int gr = tid >> 1, gk = (tid & 1) * 8;
    const float* Gptr = W + (size_t)(m0 + gr)*NN + k0 + gk;

    float4 ra0 = *(const float4*)(Aptr);
    float4 ra1 = *(const float4*)(Aptr + 4);
    float4 ra2 = *(const float4*)(Aptr + 8);
    float4 ra3 = *(const float4*)(Aptr + 12);
    float4 rg0 = *(const float4*)(Gptr);
    float4 rg1 = *(const float4*)(Gptr + 4);
    {
        float* as = &As[0][tid];
        as[0*PADW]=ra0.x;  as[1*PADW]=ra0.y;  as[2*PADW]=ra0.z;  as[3*PADW]=ra0.w;
        as[4*PADW]=ra1.x;  as[5*PADW]=ra1.y;  as[6*PADW]=ra1.z;  as[7*PADW]=ra1.w;
        as[8*PADW]=ra2.x;  as[9*PADW]=ra2.y;  as[10*PADW]=ra2.z; as[11*PADW]=ra2.w;
        as[12*PADW]=ra3.x; as[13*PADW]=ra3.y; as[14*PADW]=ra3.z; as[15*PADW]=ra3.w;
        float* gsp = &Gs[0][gk*PADN + gr];
        gsp[0*PADN]=rg0.x; gsp[1*PADN]=rg0.y; gsp[2*PADN]=rg0.z; gsp[3*PADN]=rg0.w;
        gsp[4*PADN]=rg1.x; gsp[5*PADN]=rg1.y; gsp[6*PADN]=rg1.z; gsp[7*PADN]=rg1.w;
    }
    __syncthreads();

    u64 acc[4][8] = {};
    for (int t = 0; t < 16; ++t) {
        int cur = t & 1;
        if (t < 15) {
            const float* ap = Aptr + (t+1)*16;
            ra0 = *(const float4*)(ap);
            ra1 = *(const float4*)(ap + 4);
            ra2 = *(const float4*)(ap + 8);
            ra3 = *(const float4*)(ap + 12);
            const float* gp = Gptr + (t+1)*16;
            rg0 = *(const float4*)(gp);
            rg1 = *(const float4*)(gp + 4);
        }
#pragma unroll
        for (int kk = 0; kk < 16; kk++) {
            const float* arow = &As[cur][kk*PADW + ty*8];
            const float* grow = &Gs[cur][kk*PADN + tx*8];
            INNER_STEP(arow, grow)
        }
        if (t < 15) {
            int nxt = cur ^ 1;
            float* as = &As[nxt][tid];
            as[0*PADW]=ra0.x;  as[1*PADW]=ra0.y;  as[2*PADW]=ra0.z;  as[3*PADW]=ra0.w;
            as[4*PADW]=ra1.x;  as[5*PADW]=ra1.y;  as[6*PADW]=ra1.z;  as[7*PADW]=ra1.w;
            as[8*PADW]=ra2.x;  as[9*PADW]=ra2.y;  as[10*PADW]=ra2.z; as[11*PADW]=ra2.w;
            as[12*PADW]=ra3.x; as[13*PADW]=ra3.y; as[14*PADW]=ra3.z; as[15*PADW]=ra3.w;
            float* gsp = &Gs[nxt][gk*PADN + gr];
            gsp[0*PADN]=rg0.x; gsp[1*PADN]=rg0.y; gsp[2*PADN]=rg0.z; gsp[3*PADN]=rg0.w;
            gsp[4*PADN]=rg1.x; gsp[5*PADN]=rg1.y; gsp[6*PADN]=rg1.z; gsp[7*PADN]=rg1.w;
        }
        __syncthreads();
    }

    float4 bv0 = {0.f,0.f,0.f,0.f}, bv1 = {0.f,0.f,0.f,0.f};
    if (ks == 0 && bias) {
        bv0 = *(const float4*)(bias + m0 + tx*8);
        bv1 = *(const float4*)(bias + m0 + tx*8 + 4);
    }
    float* C = (ks == 0) ? C0 : (ks == 1) ? C1 : (ks == 2) ? C2 : C3;
    float* Cb = C + (size_t)bp*(2*CC)*NN + m0;
#pragma unroll
    for (int i = 0; i < 4; i++) {
        int m = ty*8 + 2*i;
        float2 u[8];
#pragma unroll
        for (int j = 0; j < 8; j++) u[j] = unpack2(acc[i][j]);
        float4 lo0 = {u[0].x+bv0.x, u[1].x+bv0.y, u[2].x+bv0.z, u[3].x+bv0.w};
        float4 lo1 = {u[4].x+bv1.x, u[5].x+bv1.y, u[6].x+bv1.z, u[7].x+bv1.w};
        float4 hi0 = {u[0].y+bv0.x, u[1].y+bv0.y, u[2].y+bv0.z, u[3].y+bv0.w};
        float4 hi1 = {u[4].y+bv1.x, u[5].y+bv1.y, u[6].y+bv1.z, u[7].y+bv1.w};
        *(float4*)(Cb + (size_t)m*NN + tx*8)         = lo0;
        *(float4*)(Cb + (size_t)m*NN + tx*8 + 4)     = lo1;
        *(float4*)(Cb + (size_t)(m+1)*NN + tx*8)     = hi0;
        *(float4*)(Cb + (size_t)(m+1)*NN + tx*8 + 4) = hi1;
    }
}

// ============ gemmT64 (attention): M=64, 64M x 128N tiles, K-split 4 ==============
__global__ void __launch_bounds__(128, 4)
gemmT64(const float* __restrict__ A, const float* __restrict__ G,
        float* __restrict__ C0, float* __restrict__ C1,
        float* __restrict__ C2, float* __restrict__ C3) {
    const int b  = blockIdx.y;
    const int n0 = blockIdx.x * 128;
    const int ks = blockIdx.z;
    const int k0 = ks * 256;
    const float* Ab = A + (size_t)b*CC*NN + k0;
    const float* Gb = G + (size_t)b*NN*NN + k0;
    __shared__ float As[2][16*PADN];
    __shared__ float Gs[2][16*PADW];
    const int tid = threadIdx.x;
    const int tx = tid & 15, ty = tid >> 4;

    const int ar = tid >> 1, ak = (tid & 1) * 8;
    const float* Aptr = Ab + (size_t)ar*NN + ak;
    const float* Gptr = Gb + (size_t)(n0 + tid)*NN;

    float4 ra0 = *(const float4*)(Aptr);
    float4 ra1 = *(const float4*)(Aptr + 4);
    float4 rg0 = *(const float4*)(Gptr);
    float4 rg1 = *(const float4*)(Gptr + 4);
    float4 rg2 = *(const float4*)(Gptr + 8);
    float4 rg3 = *(const float4*)(Gptr + 12);
    {
        float* as = &As[0][ak*PADN + ar];
        as[0*PADN]=ra0.x; as[1*PADN]=ra0.y; as[2*PADN]=ra0.z; as[3*PADN]=ra0.w;
        as[4*PADN]=ra1.x; as[5*PADN]=ra1.y; as[6*PADN]=ra1.z; as[7*PADN]=ra1.w;
        float* gsp = &Gs[0][tid];
        gsp[0*PADW]=rg0.x;  gsp[1*PADW]=rg0.y;  gsp[2*PADW]=rg0.z;  gsp[3*PADW]=rg0.w;
        gsp[4*PADW]=rg1.x;  gsp[5*PADW]=rg1.y;  gsp[6*PADW]=rg1.z;  gsp[7*PADW]=rg1.w;
        gsp[8*PADW]=rg2.x;  gsp[9*PADW]=rg2.y;  gsp[10*PADW]=rg2.z; gsp[11*PADW]=rg2.w;
        gsp[12*PADW]=rg3.x; gsp[13*PADW]=rg3.y; gsp[14*PADW]=rg3.z; gsp[15*PADW]=rg3.w;
    }
    __syncthreads();

    u64 acc[4][8] = {};
    for (int t = 0; t < 16; ++t) {
        int cur = t & 1;
        if (t < 15) {
            const float* ap = Aptr + (t+1)*16;
            ra0 = *(const float4*)(ap);
            ra1 = *(const float4*)(ap + 4);
            const float* gp = Gptr + (t+1)*16;
            rg0 = *(const float4*)(gp);
            rg1 = *(const float4*)(gp + 4);
            rg2 = *(const float4*)(gp + 8);
            rg3 = *(const float4*)(gp + 12);
        }
#pragma unroll
        for (int kk = 0; kk < 16; kk++) {
            const float* arow = &As[cur][kk*PADN + ty*8];
            const float* grow = &Gs[cur][kk*PADW + tx*8];
            INNER_STEP(arow, grow)
        }
        if (t < 15) {
            int nxt = cur ^ 1;
            float* as = &As[nxt][ak*PADN + ar];
            as[0*PADN]=ra0.x; as[1*PADN]=ra0.y; as[2*PADN]=ra0.z; as[3*PADN]=ra0.w;
            as[4*PADN]=ra1.x; as[5*PADN]=ra1.y; as[6*PADN]=ra1.z; as[7*PADN]=ra1.w;
            float* gsp = &Gs[nxt][tid];
            gsp[0*PADW]=rg0.x;  gsp[1*PADW]=rg0.y;  gsp[2*PADW]=rg0.z;  gsp[3*PADW]=rg0.w;
            gsp[4*PADW]=rg1.x;  gsp[5*PADW]=rg1.y;  gsp[6*PADW]=rg1.z;  gsp[7*PADW]=rg1.w;
            gsp[8*PADW]=rg2.x;  gsp[9*PADW]=rg2.y;  gsp[10*PADW]=rg2.z; gsp[11*PADW]=rg2.w;
            gsp[12*PADW]=rg3.x; gsp[13*PADW]=rg3.y; gsp[14*PADW]=rg3.z; gsp[15*PADW]=rg3.w;
        }
        __syncthreads();
    }

    float* C = (ks == 0) ? C0 : (ks == 1) ? C1 : (ks == 2) ? C2 : C3;
    float* Cb = C + (size_t)b*CC*NN + n0;
#pragma unroll
    for (int i = 0; i < 4; i++) {
        int m = ty*8 + 2*i;
        float2 u[8];
#pragma unroll
        for (int j = 0; j < 8; j++) u[j] = unpack2(acc[i][j]);
        float4 lo0 = {u[0].x,u[1].x,u[2].x,u[3].x};
        float4 lo1 = {u[4].x,u[5].x,u[6].x,u[7].x};
        float4 hi0 = {u[0].y,u[1].y,u[2].y,u[3].y};
        float4 hi1 = {u[4].y,u[5].y,u[6].y,u[7].y};
        *(float4*)(Cb + (size_t)m*NN + tx*8)         = lo0;
        *(float4*)(Cb + (size_t)m*NN + tx*8 + 4)     = lo1;
        *(float4*)(Cb + (size_t)(m+1)*NN + tx*8)     = hi0;
        *(float4*)(Cb + (size_t)(m+1)*NN + tx*8 + 4) = hi1;
    }
}

// ---------------- 64x64 channel mix (dual weight via z, up to 4 summed inputs) -----
__global__ void __launch_bounds__(128)
chanmixD(const float* __restrict__ in, const float* __restrict__ in2,
         const float* __restrict__ in3, const float* __restrict__ in4,
         int reluIn, size_t inBstride, size_t inZoff,
         const float* __restrict__ Wa, const float* __restrict__ ba,
         const float* __restrict__ Wb, const float* __restrict__ bb_,
         int trans, float* __restrict__ out, size_t outBstride) {
    const int z = blockIdx.z;
    const float* W    = z ? Wb  : Wa;
    const float* bias = z ? bb_ : ba;
    const int b = blockIdx.y, n0 = blockIdx.x * 64;
    __shared__ float Ms[64*PADN];
    __shared__ float Xs[64*PADN];
    const int tid = threadIdx.x;
    for (int i = tid; i < 64*64; i += 128) {
        int o = i >> 6, k = i & 63;
        Ms[k*PADN + o] = trans ? W[k*64 + o] : W[o*64 + k];
    }
    const size_t boff = (size_t)b*inBstride + (size_t)z*inZoff + n0;
    for (int i = tid; i < 64*16; i += 128) {
        int k = i >> 4, n4 = (i & 15) * 4;
        size_t off = boff + (size_t)k*NN + n4;
        float4 v = *(const float4*)(in + off);
        if (in2) { float4 w2 = *(const float4*)(in2 + off); v.x+=w2.x; v.y+=w2.y; v.z+=w2.z; v.w+=w2.w; }
        if (in3) { float4 w3 = *(const float4*)(in3 + off); v.x+=w3.x; v.y+=w3.y; v.z+=w3.z; v.w+=w3.w; }
        if (in4) { float4 w4 = *(const float4*)(in4 + off); v.x+=w4.x; v.y+=w4.y; v.z+=w4.z; v.w+=w4.w; }
        if (reluIn) {
            v.x = fmaxf(v.x, 0.f); v.y = fmaxf(v.y, 0.f);
            v.z = fmaxf(v.z, 0.f); v.w = fmaxf(v.w, 0.f);
        }
        *(float4*)&Xs[k*PADN + n4] = v;
    }
    __syncthreads();
    const int tx = tid & 15, ty = tid >> 4;
    u64 acc[4][4] = {};
#pragma unroll 8
    for (int k = 0; k < 64; k++) {
        const float* mrow = &Ms[k*PADN + ty*8];
        ulonglong2 av0 = *(const ulonglong2*)(mrow);
        ulonglong2 av1 = *(const ulonglong2*)(mrow + 4);
        float4 xv = *(const float4*)&Xs[k*PADN + tx*4];
        u64 gs0 = splat2(xv.x), gs1 = splat2(xv.y), gs2 = splat2(xv.z), gs3 = splat2(xv.w);
        ffma2(acc[0][0], av0.x, gs0); ffma2(acc[0][1], av0.x, gs1);
        ffma2(acc[0][2], av0.x, gs2); ffma2(acc[0][3], av0.x, gs3);
        ffma2(acc[1][0], av0.y, gs0); ffma2(acc[1][1], av0.y, gs1);
        ffma2(acc[1][2], av0.y, gs2); ffma2(acc[1][3], av0.y, gs3);
        ffma2(acc[2][0], av1.x, gs0); ffma2(acc[2][1], av1.x, gs1);
        ffma2(acc[2][2], av1.x, gs2); ffma2(acc[2][3], av1.x, gs3);
        ffma2(acc[3][0], av1.y, gs0); ffma2(acc[3][1], av1.y, gs1);
        ffma2(acc[3][2], av1.y, gs2); ffma2(acc[3][3], av1.y, gs3);
    }
    float* outb = out + (size_t)b*outBstride + (size_t)z*CC*NN + n0;
#pragma unroll
    for (int i = 0; i < 4; i++) {
        int o = ty*8 + 2*i;
        float b0 = bias ? bias[o]   : 0.f;
        float b1 = bias ? bias[o+1] : 0.f;
        float2 v0 = unpack2(acc[i][0]), v1 = unpack2(acc[i][1]);
        float2 v2 = unpack2(acc[i][2]), v3 = unpack2(acc[i][3]);
        float4 lo = {v0.x + b0, v1.x + b0, v2.x + b0, v3.x + b0};
        float4 hi = {v0.y + b1, v1.y + b1, v2.y + b1, v3.y + b1};
        *(float4*)(outb + (size_t)o*NN + tx*4) = lo;
        *(float4*)(outb + (size_t)(o+1)*NN + tx*4) = hi;
    }
}

// ---------------- attention scores (rank-1) ----------------
__global__ void k_s12(const float* __restrict__ att_a) {
    __shared__ float a1[64], a2[64];
    int t = threadIdx.x;
    if (t < 64) a1[t] = att_a[t];
    else if (t < 128) a2[t-64] = att_a[t];
    __syncthreads();
    int b = blockIdx.x;
    int i = blockIdx.y * 256 + t;
    const float* h = g_hT + (size_t)b*CC*NN + i;
    float v1 = 0.f, v2 = 0.f;
#pragma unroll 8
    for (int c = 0; c < 64; c++) {
        float hv = h[(size_t)c*NN];
        v1 = fmaf(hv, a1[c], v1);
        v2 = fmaf(hv, a2[c], v2);
    }
    g_s1[b*NN + i] = v1;
    g_s2[b*NN + i] = v2;
}

__global__ void k_attrow() {
    int b = blockIdx.y, i = blockIdx.x, t = threadIdx.x;
    float s1 = g_s1[b*NN + i];
    const float* s2 = g_s2 + b*NN;
    float v[4];
    float mx = -1e30f;
#pragma unroll
    for (int q = 0; q < 4; q++) {
        float e = s1 + s2[t + 256*q];
        e = (e > 0.f) ? e : 0.01f*e;
        v[q] = e;
        mx = fmaxf(mx, e);
    }
    __shared__ float sh[256];
    sh[t] = mx; __syncthreads();
    for (int o = 128; o > 0; o >>= 1) { if (t < o) sh[t] = fmaxf(sh[t], sh[t+o]); __syncthreads(); }
    mx = sh[0]; __syncthreads();
    float sm = 0.f;
#pragma unroll
    for (int q = 0; q < 4; q++) { v[q] = __expf(v[q] - mx); sm += v[q]; }
    sh[t] = sm; __syncthreads();
    for (int o = 128; o > 0; o >>= 1) { if (t < o) sh[t] += sh[t+o]; __syncthreads(); }
    float inv = 1.f / sh[0];
    float* arow = g_att + ((size_t)b*NN + i)*NN;
#pragma unroll
    for (int q = 0; q < 4; q++) arow[t + 256*q] = v[q] * inv;
}

// ---------------- learned adjacency (gram + rbf) ----------------
__global__ void k_sq() {
    int b = blockIdx.x, n = blockIdx.y * 256 + threadIdx.x;
    const float* xp = g_xuai + (size_t)b*CC*NN + n;
    float s = 0.f;
#pragma unroll 8
    for (int c = 0; c < CC; c++) { float v = xp[(size_t)c*NN]; s = fmaf(v, v, s); }
    g_sq[b*NN + n] = s;
}

__global__ void __launch_bounds__(128)
k_gram() {
    const int b  = blockIdx.z;
    const int i0 = blockIdx.x * 64;
    const int jb = blockIdx.y;
    const int j0 = jb * 128;
    __shared__ float Xi[64*PADN];
    __shared__ float Xj[64*PADW];
    const float* X = g_xuai + (size_t)b*CC*NN;
    const int tid = threadIdx.x;
    {
        int c = tid >> 1, o = (tid & 1) * 32;
        const float* src = X + (size_t)c*NN + i0 + o;
        float* dst = &Xi[c*PADN + o];
#pragma unroll
        for (int q = 0; q < 32; q += 4) *(float4*)(dst+q) = *(const float4*)(src+q);
    }
    {
        int c = tid >> 1, o = (tid & 1) * 64;
        const float* src = X + (size_t)c*NN + j0 + o;
        float* dst = &Xj[c*PADW + o];
#pragma unroll
        for (int q = 0; q < 64; q += 4) *(float4*)(dst+q) = *(const float4*)(src+q);
    }
    __syncthreads();
    const int tx = tid & 15, ty = tid >> 4;
    u64 acc[4][8] = {};
#pragma unroll 8
    for (int kk = 0; kk < 64; kk++) {
        const float* arow = &Xi[kk*PADN + ty*8];
        const float* grow = &Xj[kk*PADW + tx*8];
        INNER_STEP(arow, grow)
    }
    const float* sq = g_sq + b*NN;
    float* glb = g_gl + (size_t)b*NN*NN;
    float rowpart[8];
#pragma unroll
    for (int p = 0; p < 4; p++) {
        int i = i0 + ty*8 + 2*p;
        float sqa = sq[i], sqb = sq[i+1];
        float2 u[8];
#pragma unroll
        for (int j = 0; j < 8; j++) u[j] = unpack2(acc[p][j]);
        float oa[8], ob[8];
        float s0 = 0.f, s1 = 0.f;
#pragma unroll
        for (int q = 0; q < 8; q++) {
            int j = j0 + tx*8 + q;
            float d2a = fmaxf(sqa + sq[j] - 2.f*u[q].x, 0.f);
            float va = __expf(__expf(-d2a * (1.f/128.f)) + ((i == j) ? 1.f : 0.f));
            oa[q] = va; s0 += va;
            float d2b = fmaxf(sqb + sq[j] - 2.f*u[q].y, 0.f);
            float vb = __expf(__expf(-d2b * (1.f/128.f)) + ((i+1 == j) ? 1.f : 0.f));
            ob[q] = vb; s1 += vb;
        }
        rowpart[2*p]   = s0;
        rowpart[2*p+1] = s1;
        float4 a0 = {oa[0],oa[1],oa[2],oa[3]}, a1v = {oa[4],oa[5],oa[6],oa[7]};
        float4 b0 = {ob[0],ob[1],ob[2],ob[3]}, b1v = {ob[4],ob[5],ob[6],ob[7]};
        *(float4*)(glb + (size_t)i*NN + j0 + tx*8)         = a0;
        *(float4*)(glb + (size_t)i*NN + j0 + tx*8 + 4)     = a1v;
        *(float4*)(glb + (size_t)(i+1)*NN + j0 + tx*8)     = b0;
        *(float4*)(glb + (size_t)(i+1)*NN + j0 + tx*8 + 4) = b1v;
    }
#pragma unroll
    for (int r = 0; r < 8; r++) {
        float v = rowpart[r];
        v += __shfl_down_sync(0xffffffffu, v, 8, 16);
        v += __shfl_down_sync(0xffffffffu, v, 4, 16);
        v += __shfl_down_sync(0xffffffffu, v, 2, 16);
        v += __shfl_down_sync(0xffffffffu, v, 1, 16);
        if (tx == 0)
            g_part[((size_t)b*8 + jb)*NN + i0 + ty*8 + r] = v;
    }
}

__global__ void k_rsfin() {
    int b = blockIdx.x, i = threadIdx.x;
    float s = 0.f;
#pragma unroll
    for (int j = 0; j < 8; j++) s += g_part[((size_t)b*8 + j)*NN + i];
    g_rsinv[b*NN + i] = 1.f / s;
}

// ---------------- layernorm stats + final fuse ----------------
__global__ void k_lnstats() {
    int b = blockIdx.x, path = blockIdx.y, t = threadIdx.x;
    size_t base = (size_t)b*(2*CC)*NN + (size_t)path*CC*NN;
    float s = 0.f, ss = 0.f;
    for (int i = t; i < CC*NN; i += 1024) {
        float v = g_sxa[base + i] + g_sxb[base + i];
        s += v; ss = fmaf(v, v, ss);
    }
    __shared__ float shs[1024], shq[1024];
    shs[t] = s; shq[t] = ss; __syncthreads();
    for (int o = 512; o > 0; o >>= 1) {
        if (t < o) { shs[t] += shs[t+o]; shq[t] += shq[t+o]; }
        __syncthreads();
    }
    if (t == 0) {
        float mean = shs[0] * (1.f/65536.f);
        float var  = shq[0] * (1.f/65536.f) - mean*mean;
        g_stats[(path*BB + b)*2 + 0] = mean;
        g_stats[(path*BB + b)*2 + 1] = rsqrtf(var + 1e-5f);
    }
}

__global__ void k_final(const float* __restrict__ ct, const float* __restrict__ ln_w,
                        const float* __restrict__ ln_b, float* __restrict__ out) {
    size_t idx = (size_t)blockIdx.x * 256 + threadIdx.x;
    int b  = (int)(idx / (CC*NN));
    int cn = (int)(idx % (CC*NN));
    float m1 = g_stats[b*2 + 0],            r1 = g_stats[b*2 + 1];
    float m2 = g_stats[(BB + b)*2 + 0],     r2 = g_stats[(BB + b)*2 + 1];
    float w = ln_w[cn], bb = ln_b[cn];
    size_t base = (size_t)b*(2*CC)*NN + cn;
    float z1v = g_sxa[base] + g_sxb[base];
    float z2v = g_sxa[base + (size_t)CC*NN] + g_sxb[base + (size_t)CC*NN];
    float xnew = (z1v - m1) * r1 * w + bb;
    float z2   = (z2v - m2) * r2 * w + bb;
    float ft = 0.5f * z2 * (1.f + erff(z2 * 0.70710678118654752f));
    float ctv = ct[idx];
    float ctn = xnew + ft * (ctv - xnew);
    float el  = (ctn > 0.f) ? ctn : expm1f(ctn);
    float xu  = g_xuai[idx];
    float ht  = xu + ft * (el - xu);
    out[idx] = ht;
    out[(size_t)BB*CC*NN + idx] = ctn;
}

// ---------------- host launch ----------------
struct DevPtrs {
    float *att, *gl, *g1, *g2, *h0a, *hT, *xuai;
    float *pa, *pb, *pc, *pd;
    float *l12, *t12a, *t12b, *u12, *a12a, *a12b, *sxa, *sxb, *rsinv;
    bool init;
};
static DevPtrs P = {};

static void init_ptrs() {
    if (P.init) return;
    void* p;
#define GET(sym, field) cudaGetSymbolAddress(&p, sym); P.field = (float*)p;
    GET(g_att, att)  GET(g_gl, gl)   GET(g_g1, g1)   GET(g_g2, g2)
    GET(g_h0a, h0a)  GET(g_hT, hT)   GET(g_xuai, xuai)
    GET(g_pa, pa)    GET(g_pb, pb)   GET(g_pc, pc)   GET(g_pd, pd)
    GET(g_l12, l12)  GET(g_t12a, t12a) GET(g_t12b, t12b) GET(g_u12, u12)
    GET(g_a12a, a12a) GET(g_a12b, a12b) GET(g_sxa, sxa) GET(g_sxb, sxb)
    GET(g_rsinv, rsinv)
#undef GET
    P.init = true;
}

extern "C" void kernel_launch(void* const* d_in, const int* in_sizes, int n_in,
                              void* d_out, int out_size) {
    const float* x      = (const float*)d_in[0];
    const float* ct     = (const float*)d_in[1];
    const float* graph  = (const float*)d_in[2];
    const float* emb_w  = (const float*)d_in[3];
    const float* emb_b  = (const float*)d_in[4];
    const float* emb2_w = (const float*)d_in[5];
    const float* emb2_b = (const float*)d_in[6];
    const float* att_W  = (const float*)d_in[7];
    const float* att_a  = (const float*)d_in[8];
    // d_in[9] = att_GL : unused (softmax output strictly positive => mask no-op)
    const float* uai_w  = (const float*)d_in[10];
    const float* uai_b  = (const float*)d_in[11];
    const float* lin1_w = (const float*)d_in[12];
    const float* lin2_w = (const float*)d_in[13];
    const float* lin2_b = (const float*)d_in[14];
    const float* ln_w   = (const float*)d_in[15];
    const float* ln_b   = (const float*)d_in[16];
    float* out = (float*)d_out;

    init_ptrs();

    const size_t GSTRIDE = (size_t)NN * NN;
    const size_t SB = (size_t)CC*NN;
    const size_t DB = (size_t)2*CC*NN;
    const dim3 gridC1(NN/64, BB, 1);
    const dim3 gridC2(NN/64, BB, 2);

    // graph laplacians
    k_lap_d    <<<dim3(NN, 2), 256>>>(graph);
    k_lap_scale<<<dim3(32, 32, 2), dim3(32, 8)>>>(graph);

    // embedding: conv1d+leakyrelu, then node-linear (M-stacked, K-split 4)
    k_emb1  <<<dim3(BB, NN/256), 256>>>(x, emb_w, emb_b);
    gemmT128<<<dim3(NN/64, BB/2, 4), 128>>>(P.h0a, emb2_w, emb2_b, P.pa, P.pb, P.pc, P.pd);

    // attention
    chanmixD<<<gridC1, 128>>>(P.pa, P.pb, P.pc, P.pd, 0, SB, 0,
                              att_W, nullptr, att_W, nullptr, 1, P.hT, SB);
    k_s12   <<<dim3(BB, NN/256), 256>>>(att_a);
    k_attrow<<<dim3(NN, BB), 256>>>();
    gemmT64 <<<dim3(NN/128, BB, 4), 128>>>(P.hT, P.att, P.pa, P.pb, P.pc, P.pd);

    // UAI: xuai = uai_w @ relu(pa+pb+pc+pd) + uai_b
    chanmixD<<<gridC1, 128>>>(P.pa, P.pb, P.pc, P.pd, 1, SB, 0,
                              uai_w, uai_b, uai_w, uai_b, 0, P.xuai, SB);

    // learned adjacency gl + row-sum inverses
    k_sq   <<<dim3(BB, NN/256), 256>>>();
    k_gram <<<dim3(NN/64, NN/128, BB), 128>>>();
    k_rsfin<<<BB, 1024>>>();

    // l1/l2 stacked propagation
    chanmixD<<<gridC2, 128>>>(P.xuai, nullptr, nullptr, nullptr, 0, SB, 0,
                              lin1_w, nullptr, lin2_w, lin2_b, 0, P.l12, DB);

    // unit0: l12 @ (gl*rsinv) -> a12a/a12b ; unit1: l12 @ g1 -> t12a/t12b
    gemmBig<<<dim3(NN/64, BB, 4), 128>>>(P.l12, P.gl, GSTRIDE, P.rsinv, nullptr, nullptr,
                                         P.g1, 0, P.a12a, P.a12b, P.t12a, P.t12b);

    chanmixD<<<gridC2, 128>>>(P.t12a, P.t12b, nullptr, nullptr, 0, DB, SB,
                              lin1_w, nullptr, lin2_w, lin2_b, 0, P.u12, DB);

    // u12 @ g2 (+ a12 split addends) -> sxa/sxb
    gemmBig<<<dim3(NN/64, BB, 2), 128>>>(P.u12, P.g2, 0, nullptr, P.a12a, P.a12b,
                                         nullptr, 0, P.sxa, P.sxb, nullptr, nullptr);

    // layernorm + gates + output
    k_lnstats<<<dim3(BB, 2), 1024>>>();
    k_final  <<<(BB*CC*NN)/256, 256>>>(ct, ln_w, ln_b, out);
}

// round 7
// speedup vs baseline: 1.7435x; 1.6297x over previous
#include <cuda_runtime.h>
#include <math.h>
#include <stdint.h>

#define BB 16
#define NN 1024
#define CC 64
#define CIN 16
#define PADN 68
#define PADW 132

typedef unsigned long long u64;

// ---------------- fp32x2 helpers (remaining CUDA-core kernels) ----------------
__device__ __forceinline__ u64 splat2(float v) {
    u64 r; asm("mov.b64 %0, {%1, %1};" : "=l"(r) : "f"(v)); return r;
}
__device__ __forceinline__ void ffma2(u64& d, u64 a, u64 b) {
    asm("fma.rn.f32x2 %0, %1, %2, %0;" : "+l"(d) : "l"(a), "l"(b));
}
__device__ __forceinline__ float2 unpack2(u64 v) {
    float2 r; asm("mov.b64 {%0, %1}, %2;" : "=f"(r.x), "=f"(r.y) : "l"(v)); return r;
}

#define INNER_STEP(ASP, GSP)                                                   \
    {                                                                          \
        ulonglong2 av0 = *(const ulonglong2*)(ASP);                            \
        ulonglong2 av1 = *(const ulonglong2*)((ASP) + 4);                      \
        float4 g0 = *(const float4*)(GSP);                                     \
        float4 g1 = *(const float4*)((GSP) + 4);                               \
        u64 s0=splat2(g0.x), s1=splat2(g0.y), s2=splat2(g0.z), s3=splat2(g0.w);\
        u64 s4=splat2(g1.x), s5=splat2(g1.y), s6=splat2(g1.z), s7=splat2(g1.w);\
        ffma2(acc[0][0],av0.x,s0); ffma2(acc[0][1],av0.x,s1);                  \
        ffma2(acc[0][2],av0.x,s2); ffma2(acc[0][3],av0.x,s3);                  \
        ffma2(acc[0][4],av0.x,s4); ffma2(acc[0][5],av0.x,s5);                  \
        ffma2(acc[0][6],av0.x,s6); ffma2(acc[0][7],av0.x,s7);                  \
        ffma2(acc[1][0],av0.y,s0); ffma2(acc[1][1],av0.y,s1);                  \
        ffma2(acc[1][2],av0.y,s2); ffma2(acc[1][3],av0.y,s3);                  \
        ffma2(acc[1][4],av0.y,s4); ffma2(acc[1][5],av0.y,s5);                  \
        ffma2(acc[1][6],av0.y,s6); ffma2(acc[1][7],av0.y,s7);                  \
        ffma2(acc[2][0],av1.x,s0); ffma2(acc[2][1],av1.x,s1);                  \
        ffma2(acc[2][2],av1.x,s2); ffma2(acc[2][3],av1.x,s3);                  \
        ffma2(acc[2][4],av1.x,s4); ffma2(acc[2][5],av1.x,s5);                  \
        ffma2(acc[2][6],av1.x,s6); ffma2(acc[2][7],av1.x,s7);                  \
        ffma2(acc[3][0],av1.y,s0); ffma2(acc[3][1],av1.y,s1);                  \
        ffma2(acc[3][2],av1.y,s2); ffma2(acc[3][3],av1.y,s3);                  \
        ffma2(acc[3][4],av1.y,s4); ffma2(acc[3][5],av1.y,s5);                  \
        ffma2(acc[3][6],av1.y,s6); ffma2(acc[3][7],av1.y,s7);                  \
    }

// ---------------- mma.sync tf32 helpers (sm_80 baseline PTX — compiles for compute_103) ---
__device__ __forceinline__ uint32_t smem_u32(const void* p) {
    uint32_t a;
    asm("{ .reg .u64 t; cvta.to.shared.u64 t, %1; cvt.u32.u64 %0, t; }" : "=r"(a) : "l"(p));
    return a;
}
__device__ __forceinline__ uint32_t f2tf32(float f) {
    uint32_t r; asm("cvt.rna.tf32.f32 %0, %1;" : "=r"(r) : "f"(f)); return r;
}
#define LDSM4(r0, r1, r2, r3, addr)                                            \
    asm volatile("ldmatrix.sync.aligned.m8n8.x4.shared.b16 {%0,%1,%2,%3}, [%4];" \
        : "=r"(r0), "=r"(r1), "=r"(r2), "=r"(r3) : "r"(addr))
#define MMA_TF32(c, a0, a1, a2, a3, b0, b1)                                    \
    asm volatile("mma.sync.aligned.m16n8k8.row.col.f32.tf32.tf32.f32 "         \
        "{%0,%1,%2,%3}, {%4,%5,%6,%7}, {%8,%9}, {%0,%1,%2,%3};"                \
        : "+f"((c)[0]), "+f"((c)[1]), "+f"((c)[2]), "+f"((c)[3])               \
        : "r"(a0), "r"(a1), "r"(a2), "r"(a3), "r"(b0), "r"(b1))

// ---------------- static device scratch ----------------
__device__ float g_att [BB*NN*NN];
__device__ float g_gl  [BB*NN*NN];   // unnormalized, symmetric
__device__ float g_g1  [NN*NN];      // K-major laplacian: B[n,k]
__device__ float g_g2  [NN*NN];
__device__ float g_d   [2*NN];
__device__ float g_h0a [BB*CC*NN];
__device__ float g_hT  [BB*CC*NN];
__device__ float g_xuai[BB*CC*NN];
__device__ float g_pa  [BB*CC*NN];
__device__ float g_pb  [BB*CC*NN];
__device__ float g_l12 [BB*2*CC*NN];
__device__ float g_t12a[BB*2*CC*NN];
__device__ float g_t12b[BB*2*CC*NN];
__device__ float g_u12 [BB*2*CC*NN];
__device__ float g_a12a[BB*2*CC*NN];
__device__ float g_a12b[BB*2*CC*NN];
__device__ float g_sxa [BB*2*CC*NN];
__device__ float g_sxb [BB*2*CC*NN];
__device__ float g_s1  [BB*NN];
__device__ float g_s2  [BB*NN];
__device__ float g_sq  [BB*NN];
__device__ float g_part[BB*8*NN];
__device__ float g_rsinv[BB*NN];
__device__ float g_stats[2*BB*2];

// =========================================================================
// mma_gemm (tf32 tensor cores): C_ks[b,c,n] = sum_{k in half ks} A[b,c,k]*B[b,n,k]
// block tile 128M x 128N, warp tile 64x32 (2x4 warps), K-step 16, K-split 2 (z).
// optional: colScale[k] on B, per-ks addend, biasN[n] (ks==0 only).
// =========================================================================
#define TPAD 20   // row stride in 32-bit words for 16-k tiles
__global__ void __launch_bounds__(256)
mma_gemm(const float* __restrict__ A, size_t aBatch, int mvalid,
         const float* __restrict__ B, size_t bBatch,
         const float* __restrict__ colScale, size_t csBatch,
         const float* __restrict__ add0, const float* __restrict__ add1,
         const float* __restrict__ biasN,
         float* __restrict__ C0, float* __restrict__ C1, size_t cBatch)
{
    __shared__ uint32_t As[2][128*TPAD];
    __shared__ uint32_t Bs[2][128*TPAD];

    const int tid  = threadIdx.x;
    const int lane = tid & 31;
    const int wid  = tid >> 5;
    const int bidx = blockIdx.y;
    const int n0   = blockIdx.x * 128;
    const int ks   = blockIdx.z;
    const int k0b  = ks * 512;

    const float* Ab = A + (size_t)bidx * aBatch + k0b;
    const float* Bb = B + (size_t)bidx * bBatch + (size_t)n0 * NN + k0b;
    const float* cs = colScale ? colScale + (size_t)bidx * csBatch + k0b : nullptr;

    // global-fill indexing: 2 float4 per thread per operand per tile
    const int frow0 = tid >> 2;            // 0..63
    const int frow1 = 64 + (tid >> 2);     // 64..127
    const int fkq   = (tid & 3) * 4;

    const uint32_t aSm = smem_u32(&As[0][0]);
    const uint32_t bSm = smem_u32(&Bs[0][0]);

    // ldmatrix per-thread row offsets (in words)
    const int aRowOff = (lane & 15) * TPAD + (lane >> 4) * 4;
    const int bRowOff = ((lane >> 4) * 8 + (lane & 7)) * TPAD + ((lane >> 3) & 1) * 4;

    const int warp_m = wid >> 2;           // 0..1 -> m base 0/64
    const int warp_n = wid & 3;            // 0..3 -> n base 0/32/64/96
    const int mbase = warp_m * 64;
    const int nbase = warp_n * 32;

    float c[4][4][4];
#pragma unroll
    for (int i = 0; i < 4; i++)
#pragma unroll
        for (int j = 0; j < 4; j++)
#pragma unroll
            for (int q = 0; q < 4; q++) c[i][j][q] = 0.f;

    float4 pa0, pa1, pb0, pb1, psc = {1.f,1.f,1.f,1.f};
    // prefetch tile 0
    {
        pa0 = *(const float4*)(Ab + (size_t)frow0 * NN + fkq);
        pa1 = (frow1 < mvalid) ? *(const float4*)(Ab + (size_t)frow1 * NN + fkq)
                               : make_float4(0.f, 0.f, 0.f, 0.f);
        pb0 = *(const float4*)(Bb + (size_t)frow0 * NN + fkq);
        pb1 = *(const float4*)(Bb + (size_t)frow1 * NN + fkq);
        if (cs) psc = *(const float4*)(cs + fkq);
    }
    // store tile 0 into buf 0
    {
        uint4 wa0 = { f2tf32(pa0.x), f2tf32(pa0.y), f2tf32(pa0.z), f2tf32(pa0.w) };
        uint4 wa1 = { f2tf32(pa1.x), f2tf32(pa1.y), f2tf32(pa1.z), f2tf32(pa1.w) };
        float4 sb0 = pb0, sb1 = pb1;
        if (cs) {
            sb0.x*=psc.x; sb0.y*=psc.y; sb0.z*=psc.z; sb0.w*=psc.w;
            sb1.x*=psc.x; sb1.y*=psc.y; sb1.z*=psc.z; sb1.w*=psc.w;
        }
        uint4 wb0 = { f2tf32(sb0.x), f2tf32(sb0.y), f2tf32(sb0.z), f2tf32(sb0.w) };
        uint4 wb1 = { f2tf32(sb1.x), f2tf32(sb1.y), f2tf32(sb1.z), f2tf32(sb1.w) };
        *(uint4*)&As[0][frow0*TPAD + fkq] = wa0;
        *(uint4*)&As[0][frow1*TPAD + fkq] = wa1;
        *(uint4*)&Bs[0][frow0*TPAD + fkq] = wb0;
        *(uint4*)&Bs[0][frow1*TPAD + fkq] = wb1;
    }
    __syncthreads();

    for (int t = 0; t < 32; ++t) {
        const int cur = t & 1;
        if (t < 31) {
            const int ko = (t + 1) * 16;
            pa0 = *(const float4*)(Ab + (size_t)frow0 * NN + ko + fkq);
            pa1 = (frow1 < mvalid) ? *(const float4*)(Ab + (size_t)frow1 * NN + ko + fkq)
                                   : make_float4(0.f, 0.f, 0.f, 0.f);
            pb0 = *(const float4*)(Bb + (size_t)frow0 * NN + ko + fkq);
            pb1 = *(const float4*)(Bb + (size_t)frow1 * NN + ko + fkq);
            if (cs) psc = *(const float4*)(cs + ko + fkq);
        }
        // compute on cur
        {
            const uint32_t aCur = aSm + cur * (128*TPAD*4);
            const uint32_t bCur = bSm + cur * (128*TPAD*4);
#pragma unroll
            for (int kk = 0; kk < 16; kk += 8) {
                uint32_t a[4][4];
#pragma unroll
                for (int mt = 0; mt < 4; mt++) {
                    uint32_t addr = aCur + ((mbase + mt*16)*TPAD + aRowOff + kk) * 4;
                    LDSM4(a[mt][0], a[mt][1], a[mt][2], a[mt][3], addr);
                }
                uint32_t bfr[4][2];
#pragma unroll
                for (int np = 0; np < 2; np++) {
                    uint32_t addr = bCur + ((nbase + np*16)*TPAD + bRowOff + kk) * 4;
                    LDSM4(bfr[np*2][0], bfr[np*2][1], bfr[np*2+1][0], bfr[np*2+1][1], addr);
                }
#pragma unroll
                for (int mt = 0; mt < 4; mt++)
#pragma unroll
                    for (int nt = 0; nt < 4; nt++)
                        MMA_TF32(c[mt][nt], a[mt][0], a[mt][1], a[mt][2], a[mt][3],
                                 bfr[nt][0], bfr[nt][1]);
            }
        }
        if (t < 31) {
            const int nxt = cur ^ 1;
            uint4 wa0 = { f2tf32(pa0.x), f2tf32(pa0.y), f2tf32(pa0.z), f2tf32(pa0.w) };
            uint4 wa1 = { f2tf32(pa1.x), f2tf32(pa1.y), f2tf32(pa1.z), f2tf32(pa1.w) };
            float4 sb0 = pb0, sb1 = pb1;
            if (cs) {
                sb0.x*=psc.x; sb0.y*=psc.y; sb0.z*=psc.z; sb0.w*=psc.w;
                sb1.x*=psc.x; sb1.y*=psc.y; sb1.z*=psc.z; sb1.w*=psc.w;
            }
            uint4 wb0 = { f2tf32(sb0.x), f2tf32(sb0.y), f2tf32(sb0.z), f2tf32(sb0.w) };
            uint4 wb1 = { f2tf32(sb1.x), f2tf32(sb1.y), f2tf32(sb1.z), f2tf32(sb1.w) };
            *(uint4*)&As[nxt][frow0*TPAD + fkq] = wa0;
            *(uint4*)&As[nxt][frow1*TPAD + fkq] = wa1;
            *(uint4*)&Bs[nxt][frow0*TPAD + fkq] = wb0;
            *(uint4*)&Bs[nxt][frow1*TPAD + fkq] = wb1;
        }
        __syncthreads();
    }

    // epilogue
    if (mbase >= mvalid) return;
    float* C = ks ? C1 : C0;
    const float* add = ks ? add1 : add0;
    float* Cb = C + (size_t)bidx * cBatch;
    const float* Adb = add ? add + (size_t)bidx * cBatch : nullptr;
    const int gid = lane >> 2, tq = lane & 3;
#pragma unroll
    for (int mt = 0; mt < 4; mt++) {
        const int r = mbase + mt*16 + gid;
#pragma unroll
        for (int nt = 0; nt < 4; nt++) {
            const int col = n0 + nbase + nt*8 + tq*2;
            float2 v0 = { c[mt][nt][0], c[mt][nt][1] };
            float2 v1 = { c[mt][nt][2], c[mt][nt][3] };
            if (biasN && ks == 0) {
                float b0 = biasN[col], b1 = biasN[col+1];
                v0.x += b0; v0.y += b1; v1.x += b0; v1.y += b1;
            }
            if (Adb) {
                float2 d0 = *(const float2*)(Adb + (size_t)r * NN + col);
                float2 d1 = *(const float2*)(Adb + (size_t)(r+8) * NN + col);
                v0.x += d0.x; v0.y += d0.y; v1.x += d1.x; v1.y += d1.y;
            }
            *(float2*)(Cb + (size_t)r * NN + col)     = v0;
            *(float2*)(Cb + (size_t)(r+8) * NN + col) = v1;
        }
    }
}

// ---------------- laplacian prep ----------------
__global__ void k_lap_d(const float* __restrict__ graph) {
    int i = blockIdx.x, k = blockIdx.y, t = threadIdx.x;
    const float* row = graph + (size_t)k*NN*NN + (size_t)i*NN;
    float s = 0.f;
    for (int j = t; j < NN; j += 256) s += row[j];
    __shared__ float sh[256];
    sh[t] = s; __syncthreads();
    for (int o = 128; o > 0; o >>= 1) { if (t < o) sh[t] += sh[t+o]; __syncthreads(); }
    if (t == 0) g_d[k*NN + i] = rsqrtf(sh[0] + 1.0f);
}

// B[n,k] = L[k,n] = (graph[n,k] + (n==k)) * d[n] * d[k]   (directly K-major)
__global__ void k_lapT(const float* __restrict__ graph) {
    int kg = blockIdx.y, m = blockIdx.x, t = threadIdx.x;
    const float* src = graph + (size_t)kg*NN*NN + (size_t)m*NN;
    float* dst = ((kg == 0) ? g_g1 : g_g2) + (size_t)m*NN;
    const float* d = g_d + kg*NN;
    float dm = d[m];
#pragma unroll
    for (int q = 0; q < 4; q++) {
        int k = t + 256*q;
        float v = src[k] + ((m == k) ? 1.f : 0.f);
        dst[k] = v * dm * d[k];
    }
}

// ---------------- embedding stage 1 ----------------
__global__ void k_emb1(const float* __restrict__ x, const float* __restrict__ emb_w,
                       const float* __restrict__ emb_b) {
    __shared__ float w[CC*CIN];
    __shared__ float bsm[CC];
    int t = threadIdx.x;
    for (int i = t; i < CC*CIN; i += 256) w[i] = emb_w[i];
    if (t < CC) bsm[t] = emb_b[t];
    __syncthreads();
    int b = blockIdx.x;
    int n = blockIdx.y * 256 + t;
    float xv[CIN];
    const float* xp = x + (size_t)b*CIN*NN + n;
#pragma unroll
    for (int c = 0; c < CIN; c++) xv[c] = xp[(size_t)c*NN];
    float* out = g_h0a + (size_t)b*CC*NN + n;
    for (int e = 0; e < CC; e++) {
        float s = bsm[e];
#pragma unroll
        for (int c = 0; c < CIN; c++) s = fmaf(w[e*CIN + c], xv[c], s);
        out[(size_t)e*NN] = (s > 0.f) ? s : 0.01f*s;
    }
}

// ---------------- 64x64 channel mix (dual weight via z, 2 summed inputs, relu-in) ----
__global__ void __launch_bounds__(128)
chanmixD(const float* __restrict__ in, const float* __restrict__ in2, int reluIn,
         size_t inBstride, size_t inZoff,
         const float* __restrict__ Wa, const float* __restrict__ ba,
         const float* __restrict__ Wb, const float* __restrict__ bb_,
         int trans, float* __restrict__ out, size_t outBstride) {
    const int z = blockIdx.z;
    const float* W    = z ? Wb  : Wa;
    const float* bias = z ? bb_ : ba;
    const int b = blockIdx.y, n0 = blockIdx.x * 64;
    __shared__ float Ms[64*PADN];
    __shared__ float Xs[64*PADN];
    const int tid = threadIdx.x;
    for (int i = tid; i < 64*64; i += 128) {
        int o = i >> 6, k = i & 63;
        Ms[k*PADN + o] = trans ? W[k*64 + o] : W[o*64 + k];
    }
    const size_t boff = (size_t)b*inBstride + (size_t)z*inZoff + n0;
    for (int i = tid; i < 64*16; i += 128) {
        int k = i >> 4, n4 = (i & 15) * 4;
        size_t off = boff + (size_t)k*NN + n4;
        float4 v = *(const float4*)(in + off);
        if (in2) {
            float4 w2 = *(const float4*)(in2 + off);
            v.x += w2.x; v.y += w2.y; v.z += w2.z; v.w += w2.w;
        }
        if (reluIn) {
            v.x = fmaxf(v.x, 0.f); v.y = fmaxf(v.y, 0.f);
            v.z = fmaxf(v.z, 0.f); v.w = fmaxf(v.w, 0.f);
        }
        *(float4*)&Xs[k*PADN + n4] = v;
    }
    __syncthreads();
    const int tx = tid & 15, ty = tid >> 4;
    u64 acc[4][4] = {};
#pragma unroll 8
    for (int k = 0; k < 64; k++) {
        const float* mrow = &Ms[k*PADN + ty*8];
        ulonglong2 av0 = *(const ulonglong2*)(mrow);
        ulonglong2 av1 = *(const ulonglong2*)(mrow + 4);
        float4 xv = *(const float4*)&Xs[k*PADN + tx*4];
        u64 gs0 = splat2(xv.x), gs1 = splat2(xv.y), gs2 = splat2(xv.z), gs3 = splat2(xv.w);
        ffma2(acc[0][0], av0.x, gs0); ffma2(acc[0][1], av0.x, gs1);
        ffma2(acc[0][2], av0.x, gs2); ffma2(acc[0][3], av0.x, gs3);
        ffma2(acc[1][0], av0.y, gs0); ffma2(acc[1][1], av0.y, gs1);
        ffma2(acc[1][2], av0.y, gs2); ffma2(acc[1][3], av0.y, gs3);
        ffma2(acc[2][0], av1.x, gs0); ffma2(acc[2][1], av1.x, gs1);
        ffma2(acc[2][2], av1.x, gs2); ffma2(acc[2][3], av1.x, gs3);
        ffma2(acc[3][0], av1.y, gs0); ffma2(acc[3][1], av1.y, gs1);
        ffma2(acc[3][2], av1.y, gs2); ffma2(acc[3][3], av1.y, gs3);
    }
    float* outb = out + (size_t)b*outBstride + (size_t)z*CC*NN + n0;
#pragma unroll
    for (int i = 0; i < 4; i++) {
        int o = ty*8 + 2*i;
        float b0 = bias ? bias[o]   : 0.f;
        float b1 = bias ? bias[o+1] : 0.f;
        float2 v0 = unpack2(acc[i][0]), v1 = unpack2(acc[i][1]);
        float2 v2 = unpack2(acc[i][2]), v3 = unpack2(acc[i][3]);
        float4 lo = {v0.x + b0, v1.x + b0, v2.x + b0, v3.x + b0};
        float4 hi = {v0.y + b1, v1.y + b1, v2.y + b1, v3.y + b1};
        *(float4*)(outb + (size_t)o*NN + tx*4) = lo;
        *(float4*)(outb + (size_t)(o+1)*NN + tx*4) = hi;
    }
}

// ---------------- attention scores (rank-1) ----------------
__global__ void k_s12(const float* __restrict__ att_a) {
    __shared__ float a1[64], a2[64];
    int t = threadIdx.x;
    if (t < 64) a1[t] = att_a[t];
    else if (t < 128) a2[t-64] = att_a[t];
    __syncthreads();
    int b = blockIdx.x;
    int i = blockIdx.y * 256 + t;
    const float* h = g_hT + (size_t)b*CC*NN + i;
    float v1 = 0.f, v2 = 0.f;
#pragma unroll 8
    for (int c = 0; c < 64; c++) {
        float hv = h[(size_t)c*NN];
        v1 = fmaf(hv, a1[c], v1);
        v2 = fmaf(hv, a2[c], v2);
    }
    g_s1[b*NN + i] = v1;
    g_s2[b*NN + i] = v2;
}

__global__ void k_attrow() {
    int b = blockIdx.y, i = blockIdx.x, t = threadIdx.x;
    float s1 = g_s1[b*NN + i];
    const float* s2 = g_s2 + b*NN;
    float v[4];
    float mx = -1e30f;
#pragma unroll
    for (int q = 0; q < 4; q++) {
        float e = s1 + s2[t + 256*q];
        e = (e > 0.f) ? e : 0.01f*e;
        v[q] = e;
        mx = fmaxf(mx, e);
    }
    __shared__ float sh[256];
    sh[t] = mx; __syncthreads();
    for (int o = 128; o > 0; o >>= 1) { if (t < o) sh[t] = fmaxf(sh[t], sh[t+o]); __syncthreads(); }
    mx = sh[0]; __syncthreads();
    float sm = 0.f;
#pragma unroll
    for (int q = 0; q < 4; q++) { v[q] = __expf(v[q] - mx); sm += v[q]; }
    sh[t] = sm; __syncthreads();
    for (int o = 128; o > 0; o >>= 1) { if (t < o) sh[t] += sh[t+o]; __syncthreads(); }
    float inv = 1.f / sh[0];
    float* arow = g_att + ((size_t)b*NN + i)*NN;
#pragma unroll
    for (int q = 0; q < 4; q++) arow[t + 256*q] = v[q] * inv;
}

// ---------------- learned adjacency (gram + rbf, symmetric; row partials) ----------
__global__ void k_sq() {
    int b = blockIdx.x, n = blockIdx.y * 256 + threadIdx.x;
    const float* xp = g_xuai + (size_t)b*CC*NN + n;
    float s = 0.f;
#pragma unroll 8
    for (int c = 0; c < CC; c++) { float v = xp[(size_t)c*NN]; s = fmaf(v, v, s); }
    g_sq[b*NN + n] = s;
}

__global__ void __launch_bounds__(128)
k_gram() {
    const int b  = blockIdx.z;
    const int i0 = blockIdx.x * 64;
    const int jb = blockIdx.y;
    const int j0 = jb * 128;
    __shared__ float Xi[64*PADN];
    __shared__ float Xj[64*PADW];
    const float* X = g_xuai + (size_t)b*CC*NN;
    const int tid = threadIdx.x;
    {
        int c = tid >> 1, o = (tid & 1) * 32;
        const float* src = X + (size_t)c*NN + i0 + o;
        float* dst = &Xi[c*PADN + o];
#pragma unroll
        for (int q = 0; q < 32; q += 4) *(float4*)(dst+q) = *(const float4*)(src+q);
    }
    {
        int c = tid >> 1, o = (tid & 1) * 64;
        const float* src = X + (size_t)c*NN + j0 + o;
        float* dst = &Xj[c*PADW + o];
#pragma unroll
        for (int q = 0; q < 64; q += 4) *(float4*)(dst+q) = *(const float4*)(src+q);
    }
    __syncthreads();
    const int tx = tid & 15, ty = tid >> 4;
    u64 acc[4][8] = {};
#pragma unroll 8
    for (int kk = 0; kk < 64; kk++) {
        const float* arow = &Xi[kk*PADN + ty*8];
        const float* grow = &Xj[kk*PADW + tx*8];
        INNER_STEP(arow, grow)
    }
    const float* sq = g_sq + b*NN;
    float* glb = g_gl + (size_t)b*NN*NN;
    float rowpart[8];
#pragma unroll
    for (int p = 0; p < 4; p++) {
        int i = i0 + ty*8 + 2*p;
        float sqa = sq[i], sqb = sq[i+1];
        float2 u[8];
#pragma unroll
        for (int j = 0; j < 8; j++) u[j] = unpack2(acc[p][j]);
        float oa[8], ob[8];
        float s0 = 0.f, s1 = 0.f;
#pragma unroll
        for (int q = 0; q < 8; q++) {
            int j = j0 + tx*8 + q;
            float d2a = fmaxf(sqa + sq[j] - 2.f*u[q].x, 0.f);
            float va = __expf(__expf(-d2a * (1.f/128.f)) + ((i == j) ? 1.f : 0.f));
            oa[q] = va; s0 += va;
            float d2b = fmaxf(sqb + sq[j] - 2.f*u[q].y, 0.f);
            float vb = __expf(__expf(-d2b * (1.f/128.f)) + ((i+1 == j) ? 1.f : 0.f));
            ob[q] = vb; s1 += vb;
        }
        rowpart[2*p]   = s0;
        rowpart[2*p+1] = s1;
        float4 a0 = {oa[0],oa[1],oa[2],oa[3]}, a1v = {oa[4],oa[5],oa[6],oa[7]};
        float4 b0 = {ob[0],ob[1],ob[2],ob[3]}, b1v = {ob[4],ob[5],ob[6],ob[7]};
        *(float4*)(glb + (size_t)i*NN + j0 + tx*8)         = a0;
        *(float4*)(glb + (size_t)i*NN + j0 + tx*8 + 4)     = a1v;
        *(float4*)(glb + (size_t)(i+1)*NN + j0 + tx*8)     = b0;
        *(float4*)(glb + (size_t)(i+1)*NN + j0 + tx*8 + 4) = b1v;
    }
#pragma unroll
    for (int r = 0; r < 8; r++) {
        float v = rowpart[r];
        v += __shfl_down_sync(0xffffffffu, v, 8, 16);
        v += __shfl_down_sync(0xffffffffu, v, 4, 16);
        v += __shfl_down_sync(0xffffffffu, v, 2, 16);
        v += __shfl_down_sync(0xffffffffu, v, 1, 16);
        if (tx == 0)
            g_part[((size_t)b*8 + jb)*NN + i0 + ty*8 + r] = v;
    }
}

__global__ void k_rsfin() {
    int b = blockIdx.x, i = threadIdx.x;
    float s = 0.f;
#pragma unroll
    for (int j = 0; j < 8; j++) s += g_part[((size_t)b*8 + j)*NN + i];
    g_rsinv[b*NN + i] = 1.f / s;
}

// ---------------- layernorm stats + final fuse (sum of 2 partials) ----------------
__global__ void k_lnstats() {
    int b = blockIdx.x, path = blockIdx.y, t = threadIdx.x;
    size_t base = (size_t)b*(2*CC)*NN + (size_t)path*CC*NN;
    float s = 0.f, ss = 0.f;
    for (int i = t; i < CC*NN; i += 1024) {
        float v = g_sxa[base + i] + g_sxb[base + i];
        s += v; ss = fmaf(v, v, ss);
    }
    __shared__ float shs[1024], shq[1024];
    shs[t] = s; shq[t] = ss; __syncthreads();
    for (int o = 512; o > 0; o >>= 1) {
        if (t < o) { shs[t] += shs[t+o]; shq[t] += shq[t+o]; }
        __syncthreads();
    }
    if (t == 0) {
        float mean = shs[0] * (1.f/65536.f);
        float var  = shq[0] * (1.f/65536.f) - mean*mean;
        g_stats[(path*BB + b)*2 + 0] = mean;
        g_stats[(path*BB + b)*2 + 1] = rsqrtf(var + 1e-5f);
    }
}

__global__ void k_final(const float* __restrict__ ct, const float* __restrict__ ln_w,
                        const float* __restrict__ ln_b, float* __restrict__ out) {
    size_t idx = (size_t)blockIdx.x * 256 + threadIdx.x;
    int b  = (int)(idx / (CC*NN));
    int cn = (int)(idx % (CC*NN));
    float m1 = g_stats[b*2 + 0],            r1 = g_stats[b*2 + 1];
    float m2 = g_stats[(BB + b)*2 + 0],     r2 = g_stats[(BB + b)*2 + 1];
    float w = ln_w[cn], bb = ln_b[cn];
    size_t base = (size_t)b*(2*CC)*NN + cn;
    float z1v = g_sxa[base] + g_sxb[base];
    float z2v = g_sxa[base + (size_t)CC*NN] + g_sxb[base + (size_t)CC*NN];
    float xnew = (z1v - m1) * r1 * w + bb;
    float z2   = (z2v - m2) * r2 * w + bb;
    float ft = 0.5f * z2 * (1.f + erff(z2 * 0.70710678118654752f));
    float ctv = ct[idx];
    float ctn = xnew + ft * (ctv - xnew);
    float el  = (ctn > 0.f) ? ctn : expm1f(ctn);
    float xu  = g_xuai[idx];
    float ht  = xu + ft * (el - xu);
    out[idx] = ht;
    out[(size_t)BB*CC*NN + idx] = ctn;
}

// ---------------- host launch ----------------
struct DevPtrs {
    float *att, *gl, *g1, *g2, *h0a, *hT, *xuai, *pa, *pb;
    float *l12, *t12a, *t12b, *u12, *a12a, *a12b, *sxa, *sxb, *rsinv;
    bool init;
};
static DevPtrs P = {};

static void init_ptrs() {
    if (P.init) return;
    void* p;
#define GET(sym, field) cudaGetSymbolAddress(&p, sym); P.field = (float*)p;
    GET(g_att, att)  GET(g_gl, gl)   GET(g_g1, g1)   GET(g_g2, g2)
    GET(g_h0a, h0a)  GET(g_hT, hT)   GET(g_xuai, xuai)
    GET(g_pa, pa)    GET(g_pb, pb)
    GET(g_l12, l12)  GET(g_t12a, t12a) GET(g_t12b, t12b) GET(g_u12, u12)
    GET(g_a12a, a12a) GET(g_a12b, a12b) GET(g_sxa, sxa) GET(g_sxb, sxb)
    GET(g_rsinv, rsinv)
#undef GET
    P.init = true;
}

extern "C" void kernel_launch(void* const* d_in, const int* in_sizes, int n_in,
                              void* d_out, int out_size) {
    const float* x      = (const float*)d_in[0];
    const float* ct     = (const float*)d_in[1];
    const float* graph  = (const float*)d_in[2];
    const float* emb_w  = (const float*)d_in[3];
    const float* emb_b  = (const float*)d_in[4];
    const float* emb2_w = (const float*)d_in[5];
    const float* emb2_b = (const float*)d_in[6];
    const float* att_W  = (const float*)d_in[7];
    const float* att_a  = (const float*)d_in[8];
    // d_in[9] = att_GL : unused (softmax output strictly positive => mask no-op)
    const float* uai_w  = (const float*)d_in[10];
    const float* uai_b  = (const float*)d_in[11];
    const float* lin1_w = (const float*)d_in[12];
    const float* lin2_w = (const float*)d_in[13];
    const float* lin2_b = (const float*)d_in[14];
    const float* ln_w   = (const float*)d_in[15];
    const float* ln_b   = (const float*)d_in[16];
    float* out = (float*)d_out;

    init_ptrs();

    const size_t GSTRIDE = (size_t)NN * NN;
    const size_t SB = (size_t)CC * NN;     // 65536
    const size_t DB = (size_t)2 * CC * NN; // 131072
    const dim3 gridC1(NN/64, BB, 1);
    const dim3 gridC2(NN/64, BB, 2);

    // graph laplacians (K-major for MMA B operand)
    k_lap_d<<<dim3(NN, 2), 256>>>(graph);
    k_lapT <<<dim3(NN, 2), 256>>>(graph);

    // embedding: conv1d+leakyrelu, then node-linear (tf32 MMA, batch pairs stacked, K-split)
    k_emb1  <<<dim3(BB, NN/256), 256>>>(x, emb_w, emb_b);
    mma_gemm<<<dim3(8, BB/2, 2), 256>>>(P.h0a, DB, 128, emb2_w, 0,
                                        nullptr, 0, nullptr, nullptr, emb2_b,
                                        P.pa, P.pb, DB);

    // attention
    chanmixD<<<gridC1, 128>>>(P.pa, P.pb, 0, SB, 0, att_W, nullptr, att_W, nullptr, 1, P.hT, SB);
    k_s12   <<<dim3(BB, NN/256), 256>>>(att_a);
    k_attrow<<<dim3(NN, BB), 256>>>();
    mma_gemm<<<dim3(8, BB, 2), 256>>>(P.hT, SB, 64, P.att, GSTRIDE,
                                      nullptr, 0, nullptr, nullptr, nullptr,
                                      P.pa, P.pb, SB);

    // UAI: xuai = uai_w @ relu(pa+pb) + uai_b
    chanmixD<<<gridC1, 128>>>(P.pa, P.pb, 1, SB, 0, uai_w, uai_b, uai_w, uai_b, 0, P.xuai, SB);

    // learned adjacency (unnormalized symmetric gl) + row-sum inverses
    k_sq   <<<dim3(BB, NN/256), 256>>>();
    k_gram <<<dim3(NN/64, NN/128, BB), 128>>>();
    k_rsfin<<<BB, 1024>>>();

    // l1/l2 stacked propagation
    chanmixD<<<gridC2, 128>>>(P.xuai, nullptr, 0, SB, 0,
                              lin1_w, nullptr, lin2_w, lin2_b, 0, P.l12, DB);

    // l12 @ (gl * rsinv-col) -> a12a/b ; l12 @ g1 -> t12a/b
    mma_gemm<<<dim3(8, BB, 2), 256>>>(P.l12, DB, 128, P.gl, GSTRIDE,
                                      P.rsinv, NN, nullptr, nullptr, nullptr,
                                      P.a12a, P.a12b, DB);
    mma_gemm<<<dim3(8, BB, 2), 256>>>(P.l12, DB, 128, P.g1, 0,
                                      nullptr, 0, nullptr, nullptr, nullptr,
                                      P.t12a, P.t12b, DB);

    chanmixD<<<gridC2, 128>>>(P.t12a, P.t12b, 0, DB, SB,
                              lin1_w, nullptr, lin2_w, lin2_b, 0, P.u12, DB);

    // u12 @ g2 + a12 (per-ks addend) -> sxa/sxb
    mma_gemm<<<dim3(8, BB, 2), 256>>>(P.u12, DB, 128, P.g2, 0,
                                      nullptr, 0, P.a12a, P.a12b, nullptr,
                                      P.sxa, P.sxb, DB);

    // layernorm + gates + output
    k_lnstats<<<dim3(BB, 2), 1024>>>();
    k_final  <<<(BB*CC*NN)/256, 256>>>(ct, ln_w, ln_b, out);
}

// round 9
// speedup vs baseline: 2.0187x; 1.1578x over previous
#include <cuda_runtime.h>
#include <math.h>
#include <stdint.h>

#define BB 16
#define NN 1024
#define CC 64
#define CIN 16
#define PADN 68
#define PADW 132

typedef unsigned long long u64;

// ---------------- fp32x2 helpers ----------------
__device__ __forceinline__ u64 splat2(float v) {
    u64 r; asm("mov.b64 %0, {%1, %1};" : "=l"(r) : "f"(v)); return r;
}
__device__ __forceinline__ void ffma2(u64& d, u64 a, u64 b) {
    asm("fma.rn.f32x2 %0, %1, %2, %0;" : "+l"(d) : "l"(a), "l"(b));
}
__device__ __forceinline__ float2 unpack2(u64 v) {
    float2 r; asm("mov.b64 {%0, %1}, %2;" : "=f"(r.x), "=f"(r.y) : "l"(v)); return r;
}

#define INNER_STEP(ASP, GSP)                                                   \
    {                                                                          \
        ulonglong2 av0 = *(const ulonglong2*)(ASP);                            \
        ulonglong2 av1 = *(const ulonglong2*)((ASP) + 4);                      \
        float4 g0 = *(const float4*)(GSP);                                     \
        float4 g1 = *(const float4*)((GSP) + 4);                               \
        u64 s0=splat2(g0.x), s1=splat2(g0.y), s2=splat2(g0.z), s3=splat2(g0.w);\
        u64 s4=splat2(g1.x), s5=splat2(g1.y), s6=splat2(g1.z), s7=splat2(g1.w);\
        ffma2(acc[0][0],av0.x,s0); ffma2(acc[0][1],av0.x,s1);                  \
        ffma2(acc[0][2],av0.x,s2); ffma2(acc[0][3],av0.x,s3);                  \
        ffma2(acc[0][4],av0.x,s4); ffma2(acc[0][5],av0.x,s5);                  \
        ffma2(acc[0][6],av0.x,s6); ffma2(acc[0][7],av0.x,s7);                  \
        ffma2(acc[1][0],av0.y,s0); ffma2(acc[1][1],av0.y,s1);                  \
        ffma2(acc[1][2],av0.y,s2); ffma2(acc[1][3],av0.y,s3);                  \
        ffma2(acc[1][4],av0.y,s4); ffma2(acc[1][5],av0.y,s5);                  \
        ffma2(acc[1][6],av0.y,s6); ffma2(acc[1][7],av0.y,s7);                  \
        ffma2(acc[2][0],av1.x,s0); ffma2(acc[2][1],av1.x,s1);                  \
        ffma2(acc[2][2],av1.x,s2); ffma2(acc[2][3],av1.x,s3);                  \
        ffma2(acc[2][4],av1.x,s4); ffma2(acc[2][5],av1.x,s5);                  \
        ffma2(acc[2][6],av1.x,s6); ffma2(acc[2][7],av1.x,s7);                  \
        ffma2(acc[3][0],av1.y,s0); ffma2(acc[3][1],av1.y,s1);                  \
        ffma2(acc[3][2],av1.y,s2); ffma2(acc[3][3],av1.y,s3);                  \
        ffma2(acc[3][4],av1.y,s4); ffma2(acc[3][5],av1.y,s5);                  \
        ffma2(acc[3][6],av1.y,s6); ffma2(acc[3][7],av1.y,s7);                  \
    }

// ---------------- mma.sync tf32 + cp.async helpers ----------------
__device__ __forceinline__ uint32_t smem_u32(const void* p) {
    uint32_t a;
    asm("{ .reg .u64 t; cvta.to.shared.u64 t, %1; cvt.u32.u64 %0, t; }" : "=r"(a) : "l"(p));
    return a;
}
// round fp32 -> tf32 (rna), keep as fp32 bit pattern (low 13 mantissa bits zero)
__device__ __forceinline__ float rnd_tf32(float f) {
    uint32_t r; asm("cvt.rna.tf32.f32 %0, %1;" : "=r"(r) : "f"(f));
    return __uint_as_float(r);
}
#define LDSM4(r0, r1, r2, r3, addr)                                            \
    asm volatile("ldmatrix.sync.aligned.m8n8.x4.shared.b16 {%0,%1,%2,%3}, [%4];" \
        : "=r"(r0), "=r"(r1), "=r"(r2), "=r"(r3) : "r"(addr))
#define MMA_TF32(c, a0, a1, a2, a3, b0, b1)                                    \
    asm volatile("mma.sync.aligned.m16n8k8.row.col.f32.tf32.tf32.f32 "         \
        "{%0,%1,%2,%3}, {%4,%5,%6,%7}, {%8,%9}, {%0,%1,%2,%3};"                \
        : "+f"((c)[0]), "+f"((c)[1]), "+f"((c)[2]), "+f"((c)[3])               \
        : "r"(a0), "r"(a1), "r"(a2), "r"(a3), "r"(b0), "r"(b1))
__device__ __forceinline__ void cp16(uint32_t dst, const void* src) {
    asm volatile("cp.async.cg.shared.global [%0], [%1], 16;" :: "r"(dst), "l"(src));
}
#define CP_COMMIT()  asm volatile("cp.async.commit_group;" ::: "memory")
#define CP_WAIT1()   asm volatile("cp.async.wait_group 1;" ::: "memory")
#define CP_WAIT0()   asm volatile("cp.async.wait_group 0;" ::: "memory")

// ---------------- static device scratch ----------------
__device__ float g_att [BB*NN*NN];
__device__ float g_gl  [BB*NN*NN];
__device__ float g_g1  [NN*NN];
__device__ float g_g2  [NN*NN];
__device__ float g_wr  [NN*NN];      // tf32-rounded emb2_w
__device__ float g_d   [2*NN];
__device__ float g_h0a [BB*CC*NN];
__device__ float g_hT  [BB*CC*NN];
__device__ float g_xuai[BB*CC*NN];
__device__ float g_pa  [BB*CC*NN];
__device__ float g_pb  [BB*CC*NN];
__device__ float g_pc  [BB*CC*NN];
__device__ float g_pd  [BB*CC*NN];
__device__ float g_l12 [BB*2*CC*NN];
__device__ float g_l12s[BB*2*CC*NN];
__device__ float g_t12a[BB*2*CC*NN];
__device__ float g_t12b[BB*2*CC*NN];
__device__ float g_u12 [BB*2*CC*NN];
__device__ float g_a12a[BB*2*CC*NN];
__device__ float g_a12b[BB*2*CC*NN];
__device__ float g_sxa [BB*2*CC*NN];
__device__ float g_sxb [BB*2*CC*NN];
__device__ float g_s1  [BB*NN];
__device__ float g_s2  [BB*NN];
__device__ float g_sq  [BB*NN];
__device__ float g_part[BB*8*NN];
__device__ float g_rsinv[BB*NN];
__device__ float g_stats[2*BB*2];

// =========================================================================
// mma_gemm (tf32): C_ks[b,c,n] = sum_{k in split ks} A[b,c,k] * B[b,n,k]
// Operands are pre-rounded to tf32 by producers; cp.async byte copies only.
// block 128M x 128N, warps 2x4 (64x32), K-step 16, cp.async double buffer.
// =========================================================================
#define TPAD 20
__global__ void __launch_bounds__(256, 2)
mma_gemm(const float* __restrict__ A, size_t aBatch, int mvalid,
         const float* __restrict__ B, size_t bBatch, int nsplit,
         const float* __restrict__ add0, const float* __restrict__ add1,
         const float* __restrict__ biasN,
         float* __restrict__ C0, float* __restrict__ C1,
         float* __restrict__ C2, float* __restrict__ C3, size_t cBatch)
{
    __shared__ uint32_t As[2][128*TPAD];
    __shared__ uint32_t Bs[2][128*TPAD];

    const int tid  = threadIdx.x;
    const int lane = tid & 31;
    const int wid  = tid >> 5;
    const int bidx = blockIdx.y;
    const int n0   = blockIdx.x * 128;
    const int ks   = blockIdx.z;
    const int kPer = NN / nsplit;
    const int T    = kPer / 16;
    const int k0b  = ks * kPer;

    const float* Ab = A + (size_t)bidx * aBatch + k0b;
    const float* Bb = B + (size_t)bidx * bBatch + (size_t)n0 * NN + k0b;

    const int frow0 = tid >> 2;
    const int frow1 = 64 + (tid >> 2);
    const int fkq   = (tid & 3) * 4;

    const float* aP0 = Ab + (size_t)frow0 * NN + fkq;
    const float* aP1 = Ab + (size_t)((frow1 < mvalid) ? frow1 : 0) * NN + fkq;
    const float* bP0 = Bb + (size_t)frow0 * NN + fkq;
    const float* bP1 = Bb + (size_t)frow1 * NN + fkq;

    const uint32_t aSm = smem_u32(&As[0][0]);
    const uint32_t bSm = smem_u32(&Bs[0][0]);
    const uint32_t aFill  = aSm + (frow0*TPAD + fkq) * 4;
    const uint32_t aFill1 = aSm + (frow1*TPAD + fkq) * 4;
    const uint32_t bFill  = bSm + (frow0*TPAD + fkq) * 4;
    const uint32_t bFill1 = bSm + (frow1*TPAD + fkq) * 4;
    const uint32_t bufStride = 128*TPAD*4;

    const int aRowOff = (lane & 15) * TPAD + (lane >> 4) * 4;
    const int bRowOff = ((lane >> 4) * 8 + (lane & 7)) * TPAD + ((lane >> 3) & 1) * 4;

    const int mbase = (wid >> 2) * 64;
    const int nbase = (wid & 3) * 32;

    float c[4][4][4];
#pragma unroll
    for (int i = 0; i < 4; i++)
#pragma unroll
        for (int j = 0; j < 4; j++)
#pragma unroll
            for (int q = 0; q < 4; q++) c[i][j][q] = 0.f;

    cp16(aFill,  aP0); cp16(aFill1, aP1);
    cp16(bFill,  bP0); cp16(bFill1, bP1);
    CP_COMMIT();

    for (int t = 0; t < T; ++t) {
        const int cur = t & 1;
        if (t + 1 < T) {
            const uint32_t off = (uint32_t)((t+1) & 1) * bufStride;
            const int ko = (t + 1) * 16;
            cp16(aFill  + off, aP0 + ko);
            cp16(aFill1 + off, aP1 + ko);
            cp16(bFill  + off, bP0 + ko);
            cp16(bFill1 + off, bP1 + ko);
            CP_COMMIT();
            CP_WAIT1();
        } else {
            CP_WAIT0();
        }
        __syncthreads();
        {
            const uint32_t aCur = aSm + cur * bufStride;
            const uint32_t bCur = bSm + cur * bufStride;
#pragma unroll
            for (int kk = 0; kk < 16; kk += 8) {
                uint32_t a[4][4];
#pragma unroll
                for (int mt = 0; mt < 4; mt++) {
                    uint32_t addr = aCur + ((mbase + mt*16)*TPAD + aRowOff + kk) * 4;
                    LDSM4(a[mt][0], a[mt][1], a[mt][2], a[mt][3], addr);
                }
                uint32_t bfr[4][2];
#pragma unroll
                for (int np = 0; np < 2; np++) {
                    uint32_t addr = bCur + ((nbase + np*16)*TPAD + bRowOff + kk) * 4;
                    LDSM4(bfr[np*2][0], bfr[np*2][1], bfr[np*2+1][0], bfr[np*2+1][1], addr);
                }
#pragma unroll
                for (int mt = 0; mt < 4; mt++)
#pragma unroll
                    for (int nt = 0; nt < 4; nt++)
                        MMA_TF32(c[mt][nt], a[mt][0], a[mt][1], a[mt][2], a[mt][3],
                                 bfr[nt][0], bfr[nt][1]);
            }
        }
        __syncthreads();
    }

    if (mbase >= mvalid) return;
    float* C = (ks == 0) ? C0 : (ks == 1) ? C1 : (ks == 2) ? C2 : C3;
    const float* add = (ks == 0) ? add0 : (ks == 1) ? add1 : nullptr;
    float* Cb = C + (size_t)bidx * cBatch;
    const float* Adb = add ? add + (size_t)bidx * cBatch : nullptr;
    const int gid = lane >> 2, tq = lane & 3;
#pragma unroll
    for (int mt = 0; mt < 4; mt++) {
        const int r = mbase + mt*16 + gid;
#pragma unroll
        for (int nt = 0; nt < 4; nt++) {
            const int col = n0 + nbase + nt*8 + tq*2;
            float2 v0 = { c[mt][nt][0], c[mt][nt][1] };
            float2 v1 = { c[mt][nt][2], c[mt][nt][3] };
            if (biasN && ks == 0) {
                float b0 = biasN[col], b1 = biasN[col+1];
                v0.x += b0; v0.y += b1; v1.x += b0; v1.y += b1;
            }
            if (Adb) {
                float2 d0 = *(const float2*)(Adb + (size_t)r * NN + col);
                float2 d1 = *(const float2*)(Adb + (size_t)(r+8) * NN + col);
                v0.x += d0.x; v0.y += d0.y; v1.x += d1.x; v1.y += d1.y;
            }
            *(float2*)(Cb + (size_t)r * NN + col)     = v0;
            *(float2*)(Cb + (size_t)(r+8) * NN + col) = v1;
        }
    }
}

// ---------------- tf32 rounding copy (for raw-input weights) ----------------
__global__ void k_wround(const float* __restrict__ src) {
    size_t i = ((size_t)blockIdx.x * 256 + threadIdx.x) * 4;
    float4 v = *(const float4*)(src + i);
    float4 w = { rnd_tf32(v.x), rnd_tf32(v.y), rnd_tf32(v.z), rnd_tf32(v.w) };
    *(float4*)(g_wr + i) = w;
}

// ---------------- laplacian prep ----------------
__global__ void k_lap_d(const float* __restrict__ graph) {
    int i = blockIdx.x, k = blockIdx.y, t = threadIdx.x;
    const float* row = graph + (size_t)k*NN*NN + (size_t)i*NN;
    float s = 0.f;
    for (int j = t; j < NN; j += 256) s += row[j];
    __shared__ float sh[256];
    sh[t] = s; __syncthreads();
    for (int o = 128; o > 0; o >>= 1) { if (t < o) sh[t] += sh[t+o]; __syncthreads(); }
    if (t == 0) g_d[k*NN + i] = rsqrtf(sh[0] + 1.0f);
}

__global__ void k_lapT(const float* __restrict__ graph) {
    int kg = blockIdx.y, m = blockIdx.x, t = threadIdx.x;
    const float* src = graph + (size_t)kg*NN*NN + (size_t)m*NN;
    float* dst = ((kg == 0) ? g_g1 : g_g2) + (size_t)m*NN;
    const float* d = g_d + kg*NN;
    float dm = d[m];
#pragma unroll
    for (int q = 0; q < 4; q++) {
        int k = t + 256*q;
        float v = src[k] + ((m == k) ? 1.f : 0.f);
        dst[k] = rnd_tf32(v * dm * d[k]);
    }
}

// ---------------- embedding stage 1 (output tf32-rounded: feeds emb2 MMA) ---------
__global__ void k_emb1(const float* __restrict__ x, const float* __restrict__ emb_w,
                       const float* __restrict__ emb_b) {
    __shared__ float w[CC*CIN];
    __shared__ float bsm[CC];
    int t = threadIdx.x;
    for (int i = t; i < CC*CIN; i += 256) w[i] = emb_w[i];
    if (t < CC) bsm[t] = emb_b[t];
    __syncthreads();
    int b = blockIdx.x;
    int n = blockIdx.y * 256 + t;
    float xv[CIN];
    const float* xp = x + (size_t)b*CIN*NN + n;
#pragma unroll
    for (int c = 0; c < CIN; c++) xv[c] = xp[(size_t)c*NN];
    float* out = g_h0a + (size_t)b*CC*NN + n;
    for (int e = 0; e < CC; e++) {
        float s = bsm[e];
#pragma unroll
        for (int c = 0; c < CIN; c++) s = fmaf(w[e*CIN + c], xv[c], s);
        float lv = (s > 0.f) ? s : 0.01f*s;
        out[(size_t)e*NN] = rnd_tf32(lv);
    }
}

// ------- 64x64 channel mix (dual weight via z, up to 4 summed inputs, relu-in,
//         optional tf32-rounded outputs, optional 2nd output scaled by nScale) -------
__global__ void __launch_bounds__(128)
chanmixD(const float* __restrict__ in, const float* __restrict__ in2,
         const float* __restrict__ in3, const float* __restrict__ in4,
         int reluIn, size_t inBstride, size_t inZoff,
         const float* __restrict__ Wa, const float* __restrict__ ba,
         const float* __restrict__ Wb, const float* __restrict__ bb_,
         int trans, int roundOut, float* __restrict__ out, size_t outBstride,
         float* __restrict__ out2, const float* __restrict__ nScale) {
    const int z = blockIdx.z;
    const float* W    = z ? Wb  : Wa;
    const float* bias = z ? bb_ : ba;
    const int b = blockIdx.y, n0 = blockIdx.x * 64;
    __shared__ float Ms[64*PADN];
    __shared__ float Xs[64*PADN];
    const int tid = threadIdx.x;
    for (int i = tid; i < 64*64; i += 128) {
        int o = i >> 6, k = i & 63;
        Ms[k*PADN + o] = trans ? W[k*64 + o] : W[o*64 + k];
    }
    const size_t boff = (size_t)b*inBstride + (size_t)z*inZoff + n0;
    for (int i = tid; i < 64*16; i += 128) {
        int k = i >> 4, n4 = (i & 15) * 4;
        size_t off = boff + (size_t)k*NN + n4;
        float4 v = *(const float4*)(in + off);
        if (in2) { float4 w2 = *(const float4*)(in2 + off); v.x+=w2.x; v.y+=w2.y; v.z+=w2.z; v.w+=w2.w; }
        if (in3) { float4 w3 = *(const float4*)(in3 + off); v.x+=w3.x; v.y+=w3.y; v.z+=w3.z; v.w+=w3.w; }
        if (in4) { float4 w4 = *(const float4*)(in4 + off); v.x+=w4.x; v.y+=w4.y; v.z+=w4.z; v.w+=w4.w; }
        if (reluIn) {
            v.x = fmaxf(v.x, 0.f); v.y = fmaxf(v.y, 0.f);
            v.z = fmaxf(v.z, 0.f); v.w = fmaxf(v.w, 0.f);
        }
        *(float4*)&Xs[k*PADN + n4] = v;
    }
    __syncthreads();
    const int tx = tid & 15, ty = tid >> 4;
    u64 acc[4][4] = {};
#pragma unroll 8
    for (int k = 0; k < 64; k++) {
        const float* mrow = &Ms[k*PADN + ty*8];
        ulonglong2 av0 = *(const ulonglong2*)(mrow);
        ulonglong2 av1 = *(const ulonglong2*)(mrow + 4);
        float4 xv = *(const float4*)&Xs[k*PADN + tx*4];
        u64 gs0 = splat2(xv.x), gs1 = splat2(xv.y), gs2 = splat2(xv.z), gs3 = splat2(xv.w);
        ffma2(acc[0][0], av0.x, gs0); ffma2(acc[0][1], av0.x, gs1);
        ffma2(acc[0][2], av0.x, gs2); ffma2(acc[0][3], av0.x, gs3);
        ffma2(acc[1][0], av0.y, gs0); ffma2(acc[1][1], av0.y, gs1);
        ffma2(acc[1][2], av0.y, gs2); ffma2(acc[1][3], av0.y, gs3);
        ffma2(acc[2][0], av1.x, gs0); ffma2(acc[2][1], av1.x, gs1);
        ffma2(acc[2][2], av1.x, gs2); ffma2(acc[2][3], av1.x, gs3);
        ffma2(acc[3][0], av1.y, gs0); ffma2(acc[3][1], av1.y, gs1);
        ffma2(acc[3][2], av1.y, gs2); ffma2(acc[3][3], av1.y, gs3);
    }
    float* outb = out + (size_t)b*outBstride + (size_t)z*CC*NN + n0;
    float* outb2 = out2 ? out2 + (size_t)b*outBstride + (size_t)z*CC*NN + n0 : nullptr;
    float4 sc = {1.f,1.f,1.f,1.f};
    if (outb2) sc = *(const float4*)(nScale + (size_t)b*NN + n0 + tx*4);
#pragma unroll
    for (int i = 0; i < 4; i++) {
        int o = ty*8 + 2*i;
        float b0 = bias ? bias[o]   : 0.f;
        float b1 = bias ? bias[o+1] : 0.f;
        float2 v0 = unpack2(acc[i][0]), v1 = unpack2(acc[i][1]);
        float2 v2 = unpack2(acc[i][2]), v3 = unpack2(acc[i][3]);
        float4 lo = {v0.x + b0, v1.x + b0, v2.x + b0, v3.x + b0};
        float4 hi = {v0.y + b1, v1.y + b1, v2.y + b1, v3.y + b1};
        if (roundOut) {
            lo.x = rnd_tf32(lo.x); lo.y = rnd_tf32(lo.y);
            lo.z = rnd_tf32(lo.z); lo.w = rnd_tf32(lo.w);
            hi.x = rnd_tf32(hi.x); hi.y = rnd_tf32(hi.y);
            hi.z = rnd_tf32(hi.z); hi.w = rnd_tf32(hi.w);
        }
        *(float4*)(outb + (size_t)o*NN + tx*4) = lo;
        *(float4*)(outb + (size_t)(o+1)*NN + tx*4) = hi;
        if (outb2) {
            float4 lo2 = {rnd_tf32(lo.x*sc.x), rnd_tf32(lo.y*sc.y),
                          rnd_tf32(lo.z*sc.z), rnd_tf32(lo.w*sc.w)};
            float4 hi2 = {rnd_tf32(hi.x*sc.x), rnd_tf32(hi.y*sc.y),
                          rnd_tf32(hi.z*sc.z), rnd_tf32(hi.w*sc.w)};
            *(float4*)(outb2 + (size_t)o*NN + tx*4) = lo2;
            *(float4*)(outb2 + (size_t)(o+1)*NN + tx*4) = hi2;
        }
    }
}

// ---------------- attention scores (rank-1) ----------------
__global__ void k_s12(const float* __restrict__ att_a) {
    __shared__ float a1[64], a2[64];
    int t = threadIdx.x;
    if (t < 64) a1[t] = att_a[t];
    else if (t < 128) a2[t-64] = att_a[t];
    __syncthreads();
    int b = blockIdx.x;
    int i = blockIdx.y * 256 + t;
    const float* h = g_hT + (size_t)b*CC*NN + i;
    float v1 = 0.f, v2 = 0.f;
#pragma unroll 8
    for (int c = 0; c < 64; c++) {
        float hv = h[(size_t)c*NN];
        v1 = fmaf(hv, a1[c], v1);
        v2 = fmaf(hv, a2[c], v2);
    }
    g_s1[b*NN + i] = v1;
    g_s2[b*NN + i] = v2;
}

// att rows tf32-rounded (feed att MMA as B operand)
__global__ void k_attrow() {
    int b = blockIdx.y, i = blockIdx.x, t = threadIdx.x;
    float s1 = g_s1[b*NN + i];
    const float* s2 = g_s2 + b*NN;
    float v[4];
    float mx = -1e30f;
#pragma unroll
    for (int q = 0; q < 4; q++) {
        float e = s1 + s2[t + 256*q];
        e = (e > 0.f) ? e : 0.01f*e;
        v[q] = e;
        mx = fmaxf(mx, e);
    }
    __shared__ float sh[256];
    sh[t] = mx; __syncthreads();
    for (int o = 128; o > 0; o >>= 1) { if (t < o) sh[t] = fmaxf(sh[t], sh[t+o]); __syncthreads(); }
    mx = sh[0]; __syncthreads();
    float sm = 0.f;
#pragma unroll
    for (int q = 0; q < 4; q++) { v[q] = __expf(v[q] - mx); sm += v[q]; }
    sh[t] = sm; __syncthreads();
    for (int o = 128; o > 0; o >>= 1) { if (t < o) sh[t] += sh[t+o]; __syncthreads(); }
    float inv = 1.f / sh[0];
    float* arow = g_att + ((size_t)b*NN + i)*NN;
#pragma unroll
    for (int q = 0; q < 4; q++) arow[t + 256*q] = rnd_tf32(v[q] * inv);
}

// ---------------- learned adjacency ----------------
__global__ void k_sq() {
    int b = blockIdx.x, n = blockIdx.y * 256 + threadIdx.x;
    const float* xp = g_xuai + (size_t)b*CC*NN + n;
    float s = 0.f;
#pragma unroll 8
    for (int c = 0; c < CC; c++) { float v = xp[(size_t)c*NN]; s = fmaf(v, v, s); }
    g_sq[b*NN + n] = s;
}

// gl stored tf32-rounded; row-sums computed over the ROUNDED values for consistency
__global__ void __launch_bounds__(128)
k_gram() {
    const int b  = blockIdx.z;
    const int i0 = blockIdx.x * 64;
    const int jb = blockIdx.y;
    const int j0 = jb * 128;
    __shared__ float Xi[64*PADN];
    __shared__ float Xj[64*PADW];
    const float* X = g_xuai + (size_t)b*CC*NN;
    const int tid = threadIdx.x;
    {
        int c = tid >> 1, o = (tid & 1) * 32;
        const float* src = X + (size_t)c*NN + i0 + o;
        float* dst = &Xi[c*PADN + o];
#pragma unroll
        for (int q = 0; q < 32; q += 4) *(float4*)(dst+q) = *(const float4*)(src+q);
    }
    {
        int c = tid >> 1, o = (tid & 1) * 64;
        const float* src = X + (size_t)c*NN + j0 + o;
        float* dst = &Xj[c*PADW + o];
#pragma unroll
        for (int q = 0; q < 64; q += 4) *(float4*)(dst+q) = *(const float4*)(src+q);
    }
    __syncthreads();
    const int tx = tid & 15, ty = tid >> 4;
    u64 acc[4][8] = {};
#pragma unroll 8
    for (int kk = 0; kk < 64; kk++) {
        const float* arow = &Xi[kk*PADN + ty*8];
        const float* grow = &Xj[kk*PADW + tx*8];
        INNER_STEP(arow, grow)
    }
    const float* sq = g_sq + b*NN;
    float* glb = g_gl + (size_t)b*NN*NN;
    float rowpart[8];
#pragma unroll
    for (int p = 0; p < 4; p++) {
        int i = i0 + ty*8 + 2*p;
        float sqa = sq[i], sqb = sq[i+1];
        float2 u[8];
#pragma unroll
        for (int j = 0; j < 8; j++) u[j] = unpack2(acc[p][j]);
        float oa[8], ob[8];
        float s0 = 0.f, s1 = 0.f;
#pragma unroll
        for (int q = 0; q < 8; q++) {
            int j = j0 + tx*8 + q;
            float d2a = fmaxf(sqa + sq[j] - 2.f*u[q].x, 0.f);
            float va = rnd_tf32(__expf(__expf(-d2a * (1.f/128.f)) + ((i == j) ? 1.f : 0.f)));
            oa[q] = va; s0 += va;
            float d2b = fmaxf(sqb + sq[j] - 2.f*u[q].y, 0.f);
            float vb = rnd_tf32(__expf(__expf(-d2b * (1.f/128.f)) + ((i+1 == j) ? 1.f : 0.f)));
            ob[q] = vb; s1 += vb;
        }
        rowpart[2*p]   = s0;
        rowpart[2*p+1] = s1;
        float4 a0 = {oa[0],oa[1],oa[2],oa[3]}, a1v = {oa[4],oa[5],oa[6],oa[7]};
        float4 b0 = {ob[0],ob[1],ob[2],ob[3]}, b1v = {ob[4],ob[5],ob[6],ob[7]};
        *(float4*)(glb + (size_t)i*NN + j0 + tx*8)         = a0;
        *(float4*)(glb + (size_t)i*NN + j0 + tx*8 + 4)     = a1v;
        *(float4*)(glb + (size_t)(i+1)*NN + j0 + tx*8)     = b0;
        *(float4*)(glb + (size_t)(i+1)*NN + j0 + tx*8 + 4) = b1v;
    }
#pragma unroll
    for (int r = 0; r < 8; r++) {
        float v = rowpart[r];
        v += __shfl_down_sync(0xffffffffu, v, 8, 16);
        v += __shfl_down_sync(0xffffffffu, v, 4, 16);
        v += __shfl_down_sync(0xffffffffu, v, 2, 16);
        v += __shfl_down_sync(0xffffffffu, v, 1, 16);
        if (tx == 0)
            g_part[((size_t)b*8 + jb)*NN + i0 + ty*8 + r] = v;
    }
}

__global__ void k_rsfin() {
    int b = blockIdx.x, i = threadIdx.x;
    float s = 0.f;
#pragma unroll
    for (int j = 0; j < 8; j++) s += g_part[((size_t)b*8 + j)*NN + i];
    g_rsinv[b*NN + i] = 1.f / s;
}

// ---------------- layernorm stats + final fuse ----------------
__global__ void k_lnstats() {
    int b = blockIdx.x, path = blockIdx.y, t = threadIdx.x;
    size_t base = (size_t)b*(2*CC)*NN + (size_t)path*CC*NN;
    float s = 0.f, ss = 0.f;
    for (int i = t; i < CC*NN; i += 1024) {
        float v = g_sxa[base + i] + g_sxb[base + i];
        s += v; ss = fmaf(v, v, ss);
    }
    __shared__ float shs[1024], shq[1024];
    shs[t] = s; shq[t] = ss; __syncthreads();
    for (int o = 512; o > 0; o >>= 1) {
        if (t < o) { shs[t] += shs[t+o]; shq[t] += shq[t+o]; }
        __syncthreads();
    }
    if (t == 0) {
        float mean = shs[0] * (1.f/65536.f);
        float var  = shq[0] * (1.f/65536.f) - mean*mean;
        g_stats[(path*BB + b)*2 + 0] = mean;
        g_stats[(path*BB + b)*2 + 1] = rsqrtf(var + 1e-5f);
    }
}

__global__ void k_final(const float* __restrict__ ct, const float* __restrict__ ln_w,
                        const float* __restrict__ ln_b, float* __restrict__ out) {
    size_t idx = (size_t)blockIdx.x * 256 + threadIdx.x;
    int b  = (int)(idx / (CC*NN));
    int cn = (int)(idx % (CC*NN));
    float m1 = g_stats[b*2 + 0],            r1 = g_stats[b*2 + 1];
    float m2 = g_stats[(BB + b)*2 + 0],     r2 = g_stats[(BB + b)*2 + 1];
    float w = ln_w[cn], bb = ln_b[cn];
    size_t base = (size_t)b*(2*CC)*NN + cn;
    float z1v = g_sxa[base] + g_sxb[base];
    float z2v = g_sxa[base + (size_t)CC*NN] + g_sxb[base + (size_t)CC*NN];
    float xnew = (z1v - m1) * r1 * w + bb;
    float z2   = (z2v - m2) * r2 * w + bb;
    float ft = 0.5f * z2 * (1.f + erff(z2 * 0.70710678118654752f));
    float ctv = ct[idx];
    float ctn = xnew + ft * (ctv - xnew);
    float el  = (ctn > 0.f) ? ctn : expm1f(ctn);
    float xu  = g_xuai[idx];
    float ht  = xu + ft * (el - xu);
    out[idx] = ht;
    out[(size_t)BB*CC*NN + idx] = ctn;
}

// ---------------- host launch ----------------
struct DevPtrs {
    float *att, *gl, *g1, *g2, *wr, *h0a, *hT, *xuai;
    float *pa, *pb, *pc, *pd;
    float *l12, *l12s, *t12a, *t12b, *u12, *a12a, *a12b, *sxa, *sxb, *rsinv;
    bool init;
};
static DevPtrs P = {};

static void init_ptrs() {
    if (P.init) return;
    void* p;
#define GET(sym, field) cudaGetSymbolAddress(&p, sym); P.field = (float*)p;
    GET(g_att, att)  GET(g_gl, gl)   GET(g_g1, g1)   GET(g_g2, g2)
    GET(g_wr, wr)    GET(g_h0a, h0a) GET(g_hT, hT)   GET(g_xuai, xuai)
    GET(g_pa, pa)    GET(g_pb, pb)   GET(g_pc, pc)   GET(g_pd, pd)
    GET(g_l12, l12)  GET(g_l12s, l12s)
    GET(g_t12a, t12a) GET(g_t12b, t12b) GET(g_u12, u12)
    GET(g_a12a, a12a) GET(g_a12b, a12b) GET(g_sxa, sxa) GET(g_sxb, sxb)
    GET(g_rsinv, rsinv)
#undef GET
    P.init = true;
}

extern "C" void kernel_launch(void* const* d_in, const int* in_sizes, int n_in,
                              void* d_out, int out_size) {
    const float* x      = (const float*)d_in[0];
    const float* ct     = (const float*)d_in[1];
    const float* graph  = (const float*)d_in[2];
    const float* emb_w  = (const float*)d_in[3];
    const float* emb_b  = (const float*)d_in[4];
    const float* emb2_w = (const float*)d_in[5];
    const float* emb2_b = (const float*)d_in[6];
    const float* att_W  = (const float*)d_in[7];
    const float* att_a  = (const float*)d_in[8];
    // d_in[9] = att_GL : unused (softmax output strictly positive => mask no-op)
    const float* uai_w  = (const float*)d_in[10];
    const float* uai_b  = (const float*)d_in[11];
    const float* lin1_w = (const float*)d_in[12];
    const float* lin2_w = (const float*)d_in[13];
    const float* lin2_b = (const float*)d_in[14];
    const float* ln_w   = (const float*)d_in[15];
    const float* ln_b   = (const float*)d_in[16];
    float* out = (float*)d_out;

    init_ptrs();

    const size_t GSTRIDE = (size_t)NN * NN;
    const size_t SB = (size_t)CC * NN;
    const size_t DB = (size_t)2 * CC * NN;
    const dim3 gridC1(NN/64, BB, 1);
    const dim3 gridC2(NN/64, BB, 2);

    // graph laplacians (K-major, tf32-rounded) + rounded emb2 weights
    k_lap_d <<<dim3(NN, 2), 256>>>(graph);
    k_lapT  <<<dim3(NN, 2), 256>>>(graph);
    k_wround<<<NN*NN/1024, 256>>>(emb2_w);

    // embedding: conv1d+leakyrelu (rounded), node-linear (tf32 MMA, pairs stacked, K-split 4)
    k_emb1  <<<dim3(BB, NN/256), 256>>>(x, emb_w, emb_b);
    mma_gemm<<<dim3(8, BB/2, 4), 256>>>(P.h0a, DB, 128, P.wr, 0, 4,
                                        nullptr, nullptr, emb2_b,
                                        P.pa, P.pb, P.pc, P.pd, DB);

    // attention (hT rounded: A operand of att MMA)
    chanmixD<<<gridC1, 128>>>(P.pa, P.pb, P.pc, P.pd, 0, SB, 0,
                              att_W, nullptr, att_W, nullptr, 1, 1, P.hT, SB,
                              nullptr, nullptr);
    k_s12   <<<dim3(BB, NN/256), 256>>>(att_a);
    k_attrow<<<dim3(NN, BB), 256>>>();
    mma_gemm<<<dim3(8, BB, 2), 256>>>(P.hT, SB, 64, P.att, GSTRIDE, 2,
                                      nullptr, nullptr, nullptr,
                                      P.pa, P.pb, nullptr, nullptr, SB);

    // UAI: xuai = uai_w @ relu(pa+pb) + uai_b  (full fp32 — feeds gram & final)
    chanmixD<<<gridC1, 128>>>(P.pa, P.pb, nullptr, nullptr, 1, SB, 0,
                              uai_w, uai_b, uai_w, uai_b, 0, 0, P.xuai, SB,
                              nullptr, nullptr);

    // learned adjacency (rounded gl, row-sums over rounded values)
    k_sq   <<<dim3(BB, NN/256), 256>>>();
    k_gram <<<dim3(NN/64, NN/128, BB), 128>>>();
    k_rsfin<<<BB, 1024>>>();

    // l1/l2 stacked propagation (rounded); rsinv-scaled copy for gl GEMM
    chanmixD<<<gridC2, 128>>>(P.xuai, nullptr, nullptr, nullptr, 0, SB, 0,
                              lin1_w, nullptr, lin2_w, lin2_b, 0, 1, P.l12, DB,
                              P.l12s, P.rsinv);

    // l12s @ gl -> a12a/b ; l12 @ g1 -> t12a/b
    mma_gemm<<<dim3(8, BB, 2), 256>>>(P.l12s, DB, 128, P.gl, GSTRIDE, 2,
                                      nullptr, nullptr, nullptr,
                                      P.a12a, P.a12b, nullptr, nullptr, DB);
    mma_gemm<<<dim3(8, BB, 2), 256>>>(P.l12, DB, 128, P.g1, 0, 2,
                                      nullptr, nullptr, nullptr,
                                      P.t12a, P.t12b, nullptr, nullptr, DB);

    chanmixD<<<gridC2, 128>>>(P.t12a, P.t12b, nullptr, nullptr, 0, DB, SB,
                              lin1_w, nullptr, lin2_w, lin2_b, 0, 1, P.u12, DB,
                              nullptr, nullptr);

    // u12 @ g2 + a12 (per-ks addend) -> sxa/sxb
    mma_gemm<<<dim3(8, BB, 2), 256>>>(P.u12, DB, 128, P.g2, 0, 2,
                                      P.a12a, P.a12b, nullptr,
                                      P.sxa, P.sxb, nullptr, nullptr, DB);

    // layernorm + gates + output
    k_lnstats<<<dim3(BB, 2), 1024>>>();
    k_final  <<<(BB*CC*NN)/256, 256>>>(ct, ln_w, ln_b, out);
}

// round 10
// speedup vs baseline: 2.1835x; 1.0816x over previous
#include <cuda_runtime.h>
#include <math.h>
#include <stdint.h>

#define BB 16
#define NN 1024
#define CC 64
#define CIN 16
#define PADN 68
#define PADW 132

typedef unsigned long long u64;

// ---------------- fp32x2 helpers ----------------
__device__ __forceinline__ u64 splat2(float v) {
    u64 r; asm("mov.b64 %0, {%1, %1};" : "=l"(r) : "f"(v)); return r;
}
__device__ __forceinline__ void ffma2(u64& d, u64 a, u64 b) {
    asm("fma.rn.f32x2 %0, %1, %2, %0;" : "+l"(d) : "l"(a), "l"(b));
}
__device__ __forceinline__ float2 unpack2(u64 v) {
    float2 r; asm("mov.b64 {%0, %1}, %2;" : "=f"(r.x), "=f"(r.y) : "l"(v)); return r;
}

#define INNER_STEP(ASP, GSP)                                                   \
    {                                                                          \
        ulonglong2 av0 = *(const ulonglong2*)(ASP);                            \
        ulonglong2 av1 = *(const ulonglong2*)((ASP) + 4);                      \
        float4 g0 = *(const float4*)(GSP);                                     \
        float4 g1 = *(const float4*)((GSP) + 4);                               \
        u64 s0=splat2(g0.x), s1=splat2(g0.y), s2=splat2(g0.z), s3=splat2(g0.w);\
        u64 s4=splat2(g1.x), s5=splat2(g1.y), s6=splat2(g1.z), s7=splat2(g1.w);\
        ffma2(acc[0][0],av0.x,s0); ffma2(acc[0][1],av0.x,s1);                  \
        ffma2(acc[0][2],av0.x,s2); ffma2(acc[0][3],av0.x,s3);                  \
        ffma2(acc[0][4],av0.x,s4); ffma2(acc[0][5],av0.x,s5);                  \
        ffma2(acc[0][6],av0.x,s6); ffma2(acc[0][7],av0.x,s7);                  \
        ffma2(acc[1][0],av0.y,s0); ffma2(acc[1][1],av0.y,s1);                  \
        ffma2(acc[1][2],av0.y,s2); ffma2(acc[1][3],av0.y,s3);                  \
        ffma2(acc[1][4],av0.y,s4); ffma2(acc[1][5],av0.y,s5);                  \
        ffma2(acc[1][6],av0.y,s6); ffma2(acc[1][7],av0.y,s7);                  \
        ffma2(acc[2][0],av1.x,s0); ffma2(acc[2][1],av1.x,s1);                  \
        ffma2(acc[2][2],av1.x,s2); ffma2(acc[2][3],av1.x,s3);                  \
        ffma2(acc[2][4],av1.x,s4); ffma2(acc[2][5],av1.x,s5);                  \
        ffma2(acc[2][6],av1.x,s6); ffma2(acc[2][7],av1.x,s7);                  \
        ffma2(acc[3][0],av1.y,s0); ffma2(acc[3][1],av1.y,s1);                  \
        ffma2(acc[3][2],av1.y,s2); ffma2(acc[3][3],av1.y,s3);                  \
        ffma2(acc[3][4],av1.y,s4); ffma2(acc[3][5],av1.y,s5);                  \
        ffma2(acc[3][6],av1.y,s6); ffma2(acc[3][7],av1.y,s7);                  \
    }

// ---------------- mma.sync tf32 + cp.async helpers ----------------
__device__ __forceinline__ uint32_t smem_u32(const void* p) {
    uint32_t a;
    asm("{ .reg .u64 t; cvta.to.shared.u64 t, %1; cvt.u32.u64 %0, t; }" : "=r"(a) : "l"(p));
    return a;
}
__device__ __forceinline__ float rnd_tf32(float f) {
    uint32_t r; asm("cvt.rna.tf32.f32 %0, %1;" : "=r"(r) : "f"(f));
    return __uint_as_float(r);
}
#define LDSM4(r0, r1, r2, r3, addr)                                            \
    asm volatile("ldmatrix.sync.aligned.m8n8.x4.shared.b16 {%0,%1,%2,%3}, [%4];" \
        : "=r"(r0), "=r"(r1), "=r"(r2), "=r"(r3) : "r"(addr))
#define MMA_TF32(c, a0, a1, a2, a3, b0, b1)                                    \
    asm volatile("mma.sync.aligned.m16n8k8.row.col.f32.tf32.tf32.f32 "         \
        "{%0,%1,%2,%3}, {%4,%5,%6,%7}, {%8,%9}, {%0,%1,%2,%3};"                \
        : "+f"((c)[0]), "+f"((c)[1]), "+f"((c)[2]), "+f"((c)[3])               \
        : "r"(a0), "r"(a1), "r"(a2), "r"(a3), "r"(b0), "r"(b1))
__device__ __forceinline__ void cp16(uint32_t dst, const void* src) {
    asm volatile("cp.async.cg.shared.global [%0], [%1], 16;" :: "r"(dst), "l"(src));
}
#define CP_COMMIT()  asm volatile("cp.async.commit_group;" ::: "memory")
#define CP_WAIT1()   asm volatile("cp.async.wait_group 1;" ::: "memory")
#define CP_WAIT0()   asm volatile("cp.async.wait_group 0;" ::: "memory")

// ---------------- static device scratch ----------------
__device__ float g_gl  [BB*NN*NN];
__device__ float g_g1  [NN*NN];
__device__ float g_g2  [NN*NN];
__device__ float g_wr  [NN*NN];
__device__ float g_d   [2*NN];
__device__ float g_h0a [BB*CC*NN];
__device__ float g_hT  [BB*CC*NN];
__device__ float g_xuai[BB*CC*NN];
__device__ float g_pa  [BB*CC*NN];
__device__ float g_pb  [BB*CC*NN];
__device__ float g_pc  [BB*CC*NN];
__device__ float g_pd  [BB*CC*NN];
__device__ float g_l12 [BB*2*CC*NN];
__device__ float g_l12s[BB*2*CC*NN];
__device__ float g_t12a[BB*2*CC*NN];
__device__ float g_t12b[BB*2*CC*NN];
__device__ float g_u12 [BB*2*CC*NN];
__device__ float g_a12a[BB*2*CC*NN];
__device__ float g_a12b[BB*2*CC*NN];
__device__ float g_sxa [BB*2*CC*NN];
__device__ float g_sxb [BB*2*CC*NN];
__device__ float g_s1  [BB*NN];
__device__ float g_s2  [BB*NN];
__device__ float g_mxs2[BB];
__device__ float g_amx [BB*NN];
__device__ float g_ainv[BB*NN];
__device__ float g_sq  [BB*NN];
__device__ float g_part[BB*8*NN];
__device__ float g_rsinv[BB*NN];
__device__ float g_stats[2*BB*2];

// =========================================================================
// mma_gemm (tf32): C_ks[b,c,n] = sum_{k in split ks} A[b,c,k] * B[b,n,k]
// =========================================================================
#define TPAD 20
__global__ void __launch_bounds__(256, 2)
mma_gemm(const float* __restrict__ A, size_t aBatch, int mvalid,
         const float* __restrict__ B, size_t bBatch, int nsplit,
         const float* __restrict__ add0, const float* __restrict__ add1,
         const float* __restrict__ biasN,
         float* __restrict__ C0, float* __restrict__ C1,
         float* __restrict__ C2, float* __restrict__ C3, size_t cBatch)
{
    __shared__ uint32_t As[2][128*TPAD];
    __shared__ uint32_t Bs[2][128*TPAD];

    const int tid  = threadIdx.x;
    const int lane = tid & 31;
    const int wid  = tid >> 5;
    const int bidx = blockIdx.y;
    const int n0   = blockIdx.x * 128;
    const int ks   = blockIdx.z;
    const int kPer = NN / nsplit;
    const int T    = kPer / 16;
    const int k0b  = ks * kPer;

    const float* Ab = A + (size_t)bidx * aBatch + k0b;
    const float* Bb = B + (size_t)bidx * bBatch + (size_t)n0 * NN + k0b;

    const int frow0 = tid >> 2;
    const int frow1 = 64 + (tid >> 2);
    const int fkq   = (tid & 3) * 4;

    const float* aP0 = Ab + (size_t)frow0 * NN + fkq;
    const float* aP1 = Ab + (size_t)((frow1 < mvalid) ? frow1 : 0) * NN + fkq;
    const float* bP0 = Bb + (size_t)frow0 * NN + fkq;
    const float* bP1 = Bb + (size_t)frow1 * NN + fkq;

    const uint32_t aSm = smem_u32(&As[0][0]);
    const uint32_t bSm = smem_u32(&Bs[0][0]);
    const uint32_t aFill  = aSm + (frow0*TPAD + fkq) * 4;
    const uint32_t aFill1 = aSm + (frow1*TPAD + fkq) * 4;
    const uint32_t bFill  = bSm + (frow0*TPAD + fkq) * 4;
    const uint32_t bFill1 = bSm + (frow1*TPAD + fkq) * 4;
    const uint32_t bufStride = 128*TPAD*4;

    const int aRowOff = (lane & 15) * TPAD + (lane >> 4) * 4;
    const int bRowOff = ((lane >> 4) * 8 + (lane & 7)) * TPAD + ((lane >> 3) & 1) * 4;

    const int mbase = (wid >> 2) * 64;
    const int nbase = (wid & 3) * 32;

    float c[4][4][4];
#pragma unroll
    for (int i = 0; i < 4; i++)
#pragma unroll
        for (int j = 0; j < 4; j++)
#pragma unroll
            for (int q = 0; q < 4; q++) c[i][j][q] = 0.f;

    cp16(aFill,  aP0); cp16(aFill1, aP1);
    cp16(bFill,  bP0); cp16(bFill1, bP1);
    CP_COMMIT();

    for (int t = 0; t < T; ++t) {
        const int cur = t & 1;
        if (t + 1 < T) {
            const uint32_t off = (uint32_t)((t+1) & 1) * bufStride;
            const int ko = (t + 1) * 16;
            cp16(aFill  + off, aP0 + ko);
            cp16(aFill1 + off, aP1 + ko);
            cp16(bFill  + off, bP0 + ko);
            cp16(bFill1 + off, bP1 + ko);
            CP_COMMIT();
            CP_WAIT1();
        } else {
            CP_WAIT0();
        }
        __syncthreads();
        {
            const uint32_t aCur = aSm + cur * bufStride;
            const uint32_t bCur = bSm + cur * bufStride;
#pragma unroll
            for (int kk = 0; kk < 16; kk += 8) {
                uint32_t a[4][4];
#pragma unroll
                for (int mt = 0; mt < 4; mt++) {
                    uint32_t addr = aCur + ((mbase + mt*16)*TPAD + aRowOff + kk) * 4;
                    LDSM4(a[mt][0], a[mt][1], a[mt][2], a[mt][3], addr);
                }
                uint32_t bfr[4][2];
#pragma unroll
                for (int np = 0; np < 2; np++) {
                    uint32_t addr = bCur + ((nbase + np*16)*TPAD + bRowOff + kk) * 4;
                    LDSM4(bfr[np*2][0], bfr[np*2][1], bfr[np*2+1][0], bfr[np*2+1][1], addr);
                }
#pragma unroll
                for (int mt = 0; mt < 4; mt++)
#pragma unroll
                    for (int nt = 0; nt < 4; nt++)
                        MMA_TF32(c[mt][nt], a[mt][0], a[mt][1], a[mt][2], a[mt][3],
                                 bfr[nt][0], bfr[nt][1]);
            }
        }
        __syncthreads();
    }

    if (mbase >= mvalid) return;
    float* C = (ks == 0) ? C0 : (ks == 1) ? C1 : (ks == 2) ? C2 : C3;
    const float* add = (ks == 0) ? add0 : (ks == 1) ? add1 : nullptr;
    float* Cb = C + (size_t)bidx * cBatch;
    const float* Adb = add ? add + (size_t)bidx * cBatch : nullptr;
    const int gid = lane >> 2, tq = lane & 3;
#pragma unroll
    for (int mt = 0; mt < 4; mt++) {
        const int r = mbase + mt*16 + gid;
#pragma unroll
        for (int nt = 0; nt < 4; nt++) {
            const int col = n0 + nbase + nt*8 + tq*2;
            float2 v0 = { c[mt][nt][0], c[mt][nt][1] };
            float2 v1 = { c[mt][nt][2], c[mt][nt][3] };
            if (biasN && ks == 0) {
                float b0 = biasN[col], b1 = biasN[col+1];
                v0.x += b0; v0.y += b1; v1.x += b0; v1.y += b1;
            }
            if (Adb) {
                float2 d0 = *(const float2*)(Adb + (size_t)r * NN + col);
                float2 d1 = *(const float2*)(Adb + (size_t)(r+8) * NN + col);
                v0.x += d0.x; v0.y += d0.y; v1.x += d1.x; v1.y += d1.y;
            }
            *(float2*)(Cb + (size_t)r * NN + col)     = v0;
            *(float2*)(Cb + (size_t)(r+8) * NN + col) = v1;
        }
    }
}

// =========================================================================
// mma_gemm_att: attention MMA with on-the-fly B generation.
// B[n,k] = rnd_tf32( exp(lrelu(s1[n]+s2[k]) - amx[n]) * ainv[n] )
// A = hT (64 valid rows). nsplit=2 fixed. C_ks -> C0/C1.
// =========================================================================
__device__ __forceinline__ float attval(float s1v, float s2v, float m, float iv) {
    float e = s1v + s2v;
    e = (e > 0.f) ? e : 0.01f * e;
    return rnd_tf32(__expf(e - m) * iv);
}

__global__ void __launch_bounds__(256, 2)
mma_gemm_att(const float* __restrict__ A, size_t aBatch,
             float* __restrict__ C0, float* __restrict__ C1, size_t cBatch)
{
    __shared__ uint32_t As[2][128*TPAD];
    __shared__ float    Bs[2][128*TPAD];

    const int tid  = threadIdx.x;
    const int lane = tid & 31;
    const int wid  = tid >> 5;
    const int bidx = blockIdx.y;
    const int n0   = blockIdx.x * 128;
    const int ks   = blockIdx.z;
    const int k0b  = ks * 512;
    const int T    = 32;

    const float* Ab = A + (size_t)bidx * aBatch + k0b;

    const int frow0 = tid >> 2;
    const int frow1 = 64 + (tid >> 2);
    const int fkq   = (tid & 3) * 4;

    const float* aP0 = Ab + (size_t)frow0 * NN + fkq;
    const float* aP1 = Ab;   // rows >= 64 dummy (read row 0)

    // per-row attention constants (rows n0+frow0 / n0+frow1)
    const float s1v0 = g_s1 [bidx*NN + n0 + frow0];
    const float m0   = g_amx[bidx*NN + n0 + frow0];
    const float iv0  = g_ainv[bidx*NN + n0 + frow0];
    const float s1v1 = g_s1 [bidx*NN + n0 + frow1];
    const float m1   = g_amx[bidx*NN + n0 + frow1];
    const float iv1  = g_ainv[bidx*NN + n0 + frow1];
    const float* s2p = g_s2 + bidx*NN + k0b + fkq;

    const uint32_t aSm = smem_u32(&As[0][0]);
    const uint32_t bSm = smem_u32(&Bs[0][0]);
    const uint32_t aFill  = aSm + (frow0*TPAD + fkq) * 4;
    const uint32_t aFill1 = aSm + (frow1*TPAD + fkq) * 4;
    const uint32_t bufStride = 128*TPAD*4;

    const int aRowOff = (lane & 15) * TPAD + (lane >> 4) * 4;
    const int bRowOff = ((lane >> 4) * 8 + (lane & 7)) * TPAD + ((lane >> 3) & 1) * 4;

    const int mbase = (wid >> 2) * 64;
    const int nbase = (wid & 3) * 32;

    float c[4][4][4];
#pragma unroll
    for (int i = 0; i < 4; i++)
#pragma unroll
        for (int j = 0; j < 4; j++)
#pragma unroll
            for (int q = 0; q < 4; q++) c[i][j][q] = 0.f;

    // prologue: A via cp.async, B computed
    cp16(aFill,  aP0); cp16(aFill1, aP1 + fkq);
    CP_COMMIT();
    {
        float4 s2v = *(const float4*)(s2p);
        float4 b0 = { attval(s1v0, s2v.x, m0, iv0), attval(s1v0, s2v.y, m0, iv0),
                      attval(s1v0, s2v.z, m0, iv0), attval(s1v0, s2v.w, m0, iv0) };
        float4 b1 = { attval(s1v1, s2v.x, m1, iv1), attval(s1v1, s2v.y, m1, iv1),
                      attval(s1v1, s2v.z, m1, iv1), attval(s1v1, s2v.w, m1, iv1) };
        *(float4*)&Bs[0][frow0*TPAD + fkq] = b0;
        *(float4*)&Bs[0][frow1*TPAD + fkq] = b1;
    }
    __syncthreads();   // prologue B visible before first compute

    for (int t = 0; t < T; ++t) {
        const int cur = t & 1;
        if (t + 1 < T) {
            const int nxt = (t+1) & 1;
            const uint32_t off = (uint32_t)nxt * bufStride;
            const int ko = (t + 1) * 16;
            cp16(aFill  + off, aP0 + ko);
            cp16(aFill1 + off, aP1 + ko + fkq);
            CP_COMMIT();
            float4 s2v = *(const float4*)(s2p + ko);
            float4 b0 = { attval(s1v0, s2v.x, m0, iv0), attval(s1v0, s2v.y, m0, iv0),
                          attval(s1v0, s2v.z, m0, iv0), attval(s1v0, s2v.w, m0, iv0) };
            float4 b1 = { attval(s1v1, s2v.x, m1, iv1), attval(s1v1, s2v.y, m1, iv1),
                          attval(s1v1, s2v.z, m1, iv1), attval(s1v1, s2v.w, m1, iv1) };
            *(float4*)&Bs[nxt][frow0*TPAD + fkq] = b0;
            *(float4*)&Bs[nxt][frow1*TPAD + fkq] = b1;
            CP_WAIT1();
        } else {
            CP_WAIT0();
        }
        __syncthreads();
        {
            const uint32_t aCur = aSm + cur * bufStride;
            const uint32_t bCur = bSm + cur * bufStride;
#pragma unroll
            for (int kk = 0; kk < 16; kk += 8) {
                uint32_t a[4][4];
#pragma unroll
                for (int mt = 0; mt < 4; mt++) {
                    uint32_t addr = aCur + ((mbase + mt*16)*TPAD + aRowOff + kk) * 4;
                    LDSM4(a[mt][0], a[mt][1], a[mt][2], a[mt][3], addr);
                }
                uint32_t bfr[4][2];
#pragma unroll
                for (int np = 0; np < 2; np++) {
                    uint32_t addr = bCur + ((nbase + np*16)*TPAD + bRowOff + kk) * 4;
                    LDSM4(bfr[np*2][0], bfr[np*2][1], bfr[np*2+1][0], bfr[np*2+1][1], addr);
                }
#pragma unroll
                for (int mt = 0; mt < 4; mt++)
#pragma unroll
                    for (int nt = 0; nt < 4; nt++)
                        MMA_TF32(c[mt][nt], a[mt][0], a[mt][1], a[mt][2], a[mt][3],
                                 bfr[nt][0], bfr[nt][1]);
            }
        }
        __syncthreads();
    }

    if (mbase >= 64) return;   // only 64 valid A rows
    float* Cb = (ks ? C1 : C0) + (size_t)bidx * cBatch;
    const int gid = lane >> 2, tq = lane & 3;
#pragma unroll
    for (int mt = 0; mt < 4; mt++) {
        const int r = mbase + mt*16 + gid;
#pragma unroll
        for (int nt = 0; nt < 4; nt++) {
            const int col = n0 + nbase + nt*8 + tq*2;
            float2 v0 = { c[mt][nt][0], c[mt][nt][1] };
            float2 v1 = { c[mt][nt][2], c[mt][nt][3] };
            *(float2*)(Cb + (size_t)r * NN + col)     = v0;
            *(float2*)(Cb + (size_t)(r+8) * NN + col) = v1;
        }
    }
}

// ---------------- tf32 rounding copy ----------------
__global__ void k_wround(const float* __restrict__ src) {
    size_t i = ((size_t)blockIdx.x * 256 + threadIdx.x) * 4;
    float4 v = *(const float4*)(src + i);
    float4 w = { rnd_tf32(v.x), rnd_tf32(v.y), rnd_tf32(v.z), rnd_tf32(v.w) };
    *(float4*)(g_wr + i) = w;
}

// ---------------- laplacian prep ----------------
__global__ void k_lap_d(const float* __restrict__ graph) {
    int i = blockIdx.x, k = blockIdx.y, t = threadIdx.x;
    const float* row = graph + (size_t)k*NN*NN + (size_t)i*NN;
    float s = 0.f;
    for (int j = t; j < NN; j += 256) s += row[j];
    __shared__ float sh[256];
    sh[t] = s; __syncthreads();
    for (int o = 128; o > 0; o >>= 1) { if (t < o) sh[t] += sh[t+o]; __syncthreads(); }
    if (t == 0) g_d[k*NN + i] = rsqrtf(sh[0] + 1.0f);
}

__global__ void k_lapT(const float* __restrict__ graph) {
    int kg = blockIdx.y, m = blockIdx.x, t = threadIdx.x;
    const float* src = graph + (size_t)kg*NN*NN + (size_t)m*NN;
    float* dst = ((kg == 0) ? g_g1 : g_g2) + (size_t)m*NN;
    const float* d = g_d + kg*NN;
    float dm = d[m];
#pragma unroll
    for (int q = 0; q < 4; q++) {
        int k = t + 256*q;
        float v = src[k] + ((m == k) ? 1.f : 0.f);
        dst[k] = rnd_tf32(v * dm * d[k]);
    }
}

// ---------------- embedding stage 1 (wider grid: z splits e-range) ----------
__global__ void k_emb1(const float* __restrict__ x, const float* __restrict__ emb_w,
                       const float* __restrict__ emb_b) {
    __shared__ float w[CC*CIN];
    __shared__ float bsm[CC];
    int t = threadIdx.x;
    for (int i = t; i < CC*CIN; i += 256) w[i] = emb_w[i];
    if (t < CC) bsm[t] = emb_b[t];
    __syncthreads();
    int b = blockIdx.x;
    int n = blockIdx.y * 256 + t;
    int e0 = blockIdx.z * 16;
    float xv[CIN];
    const float* xp = x + (size_t)b*CIN*NN + n;
#pragma unroll
    for (int c = 0; c < CIN; c++) xv[c] = xp[(size_t)c*NN];
    float* out = g_h0a + (size_t)b*CC*NN + n;
    for (int e = e0; e < e0 + 16; e++) {
        float s = bsm[e];
#pragma unroll
        for (int c = 0; c < CIN; c++) s = fmaf(w[e*CIN + c], xv[c], s);
        float lv = (s > 0.f) ? s : 0.01f*s;
        out[(size_t)e*NN] = rnd_tf32(lv);
    }
}

// ------- 64x64 channel mix -------
__global__ void __launch_bounds__(128)
chanmixD(const float* __restrict__ in, const float* __restrict__ in2,
         const float* __restrict__ in3, const float* __restrict__ in4,
         int reluIn, size_t inBstride, size_t inZoff,
         const float* __restrict__ Wa, const float* __restrict__ ba,
         const float* __restrict__ Wb, const float* __restrict__ bb_,
         int trans, int roundOut, float* __restrict__ out, size_t outBstride,
         float* __restrict__ out2, const float* __restrict__ nScale) {
    const int z = blockIdx.z;
    const float* W    = z ? Wb  : Wa;
    const float* bias = z ? bb_ : ba;
    const int b = blockIdx.y, n0 = blockIdx.x * 64;
    __shared__ float Ms[64*PADN];
    __shared__ float Xs[64*PADN];
    const int tid = threadIdx.x;
    for (int i = tid; i < 64*64; i += 128) {
        int o = i >> 6, k = i & 63;
        Ms[k*PADN + o] = trans ? W[k*64 + o] : W[o*64 + k];
    }
    const size_t boff = (size_t)b*inBstride + (size_t)z*inZoff + n0;
    for (int i = tid; i < 64*16; i += 128) {
        int k = i >> 4, n4 = (i & 15) * 4;
        size_t off = boff + (size_t)k*NN + n4;
        float4 v = *(const float4*)(in + off);
        if (in2) { float4 w2 = *(const float4*)(in2 + off); v.x+=w2.x; v.y+=w2.y; v.z+=w2.z; v.w+=w2.w; }
        if (in3) { float4 w3 = *(const float4*)(in3 + off); v.x+=w3.x; v.y+=w3.y; v.z+=w3.z; v.w+=w3.w; }
        if (in4) { float4 w4 = *(const float4*)(in4 + off); v.x+=w4.x; v.y+=w4.y; v.z+=w4.z; v.w+=w4.w; }
        if (reluIn) {
            v.x = fmaxf(v.x, 0.f); v.y = fmaxf(v.y, 0.f);
            v.z = fmaxf(v.z, 0.f); v.w = fmaxf(v.w, 0.f);
        }
        *(float4*)&Xs[k*PADN + n4] = v;
    }
    __syncthreads();
    const int tx = tid & 15, ty = tid >> 4;
    u64 acc[4][4] = {};
#pragma unroll 8
    for (int k = 0; k < 64; k++) {
        const float* mrow = &Ms[k*PADN + ty*8];
        ulonglong2 av0 = *(const ulonglong2*)(mrow);
        ulonglong2 av1 = *(const ulonglong2*)(mrow + 4);
        float4 xv = *(const float4*)&Xs[k*PADN + tx*4];
        u64 gs0 = splat2(xv.x), gs1 = splat2(xv.y), gs2 = splat2(xv.z), gs3 = splat2(xv.w);
        ffma2(acc[0][0], av0.x, gs0); ffma2(acc[0][1], av0.x, gs1);
        ffma2(acc[0][2], av0.x, gs2); ffma2(acc[0][3], av0.x, gs3);
        ffma2(acc[1][0], av0.y, gs0); ffma2(acc[1][1], av0.y, gs1);
        ffma2(acc[1][2], av0.y, gs2); ffma2(acc[1][3], av0.y, gs3);
        ffma2(acc[2][0], av1.x, gs0); ffma2(acc[2][1], av1.x, gs1);
        ffma2(acc[2][2], av1.x, gs2); ffma2(acc[2][3], av1.x, gs3);
        ffma2(acc[3][0], av1.y, gs0); ffma2(acc[3][1], av1.y, gs1);
        ffma2(acc[3][2], av1.y, gs2); ffma2(acc[3][3], av1.y, gs3);
    }
    float* outb = out + (size_t)b*outBstride + (size_t)z*CC*NN + n0;
    float* outb2 = out2 ? out2 + (size_t)b*outBstride + (size_t)z*CC*NN + n0 : nullptr;
    float4 sc = {1.f,1.f,1.f,1.f};
    if (outb2) sc = *(const float4*)(nScale + (size_t)b*NN + n0 + tx*4);
#pragma unroll
    for (int i = 0; i < 4; i++) {
        int o = ty*8 + 2*i;
        float b0 = bias ? bias[o]   : 0.f;
        float b1 = bias ? bias[o+1] : 0.f;
        float2 v0 = unpack2(acc[i][0]), v1 = unpack2(acc[i][1]);
        float2 v2 = unpack2(acc[i][2]), v3 = unpack2(acc[i][3]);
        float4 lo = {v0.x + b0, v1.x + b0, v2.x + b0, v3.x + b0};
        float4 hi = {v0.y + b1, v1.y + b1, v2.y + b1, v3.y + b1};
        if (roundOut) {
            lo.x = rnd_tf32(lo.x); lo.y = rnd_tf32(lo.y);
            lo.z = rnd_tf32(lo.z); lo.w = rnd_tf32(lo.w);
            hi.x = rnd_tf32(hi.x); hi.y = rnd_tf32(hi.y);
            hi.z = rnd_tf32(hi.z); hi.w = rnd_tf32(hi.w);
        }
        *(float4*)(outb + (size_t)o*NN + tx*4) = lo;
        *(float4*)(outb + (size_t)(o+1)*NN + tx*4) = hi;
        if (outb2) {
            float4 lo2 = {rnd_tf32(lo.x*sc.x), rnd_tf32(lo.y*sc.y),
                          rnd_tf32(lo.z*sc.z), rnd_tf32(lo.w*sc.w)};
            float4 hi2 = {rnd_tf32(hi.x*sc.x), rnd_tf32(hi.y*sc.y),
                          rnd_tf32(hi.z*sc.z), rnd_tf32(hi.w*sc.w)};
            *(float4*)(outb2 + (size_t)o*NN + tx*4) = lo2;
            *(float4*)(outb2 + (size_t)(o+1)*NN + tx*4) = hi2;
        }
    }
}

// ---------------- attention scores ----------------
__global__ void k_s12(const float* __restrict__ att_a) {
    __shared__ float a1[64], a2[64];
    int t = threadIdx.x;
    if (t < 64) a1[t] = att_a[t];
    else if (t < 128) a2[t-64] = att_a[t];
    __syncthreads();
    int b = blockIdx.x;
    int i = blockIdx.y * 256 + t;
    const float* h = g_hT + (size_t)b*CC*NN + i;
    float v1 = 0.f, v2 = 0.f;
#pragma unroll 8
    for (int c = 0; c < 64; c++) {
        float hv = h[(size_t)c*NN];
        v1 = fmaf(hv, a1[c], v1);
        v2 = fmaf(hv, a2[c], v2);
    }
    g_s1[b*NN + i] = v1;
    g_s2[b*NN + i] = v2;
}

__global__ void k_s2max() {
    int b = blockIdx.x, t = threadIdx.x;
    const float* s2 = g_s2 + b*NN;
    float mx = -1e30f;
    for (int j = t; j < NN; j += 256) mx = fmaxf(mx, s2[j]);
    __shared__ float sh[256];
    sh[t] = mx; __syncthreads();
    for (int o = 128; o > 0; o >>= 1) { if (t < o) sh[t] = fmaxf(sh[t], sh[t+o]); __syncthreads(); }
    if (t == 0) g_mxs2[b] = sh[0];
}

// per-row max (O(1) via monotone lrelu) + 1/sum
__global__ void k_attinv() {
    int b = blockIdx.y;
    int row = blockIdx.x * 8 + (threadIdx.x >> 5);
    int lane = threadIdx.x & 31;
    float s1v = g_s1[b*NN + row];
    float m = s1v + g_mxs2[b];
    m = (m > 0.f) ? m : 0.01f * m;
    const float* s2 = g_s2 + b*NN;
    float sum = 0.f;
    for (int j = lane; j < NN; j += 32) {
        float e = s1v + s2[j];
        e = (e > 0.f) ? e : 0.01f * e;
        sum += __expf(e - m);
    }
#pragma unroll
    for (int o = 16; o > 0; o >>= 1) sum += __shfl_down_sync(0xffffffffu, sum, o);
    if (lane == 0) {
        g_amx [b*NN + row] = m;
        g_ainv[b*NN + row] = 1.f / sum;
    }
}

// ---------------- learned adjacency ----------------
__global__ void k_sq() {
    int b = blockIdx.x, n = blockIdx.y * 256 + threadIdx.x;
    const float* xp = g_xuai + (size_t)b*CC*NN + n;
    float s = 0.f;
#pragma unroll 8
    for (int c = 0; c < CC; c++) { float v = xp[(size_t)c*NN]; s = fmaf(v, v, s); }
    g_sq[b*NN + n] = s;
}

__global__ void __launch_bounds__(128)
k_gram() {
    const int b  = blockIdx.z;
    const int i0 = blockIdx.x * 64;
    const int jb = blockIdx.y;
    const int j0 = jb * 128;
    __shared__ float Xi[64*PADN];
    __shared__ float Xj[64*PADW];
    const float* X = g_xuai + (size_t)b*CC*NN;
    const int tid = threadIdx.x;
    {
        int c = tid >> 1, o = (tid & 1) * 32;
        const float* src = X + (size_t)c*NN + i0 + o;
        float* dst = &Xi[c*PADN + o];
#pragma unroll
        for (int q = 0; q < 32; q += 4) *(float4*)(dst+q) = *(const float4*)(src+q);
    }
    {
        int c = tid >> 1, o = (tid & 1) * 64;
        const float* src = X + (size_t)c*NN + j0 + o;
        float* dst = &Xj[c*PADW + o];
#pragma unroll
        for (int q = 0; q < 64; q += 4) *(float4*)(dst+q) = *(const float4*)(src+q);
    }
    __syncthreads();
    const int tx = tid & 15, ty = tid >> 4;
    u64 acc[4][8] = {};
#pragma unroll 8
    for (int kk = 0; kk < 64; kk++) {
        const float* arow = &Xi[kk*PADN + ty*8];
        const float* grow = &Xj[kk*PADW + tx*8];
        INNER_STEP(arow, grow)
    }
    const float* sq = g_sq + b*NN;
    float* glb = g_gl + (size_t)b*NN*NN;
    float rowpart[8];
#pragma unroll
    for (int p = 0; p < 4; p++) {
        int i = i0 + ty*8 + 2*p;
        float sqa = sq[i], sqb = sq[i+1];
        float2 u[8];
#pragma unroll
        for (int j = 0; j < 8; j++) u[j] = unpack2(acc[p][j]);
        float oa[8], ob[8];
        float s0 = 0.f, s1 = 0.f;
#pragma unroll
        for (int q = 0; q < 8; q++) {
            int j = j0 + tx*8 + q;
            float d2a = fmaxf(sqa + sq[j] - 2.f*u[q].x, 0.f);
            float va = rnd_tf32(__expf(__expf(-d2a * (1.f/128.f)) + ((i == j) ? 1.f : 0.f)));
            oa[q] = va; s0 += va;
            float d2b = fmaxf(sqb + sq[j] - 2.f*u[q].y, 0.f);
            float vb = rnd_tf32(__expf(__expf(-d2b * (1.f/128.f)) + ((i+1 == j) ? 1.f : 0.f)));
            ob[q] = vb; s1 += vb;
        }
        rowpart[2*p]   = s0;
        rowpart[2*p+1] = s1;
        float4 a0 = {oa[0],oa[1],oa[2],oa[3]}, a1v = {oa[4],oa[5],oa[6],oa[7]};
        float4 b0 = {ob[0],ob[1],ob[2],ob[3]}, b1v = {ob[4],ob[5],ob[6],ob[7]};
        *(float4*)(glb + (size_t)i*NN + j0 + tx*8)         = a0;
        *(float4*)(glb + (size_t)i*NN + j0 + tx*8 + 4)     = a1v;
        *(float4*)(glb + (size_t)(i+1)*NN + j0 + tx*8)     = b0;
        *(float4*)(glb + (size_t)(i+1)*NN + j0 + tx*8 + 4) = b1v;
    }
#pragma unroll
    for (int r = 0; r < 8; r++) {
        float v = rowpart[r];
        v += __shfl_down_sync(0xffffffffu, v, 8, 16);
        v += __shfl_down_sync(0xffffffffu, v, 4, 16);
        v += __shfl_down_sync(0xffffffffu, v, 2, 16);
        v += __shfl_down_sync(0xffffffffu, v, 1, 16);
        if (tx == 0)
            g_part[((size_t)b*8 + jb)*NN + i0 + ty*8 + r] = v;
    }
}

__global__ void k_rsfin() {
    int b = blockIdx.x, i = threadIdx.x;
    float s = 0.f;
#pragma unroll
    for (int j = 0; j < 8; j++) s += g_part[((size_t)b*8 + j)*NN + i];
    g_rsinv[b*NN + i] = 1.f / s;
}

// ---------------- layernorm stats + final fuse ----------------
__global__ void k_lnstats() {
    int b = blockIdx.x, path = blockIdx.y, t = threadIdx.x;
    size_t base = (size_t)b*(2*CC)*NN + (size_t)path*CC*NN;
    float s = 0.f, ss = 0.f;
    for (int i = t; i < CC*NN; i += 1024) {
        float v = g_sxa[base + i] + g_sxb[base + i];
        s += v; ss = fmaf(v, v, ss);
    }
    __shared__ float shs[1024], shq[1024];
    shs[t] = s; shq[t] = ss; __syncthreads();
    for (int o = 512; o > 0; o >>= 1) {
        if (t < o) { shs[t] += shs[t+o]; shq[t] += shq[t+o]; }
        __syncthreads();
    }
    if (t == 0) {
        float mean = shs[0] * (1.f/65536.f);
        float var  = shq[0] * (1.f/65536.f) - mean*mean;
        g_stats[(path*BB + b)*2 + 0] = mean;
        g_stats[(path*BB + b)*2 + 1] = rsqrtf(var + 1e-5f);
    }
}

__global__ void k_final(const float* __restrict__ ct, const float* __restrict__ ln_w,
                        const float* __restrict__ ln_b, float* __restrict__ out) {
    size_t idx = (size_t)blockIdx.x * 256 + threadIdx.x;
    int b  = (int)(idx / (CC*NN));
    int cn = (int)(idx % (CC*NN));
    float m1 = g_stats[b*2 + 0],            r1 = g_stats[b*2 + 1];
    float m2 = g_stats[(BB + b)*2 + 0],     r2 = g_stats[(BB + b)*2 + 1];
    float w = ln_w[cn], bb = ln_b[cn];
    size_t base = (size_t)b*(2*CC)*NN + cn;
    float z1v = g_sxa[base] + g_sxb[base];
    float z2v = g_sxa[base + (size_t)CC*NN] + g_sxb[base + (size_t)CC*NN];
    float xnew = (z1v - m1) * r1 * w + bb;
    float z2   = (z2v - m2) * r2 * w + bb;
    float ft = 0.5f * z2 * (1.f + erff(z2 * 0.70710678118654752f));
    float ctv = ct[idx];
    float ctn = xnew + ft * (ctv - xnew);
    float el  = (ctn > 0.f) ? ctn : expm1f(ctn);
    float xu  = g_xuai[idx];
    float ht  = xu + ft * (el - xu);
    out[idx] = ht;
    out[(size_t)BB*CC*NN + idx] = ctn;
}

// ---------------- host launch ----------------
struct DevPtrs {
    float *gl, *g1, *g2, *wr, *h0a, *hT, *xuai;
    float *pa, *pb, *pc, *pd;
    float *l12, *l12s, *t12a, *t12b, *u12, *a12a, *a12b, *sxa, *sxb, *rsinv;
    bool init;
};
static DevPtrs P = {};

static void init_ptrs() {
    if (P.init) return;
    void* p;
#define GET(sym, field) cudaGetSymbolAddress(&p, sym); P.field = (float*)p;
    GET(g_gl, gl)   GET(g_g1, g1)   GET(g_g2, g2)
    GET(g_wr, wr)    GET(g_h0a, h0a) GET(g_hT, hT)   GET(g_xuai, xuai)
    GET(g_pa, pa)    GET(g_pb, pb)   GET(g_pc, pc)   GET(g_pd, pd)
    GET(g_l12, l12)  GET(g_l12s, l12s)
    GET(g_t12a, t12a) GET(g_t12b, t12b) GET(g_u12, u12)
    GET(g_a12a, a12a) GET(g_a12b, a12b) GET(g_sxa, sxa) GET(g_sxb, sxb)
    GET(g_rsinv, rsinv)
#undef GET
    P.init = true;
}

extern "C" void kernel_launch(void* const* d_in, const int* in_sizes, int n_in,
                              void* d_out, int out_size) {
    const float* x      = (const float*)d_in[0];
    const float* ct     = (const float*)d_in[1];
    const float* graph  = (const float*)d_in[2];
    const float* emb_w  = (const float*)d_in[3];
    const float* emb_b  = (const float*)d_in[4];
    const float* emb2_w = (const float*)d_in[5];
    const float* emb2_b = (const float*)d_in[6];
    const float* att_W  = (const float*)d_in[7];
    const float* att_a  = (const float*)d_in[8];
    // d_in[9] = att_GL : unused (softmax output strictly positive => mask no-op)
    const float* uai_w  = (const float*)d_in[10];
    const float* uai_b  = (const float*)d_in[11];
    const float* lin1_w = (const float*)d_in[12];
    const float* lin2_w = (const float*)d_in[13];
    const float* lin2_b = (const float*)d_in[14];
    const float* ln_w   = (const float*)d_in[15];
    const float* ln_b   = (const float*)d_in[16];
    float* out = (float*)d_out;

    init_ptrs();

    const size_t GSTRIDE = (size_t)NN * NN;
    const size_t SB = (size_t)CC * NN;
    const size_t DB = (size_t)2 * CC * NN;
    const dim3 gridC1(NN/64, BB, 1);
    const dim3 gridC2(NN/64, BB, 2);

    // graph laplacians (K-major, tf32-rounded) + rounded emb2 weights
    k_lap_d <<<dim3(NN, 2), 256>>>(graph);
    k_lapT  <<<dim3(NN, 2), 256>>>(graph);
    k_wround<<<NN*NN/1024, 256>>>(emb2_w);

    // embedding: conv1d+leakyrelu (rounded, wide grid), node-linear MMA (K-split 4)
    k_emb1  <<<dim3(BB, NN/256, 4), 256>>>(x, emb_w, emb_b);
    mma_gemm<<<dim3(8, BB/2, 4), 256>>>(P.h0a, DB, 128, P.wr, 0, 4,
                                        nullptr, nullptr, emb2_b,
                                        P.pa, P.pb, P.pc, P.pd, DB);

    // attention: hT (rounded), scores, row max/inv, MMA with on-the-fly B
    chanmixD<<<gridC1, 128>>>(P.pa, P.pb, P.pc, P.pd, 0, SB, 0,
                              att_W, nullptr, att_W, nullptr, 1, 1, P.hT, SB,
                              nullptr, nullptr);
    k_s12   <<<dim3(BB, NN/256), 256>>>(att_a);
    k_s2max <<<BB, 256>>>();
    k_attinv<<<dim3(NN/8, BB), 256>>>();
    mma_gemm_att<<<dim3(8, BB, 2), 256>>>(P.hT, SB, P.pa, P.pb, SB);

    // UAI: xuai = uai_w @ relu(pa+pb) + uai_b  (full fp32)
    chanmixD<<<gridC1, 128>>>(P.pa, P.pb, nullptr, nullptr, 1, SB, 0,
                              uai_w, uai_b, uai_w, uai_b, 0, 0, P.xuai, SB,
                              nullptr, nullptr);

    // learned adjacency (rounded gl, row-sums over rounded values)
    k_sq   <<<dim3(BB, NN/256), 256>>>();
    k_gram <<<dim3(NN/64, NN/128, BB), 128>>>();
    k_rsfin<<<BB, 1024>>>();

    // l1/l2 stacked propagation (rounded); rsinv-scaled copy for gl GEMM
    chanmixD<<<gridC2, 128>>>(P.xuai, nullptr, nullptr, nullptr, 0, SB, 0,
                              lin1_w, nullptr, lin2_w, lin2_b, 0, 1, P.l12, DB,
                              P.l12s, P.rsinv);

    // l12s @ gl -> a12a/b ; l12 @ g1 -> t12a/b
    mma_gemm<<<dim3(8, BB, 2), 256>>>(P.l12s, DB, 128, P.gl, GSTRIDE, 2,
                                      nullptr, nullptr, nullptr,
                                      P.a12a, P.a12b, nullptr, nullptr, DB);
    mma_gemm<<<dim3(8, BB, 2), 256>>>(P.l12, DB, 128, P.g1, 0, 2,
                                      nullptr, nullptr, nullptr,
                                      P.t12a, P.t12b, nullptr, nullptr, DB);

    chanmixD<<<gridC2, 128>>>(P.t12a, P.t12b, nullptr, nullptr, 0, DB, SB,
                              lin1_w, nullptr, lin2_w, lin2_b, 0, 1, P.u12, DB,
                              nullptr, nullptr);

    // u12 @ g2 + a12 (per-ks addend) -> sxa/sxb
    mma_gemm<<<dim3(8, BB, 2), 256>>>(P.u12, DB, 128, P.g2, 0, 2,
                                      P.a12a, P.a12b, nullptr,
                                      P.sxa, P.sxb, nullptr, nullptr, DB);

    // layernorm + gates + output
    k_lnstats<<<dim3(BB, 2), 1024>>>();
    k_final  <<<(BB*CC*NN)/256, 256>>>(ct, ln_w, ln_b, out);
}

// round 11
// speedup vs baseline: 2.4769x; 1.1344x over previous
#include <cuda_runtime.h>
#include <math.h>
#include <stdint.h>

#define BB 16
#define NN 1024
#define CC 64
#define CIN 16
#define PADN 68

typedef unsigned long long u64;

// ---------------- fp32x2 helpers (chanmix) ----------------
__device__ __forceinline__ u64 splat2(float v) {
    u64 r; asm("mov.b64 %0, {%1, %1};" : "=l"(r) : "f"(v)); return r;
}
__device__ __forceinline__ void ffma2(u64& d, u64 a, u64 b) {
    asm("fma.rn.f32x2 %0, %1, %2, %0;" : "+l"(d) : "l"(a), "l"(b));
}
__device__ __forceinline__ float2 unpack2(u64 v) {
    float2 r; asm("mov.b64 {%0, %1}, %2;" : "=f"(r.x), "=f"(r.y) : "l"(v)); return r;
}

// ---------------- mma.sync tf32 + cp.async helpers ----------------
__device__ __forceinline__ uint32_t smem_u32(const void* p) {
    uint32_t a;
    asm("{ .reg .u64 t; cvta.to.shared.u64 t, %1; cvt.u32.u64 %0, t; }" : "=r"(a) : "l"(p));
    return a;
}
__device__ __forceinline__ float rnd_tf32(float f) {
    uint32_t r; asm("cvt.rna.tf32.f32 %0, %1;" : "=r"(r) : "f"(f));
    return __uint_as_float(r);
}
#define LDSM4(r0, r1, r2, r3, addr)                                            \
    asm volatile("ldmatrix.sync.aligned.m8n8.x4.shared.b16 {%0,%1,%2,%3}, [%4];" \
        : "=r"(r0), "=r"(r1), "=r"(r2), "=r"(r3) : "r"(addr))
#define MMA_TF32(c, a0, a1, a2, a3, b0, b1)                                    \
    asm volatile("mma.sync.aligned.m16n8k8.row.col.f32.tf32.tf32.f32 "         \
        "{%0,%1,%2,%3}, {%4,%5,%6,%7}, {%8,%9}, {%0,%1,%2,%3};"                \
        : "+f"((c)[0]), "+f"((c)[1]), "+f"((c)[2]), "+f"((c)[3])               \
        : "r"(a0), "r"(a1), "r"(a2), "r"(a3), "r"(b0), "r"(b1))
__device__ __forceinline__ void cp16(uint32_t dst, const void* src) {
    asm volatile("cp.async.cg.shared.global [%0], [%1], 16;" :: "r"(dst), "l"(src));
}
#define CP_COMMIT()  asm volatile("cp.async.commit_group;" ::: "memory")
#define CP_WAIT1()   asm volatile("cp.async.wait_group 1;" ::: "memory")
#define CP_WAIT0()   asm volatile("cp.async.wait_group 0;" ::: "memory")

// ---------------- static device scratch ----------------
__device__ float g_gl  [BB*NN*NN];
__device__ float g_g1  [NN*NN];
__device__ float g_g2  [NN*NN];
__device__ float g_wr  [NN*NN];
__device__ float g_d   [2*NN];
__device__ float g_h0a [BB*CC*NN];
__device__ float g_hT  [BB*CC*NN];
__device__ float g_xuai[BB*CC*NN];
__device__ float g_xuaiT[BB*NN*CC];   // transposed + tf32-rounded
__device__ float g_pa  [BB*CC*NN];
__device__ float g_pb  [BB*CC*NN];
__device__ float g_pc  [BB*CC*NN];
__device__ float g_pd  [BB*CC*NN];
__device__ float g_l12 [BB*2*CC*NN];
__device__ float g_l12s[BB*2*CC*NN];
__device__ float g_t12a[BB*2*CC*NN];
__device__ float g_t12b[BB*2*CC*NN];
__device__ float g_u12 [BB*2*CC*NN];
__device__ float g_a12a[BB*2*CC*NN];
__device__ float g_a12b[BB*2*CC*NN];
__device__ float g_sxa [BB*2*CC*NN];
__device__ float g_sxb [BB*2*CC*NN];
__device__ float g_s1  [BB*NN];
__device__ float g_s2  [BB*NN];
__device__ float g_mxs2[BB];
__device__ float g_amx [BB*NN];
__device__ float g_ainv[BB*NN];
__device__ float g_sq  [BB*NN];
__device__ float g_part[BB*8*NN];
__device__ float g_rsinv[BB*NN];
__device__ float g_stats[2*BB*2];

// =========================================================================
// mma_gemm (tf32): C_ks[b,c,n] = sum_{k in split ks} A[b,c,k] * B[b,n,k]
// =========================================================================
#define TPAD 20
__global__ void __launch_bounds__(256, 2)
mma_gemm(const float* __restrict__ A, size_t aBatch, int mvalid,
         const float* __restrict__ B, size_t bBatch, int nsplit,
         const float* __restrict__ add0, const float* __restrict__ add1,
         const float* __restrict__ biasN,
         float* __restrict__ C0, float* __restrict__ C1,
         float* __restrict__ C2, float* __restrict__ C3, size_t cBatch)
{
    __shared__ uint32_t As[2][128*TPAD];
    __shared__ uint32_t Bs[2][128*TPAD];

    const int tid  = threadIdx.x;
    const int lane = tid & 31;
    const int wid  = tid >> 5;
    const int bidx = blockIdx.y;
    const int n0   = blockIdx.x * 128;
    const int ks   = blockIdx.z;
    const int kPer = NN / nsplit;
    const int T    = kPer / 16;
    const int k0b  = ks * kPer;

    const float* Ab = A + (size_t)bidx * aBatch + k0b;
    const float* Bb = B + (size_t)bidx * bBatch + (size_t)n0 * NN + k0b;

    const int frow0 = tid >> 2;
    const int frow1 = 64 + (tid >> 2);
    const int fkq   = (tid & 3) * 4;

    const float* aP0 = Ab + (size_t)frow0 * NN + fkq;
    const float* aP1 = Ab + (size_t)((frow1 < mvalid) ? frow1 : 0) * NN + fkq;
    const float* bP0 = Bb + (size_t)frow0 * NN + fkq;
    const float* bP1 = Bb + (size_t)frow1 * NN + fkq;

    const uint32_t aSm = smem_u32(&As[0][0]);
    const uint32_t bSm = smem_u32(&Bs[0][0]);
    const uint32_t aFill  = aSm + (frow0*TPAD + fkq) * 4;
    const uint32_t aFill1 = aSm + (frow1*TPAD + fkq) * 4;
    const uint32_t bFill  = bSm + (frow0*TPAD + fkq) * 4;
    const uint32_t bFill1 = bSm + (frow1*TPAD + fkq) * 4;
    const uint32_t bufStride = 128*TPAD*4;

    const int aRowOff = (lane & 15) * TPAD + (lane >> 4) * 4;
    const int bRowOff = ((lane >> 4) * 8 + (lane & 7)) * TPAD + ((lane >> 3) & 1) * 4;

    const int mbase = (wid >> 2) * 64;
    const int nbase = (wid & 3) * 32;

    float c[4][4][4];
#pragma unroll
    for (int i = 0; i < 4; i++)
#pragma unroll
        for (int j = 0; j < 4; j++)
#pragma unroll
            for (int q = 0; q < 4; q++) c[i][j][q] = 0.f;

    cp16(aFill,  aP0); cp16(aFill1, aP1);
    cp16(bFill,  bP0); cp16(bFill1, bP1);
    CP_COMMIT();

    for (int t = 0; t < T; ++t) {
        const int cur = t & 1;
        if (t + 1 < T) {
            const uint32_t off = (uint32_t)((t+1) & 1) * bufStride;
            const int ko = (t + 1) * 16;
            cp16(aFill  + off, aP0 + ko);
            cp16(aFill1 + off, aP1 + ko);
            cp16(bFill  + off, bP0 + ko);
            cp16(bFill1 + off, bP1 + ko);
            CP_COMMIT();
            CP_WAIT1();
        } else {
            CP_WAIT0();
        }
        __syncthreads();
        {
            const uint32_t aCur = aSm + cur * bufStride;
            const uint32_t bCur = bSm + cur * bufStride;
#pragma unroll
            for (int kk = 0; kk < 16; kk += 8) {
                uint32_t a[4][4];
#pragma unroll
                for (int mt = 0; mt < 4; mt++) {
                    uint32_t addr = aCur + ((mbase + mt*16)*TPAD + aRowOff + kk) * 4;
                    LDSM4(a[mt][0], a[mt][1], a[mt][2], a[mt][3], addr);
                }
                uint32_t bfr[4][2];
#pragma unroll
                for (int np = 0; np < 2; np++) {
                    uint32_t addr = bCur + ((nbase + np*16)*TPAD + bRowOff + kk) * 4;
                    LDSM4(bfr[np*2][0], bfr[np*2][1], bfr[np*2+1][0], bfr[np*2+1][1], addr);
                }
#pragma unroll
                for (int mt = 0; mt < 4; mt++)
#pragma unroll
                    for (int nt = 0; nt < 4; nt++)
                        MMA_TF32(c[mt][nt], a[mt][0], a[mt][1], a[mt][2], a[mt][3],
                                 bfr[nt][0], bfr[nt][1]);
            }
        }
        __syncthreads();
    }

    if (mbase >= mvalid) return;
    float* C = (ks == 0) ? C0 : (ks == 1) ? C1 : (ks == 2) ? C2 : C3;
    const float* add = (ks == 0) ? add0 : (ks == 1) ? add1 : nullptr;
    float* Cb = C + (size_t)bidx * cBatch;
    const float* Adb = add ? add + (size_t)bidx * cBatch : nullptr;
    const int gid = lane >> 2, tq = lane & 3;
#pragma unroll
    for (int mt = 0; mt < 4; mt++) {
        const int r = mbase + mt*16 + gid;
#pragma unroll
        for (int nt = 0; nt < 4; nt++) {
            const int col = n0 + nbase + nt*8 + tq*2;
            float2 v0 = { c[mt][nt][0], c[mt][nt][1] };
            float2 v1 = { c[mt][nt][2], c[mt][nt][3] };
            if (biasN && ks == 0) {
                float b0 = biasN[col], b1 = biasN[col+1];
                v0.x += b0; v0.y += b1; v1.x += b0; v1.y += b1;
            }
            if (Adb) {
                float2 d0 = *(const float2*)(Adb + (size_t)r * NN + col);
                float2 d1 = *(const float2*)(Adb + (size_t)(r+8) * NN + col);
                v0.x += d0.x; v0.y += d0.y; v1.x += d1.x; v1.y += d1.y;
            }
            *(float2*)(Cb + (size_t)r * NN + col)     = v0;
            *(float2*)(Cb + (size_t)(r+8) * NN + col) = v1;
        }
    }
}

// =========================================================================
// mma_gemm_att: attention MMA with on-the-fly B generation.
// =========================================================================
__device__ __forceinline__ float attval(float s1v, float s2v, float m, float iv) {
    float e = s1v + s2v;
    e = (e > 0.f) ? e : 0.01f * e;
    return rnd_tf32(__expf(e - m) * iv);
}

__global__ void __launch_bounds__(256, 2)
mma_gemm_att(const float* __restrict__ A, size_t aBatch,
             float* __restrict__ C0, float* __restrict__ C1, size_t cBatch)
{
    __shared__ uint32_t As[2][128*TPAD];
    __shared__ float    Bs[2][128*TPAD];

    const int tid  = threadIdx.x;
    const int lane = tid & 31;
    const int wid  = tid >> 5;
    const int bidx = blockIdx.y;
    const int n0   = blockIdx.x * 128;
    const int ks   = blockIdx.z;
    const int k0b  = ks * 512;
    const int T    = 32;

    const float* Ab = A + (size_t)bidx * aBatch + k0b;

    const int frow0 = tid >> 2;
    const int frow1 = 64 + (tid >> 2);
    const int fkq   = (tid & 3) * 4;

    const float* aP0 = Ab + (size_t)frow0 * NN + fkq;
    const float* aP1 = Ab;

    const float s1v0 = g_s1 [bidx*NN + n0 + frow0];
    const float m0   = g_amx[bidx*NN + n0 + frow0];
    const float iv0  = g_ainv[bidx*NN + n0 + frow0];
    const float s1v1 = g_s1 [bidx*NN + n0 + frow1];
    const float m1   = g_amx[bidx*NN + n0 + frow1];
    const float iv1  = g_ainv[bidx*NN + n0 + frow1];
    const float* s2p = g_s2 + bidx*NN + k0b + fkq;

    const uint32_t aSm = smem_u32(&As[0][0]);
    const uint32_t bSm = smem_u32(&Bs[0][0]);
    const uint32_t aFill  = aSm + (frow0*TPAD + fkq) * 4;
    const uint32_t aFill1 = aSm + (frow1*TPAD + fkq) * 4;
    const uint32_t bufStride = 128*TPAD*4;

    const int aRowOff = (lane & 15) * TPAD + (lane >> 4) * 4;
    const int bRowOff = ((lane >> 4) * 8 + (lane & 7)) * TPAD + ((lane >> 3) & 1) * 4;

    const int mbase = (wid >> 2) * 64;
    const int nbase = (wid & 3) * 32;

    float c[4][4][4];
#pragma unroll
    for (int i = 0; i < 4; i++)
#pragma unroll
        for (int j = 0; j < 4; j++)
#pragma unroll
            for (int q = 0; q < 4; q++) c[i][j][q] = 0.f;

    cp16(aFill,  aP0); cp16(aFill1, aP1 + fkq);
    CP_COMMIT();
    {
        float4 s2v = *(const float4*)(s2p);
        float4 b0 = { attval(s1v0, s2v.x, m0, iv0), attval(s1v0, s2v.y, m0, iv0),
                      attval(s1v0, s2v.z, m0, iv0), attval(s1v0, s2v.w, m0, iv0) };
        float4 b1 = { attval(s1v1, s2v.x, m1, iv1), attval(s1v1, s2v.y, m1, iv1),
                      attval(s1v1, s2v.z, m1, iv1), attval(s1v1, s2v.w, m1, iv1) };
        *(float4*)&Bs[0][frow0*TPAD + fkq] = b0;
        *(float4*)&Bs[0][frow1*TPAD + fkq] = b1;
    }
    __syncthreads();

    for (int t = 0; t < T; ++t) {
        const int cur = t & 1;
        if (t + 1 < T) {
            const int nxt = (t+1) & 1;
            const uint32_t off = (uint32_t)nxt * bufStride;
            const int ko = (t + 1) * 16;
            cp16(aFill  + off, aP0 + ko);
            cp16(aFill1 + off, aP1 + ko + fkq);
            CP_COMMIT();
            float4 s2v = *(const float4*)(s2p + ko);
            float4 b0 = { attval(s1v0, s2v.x, m0, iv0), attval(s1v0, s2v.y, m0, iv0),
                          attval(s1v0, s2v.z, m0, iv0), attval(s1v0, s2v.w, m0, iv0) };
            float4 b1 = { attval(s1v1, s2v.x, m1, iv1), attval(s1v1, s2v.y, m1, iv1),
                          attval(s1v1, s2v.z, m1, iv1), attval(s1v1, s2v.w, m1, iv1) };
            *(float4*)&Bs[nxt][frow0*TPAD + fkq] = b0;
            *(float4*)&Bs[nxt][frow1*TPAD + fkq] = b1;
            CP_WAIT1();
        } else {
            CP_WAIT0();
        }
        __syncthreads();
        {
            const uint32_t aCur = aSm + cur * bufStride;
            const uint32_t bCur = bSm + cur * bufStride;
#pragma unroll
            for (int kk = 0; kk < 16; kk += 8) {
                uint32_t a[4][4];
#pragma unroll
                for (int mt = 0; mt < 4; mt++) {
                    uint32_t addr = aCur + ((mbase + mt*16)*TPAD + aRowOff + kk) * 4;
                    LDSM4(a[mt][0], a[mt][1], a[mt][2], a[mt][3], addr);
                }
                uint32_t bfr[4][2];
#pragma unroll
                for (int np = 0; np < 2; np++) {
                    uint32_t addr = bCur + ((nbase + np*16)*TPAD + bRowOff + kk) * 4;
                    LDSM4(bfr[np*2][0], bfr[np*2][1], bfr[np*2+1][0], bfr[np*2+1][1], addr);
                }
#pragma unroll
                for (int mt = 0; mt < 4; mt++)
#pragma unroll
                    for (int nt = 0; nt < 4; nt++)
                        MMA_TF32(c[mt][nt], a[mt][0], a[mt][1], a[mt][2], a[mt][3],
                                 bfr[nt][0], bfr[nt][1]);
            }
        }
        __syncthreads();
    }

    if (mbase >= 64) return;
    float* Cb = (ks ? C1 : C0) + (size_t)bidx * cBatch;
    const int gid = lane >> 2, tq = lane & 3;
#pragma unroll
    for (int mt = 0; mt < 4; mt++) {
        const int r = mbase + mt*16 + gid;
#pragma unroll
        for (int nt = 0; nt < 4; nt++) {
            const int col = n0 + nbase + nt*8 + tq*2;
            float2 v0 = { c[mt][nt][0], c[mt][nt][1] };
            float2 v1 = { c[mt][nt][2], c[mt][nt][3] };
            *(float2*)(Cb + (size_t)r * NN + col)     = v0;
            *(float2*)(Cb + (size_t)(r+8) * NN + col) = v1;
        }
    }
}

// =========================================================================
// k_gram_mma: gl = transform( XtT @ XtT^T ), row partial sums fused.
// A[m,k] = xuaiT[b][i0+m][k], B[n,k] = xuaiT[b][j0+n][k], K = 64.
// tile 128 x 128, 2x4 warps, single buffer (dynamic smem).
// =========================================================================
#define GSTRIDE_W 68
__global__ void __launch_bounds__(256)
k_gram_mma()
{
    extern __shared__ uint32_t gsm[];
    __shared__ float rowsW[8][64];

    const int tid  = threadIdx.x;
    const int lane = tid & 31;
    const int wid  = tid >> 5;
    const int b  = blockIdx.z;
    const int i0 = blockIdx.x * 128;
    const int jb = blockIdx.y;
    const int j0 = jb * 128;

    const float* XT = g_xuaiT + (size_t)b * NN * CC;
    const uint32_t aSm = smem_u32(&gsm[0]);
    const uint32_t bSm = aSm + 128*GSTRIDE_W*4;

    // fill: 2048 cp16 per tile, 8 per thread per tile
#pragma unroll
    for (int q = 0; q < 8; q++) {
        int f = q * 256 + tid;
        int row = f >> 4, seg = (f & 15) * 4;
        cp16(aSm + (row*GSTRIDE_W + seg) * 4, XT + (size_t)(i0 + row) * CC + seg);
        cp16(bSm + (row*GSTRIDE_W + seg) * 4, XT + (size_t)(j0 + row) * CC + seg);
    }
    CP_COMMIT();
    CP_WAIT0();
    __syncthreads();

    const int aRowOff = (lane & 15) * GSTRIDE_W + (lane >> 4) * 4;
    const int bRowOff = ((lane >> 4) * 8 + (lane & 7)) * GSTRIDE_W + ((lane >> 3) & 1) * 4;
    const int mbase = (wid >> 2) * 64;
    const int nbase = (wid & 3) * 32;

    float c[4][4][4];
#pragma unroll
    for (int i = 0; i < 4; i++)
#pragma unroll
        for (int j = 0; j < 4; j++)
#pragma unroll
            for (int q = 0; q < 4; q++) c[i][j][q] = 0.f;

#pragma unroll
    for (int kk = 0; kk < 64; kk += 8) {
        uint32_t a[4][4];
#pragma unroll
        for (int mt = 0; mt < 4; mt++) {
            uint32_t addr = aSm + ((mbase + mt*16)*GSTRIDE_W + aRowOff + kk) * 4;
            LDSM4(a[mt][0], a[mt][1], a[mt][2], a[mt][3], addr);
        }
        uint32_t bfr[4][2];
#pragma unroll
        for (int np = 0; np < 2; np++) {
            uint32_t addr = bSm + ((nbase + np*16)*GSTRIDE_W + bRowOff + kk) * 4;
            LDSM4(bfr[np*2][0], bfr[np*2][1], bfr[np*2+1][0], bfr[np*2+1][1], addr);
        }
#pragma unroll
        for (int mt = 0; mt < 4; mt++)
#pragma unroll
            for (int nt = 0; nt < 4; nt++)
                MMA_TF32(c[mt][nt], a[mt][0], a[mt][1], a[mt][2], a[mt][3],
                         bfr[nt][0], bfr[nt][1]);
    }

    // epilogue: transform + store gl + row partial sums
    const float* sq = g_sq + b*NN;
    float* glb = g_gl + (size_t)b*NN*NN;
    const int gid = lane >> 2, tq = lane & 3;
#pragma unroll
    for (int mt = 0; mt < 4; mt++) {
        const int rl = mbase + mt*16 + gid;      // local row 0..127
        const int gi0 = i0 + rl, gi1 = gi0 + 8;
        const float sqa = sq[gi0], sqb = sq[gi1];
        float rp0 = 0.f, rp1 = 0.f;
#pragma unroll
        for (int nt = 0; nt < 4; nt++) {
            const int col = j0 + nbase + nt*8 + tq*2;
            const float sj0 = sq[col], sj1 = sq[col+1];
            float d00 = fmaxf(sqa + sj0 - 2.f*c[mt][nt][0], 0.f);
            float d01 = fmaxf(sqa + sj1 - 2.f*c[mt][nt][1], 0.f);
            float d10 = fmaxf(sqb + sj0 - 2.f*c[mt][nt][2], 0.f);
            float d11 = fmaxf(sqb + sj1 - 2.f*c[mt][nt][3], 0.f);
            float v00 = rnd_tf32(__expf(__expf(-d00*(1.f/128.f)) + ((gi0 == col)   ? 1.f : 0.f)));
            float v01 = rnd_tf32(__expf(__expf(-d01*(1.f/128.f)) + ((gi0 == col+1) ? 1.f : 0.f)));
            float v10 = rnd_tf32(__expf(__expf(-d10*(1.f/128.f)) + ((gi1 == col)   ? 1.f : 0.f)));
            float v11 = rnd_tf32(__expf(__expf(-d11*(1.f/128.f)) + ((gi1 == col+1) ? 1.f : 0.f)));
            float2 w0 = {v00, v01}, w1 = {v10, v11};
            *(float2*)(glb + (size_t)gi0 * NN + col) = w0;
            *(float2*)(glb + (size_t)gi1 * NN + col) = w1;
            rp0 += v00 + v01;
            rp1 += v10 + v11;
        }
        // reduce across the 4 tq lanes (width 4)
        rp0 += __shfl_xor_sync(0xffffffffu, rp0, 1, 4);
        rp0 += __shfl_xor_sync(0xffffffffu, rp0, 2, 4);
        rp1 += __shfl_xor_sync(0xffffffffu, rp1, 1, 4);
        rp1 += __shfl_xor_sync(0xffffffffu, rp1, 2, 4);
        if (tq == 0) {
            rowsW[wid][mt*16 + gid]     = rp0;
            rowsW[wid][mt*16 + gid + 8] = rp1;
        }
    }
    __syncthreads();
    if (tid < 128) {
        int half = tid >> 6, lr = tid & 63;
        float s = rowsW[half*4 + 0][lr] + rowsW[half*4 + 1][lr]
                + rowsW[half*4 + 2][lr] + rowsW[half*4 + 3][lr];
        g_part[((size_t)b*8 + jb)*NN + i0 + tid] = s;
    }
}

// ---------------- transpose + round xuai -> xuaiT ----------------
__global__ void k_xT() {
    __shared__ float t[32][33];
    int b = blockIdx.z, n0 = blockIdx.x * 32, c0 = blockIdx.y * 32;
    const float* X = g_xuai + (size_t)b*CC*NN;
    for (int r = threadIdx.y; r < 32; r += 8)
        t[r][threadIdx.x] = X[(size_t)(c0 + r)*NN + n0 + threadIdx.x];
    __syncthreads();
    float* XT = g_xuaiT + (size_t)b*NN*CC;
    for (int r = threadIdx.y; r < 32; r += 8)
        XT[(size_t)(n0 + r)*CC + c0 + threadIdx.x] = rnd_tf32(t[threadIdx.x][r]);
}

// ---------------- tf32 rounding copy ----------------
__global__ void k_wround(const float* __restrict__ src) {
    size_t i = ((size_t)blockIdx.x * 256 + threadIdx.x) * 4;
    float4 v = *(const float4*)(src + i);
    float4 w = { rnd_tf32(v.x), rnd_tf32(v.y), rnd_tf32(v.z), rnd_tf32(v.w) };
    *(float4*)(g_wr + i) = w;
}

// ---------------- laplacian prep ----------------
__global__ void k_lap_d(const float* __restrict__ graph) {
    int i = blockIdx.x, k = blockIdx.y, t = threadIdx.x;
    const float* row = graph + (size_t)k*NN*NN + (size_t)i*NN;
    float s = 0.f;
    for (int j = t; j < NN; j += 256) s += row[j];
    __shared__ float sh[256];
    sh[t] = s; __syncthreads();
    for (int o = 128; o > 0; o >>= 1) { if (t < o) sh[t] += sh[t+o]; __syncthreads(); }
    if (t == 0) g_d[k*NN + i] = rsqrtf(sh[0] + 1.0f);
}

__global__ void k_lapT(const float* __restrict__ graph) {
    int kg = blockIdx.y, m = blockIdx.x, t = threadIdx.x;
    const float* src = graph + (size_t)kg*NN*NN + (size_t)m*NN;
    float* dst = ((kg == 0) ? g_g1 : g_g2) + (size_t)m*NN;
    const float* d = g_d + kg*NN;
    float dm = d[m];
#pragma unroll
    for (int q = 0; q < 4; q++) {
        int k = t + 256*q;
        float v = src[k] + ((m == k) ? 1.f : 0.f);
        dst[k] = rnd_tf32(v * dm * d[k]);
    }
}

// ---------------- embedding stage 1 ----------------
__global__ void k_emb1(const float* __restrict__ x, const float* __restrict__ emb_w,
                       const float* __restrict__ emb_b) {
    __shared__ float w[CC*CIN];
    __shared__ float bsm[CC];
    int t = threadIdx.x;
    for (int i = t; i < CC*CIN; i += 256) w[i] = emb_w[i];
    if (t < CC) bsm[t] = emb_b[t];
    __syncthreads();
    int b = blockIdx.x;
    int n = blockIdx.y * 256 + t;
    int e0 = blockIdx.z * 16;
    float xv[CIN];
    const float* xp = x + (size_t)b*CIN*NN + n;
#pragma unroll
    for (int c = 0; c < CIN; c++) xv[c] = xp[(size_t)c*NN];
    float* out = g_h0a + (size_t)b*CC*NN + n;
    for (int e = e0; e < e0 + 16; e++) {
        float s = bsm[e];
#pragma unroll
        for (int c = 0; c < CIN; c++) s = fmaf(w[e*CIN + c], xv[c], s);
        float lv = (s > 0.f) ? s : 0.01f*s;
        out[(size_t)e*NN] = rnd_tf32(lv);
    }
}

// ------- 64x64 channel mix -------
__global__ void __launch_bounds__(128)
chanmixD(const float* __restrict__ in, const float* __restrict__ in2,
         const float* __restrict__ in3, const float* __restrict__ in4,
         int reluIn, size_t inBstride, size_t inZoff,
         const float* __restrict__ Wa, const float* __restrict__ ba,
         const float* __restrict__ Wb, const float* __restrict__ bb_,
         int trans, int roundOut, float* __restrict__ out, size_t outBstride,
         float* __restrict__ out2, const float* __restrict__ nScale) {
    const int z = blockIdx.z;
    const float* W    = z ? Wb  : Wa;
    const float* bias = z ? bb_ : ba;
    const int b = blockIdx.y, n0 = blockIdx.x * 64;
    __shared__ float Ms[64*PADN];
    __shared__ float Xs[64*PADN];
    const int tid = threadIdx.x;
    for (int i = tid; i < 64*64; i += 128) {
        int o = i >> 6, k = i & 63;
        Ms[k*PADN + o] = trans ? W[k*64 + o] : W[o*64 + k];
    }
    const size_t boff = (size_t)b*inBstride + (size_t)z*inZoff + n0;
    for (int i = tid; i < 64*16; i += 128) {
        int k = i >> 4, n4 = (i & 15) * 4;
        size_t off = boff + (size_t)k*NN + n4;
        float4 v = *(const float4*)(in + off);
        if (in2) { float4 w2 = *(const float4*)(in2 + off); v.x+=w2.x; v.y+=w2.y; v.z+=w2.z; v.w+=w2.w; }
        if (in3) { float4 w3 = *(const float4*)(in3 + off); v.x+=w3.x; v.y+=w3.y; v.z+=w3.z; v.w+=w3.w; }
        if (in4) { float4 w4 = *(const float4*)(in4 + off); v.x+=w4.x; v.y+=w4.y; v.z+=w4.z; v.w+=w4.w; }
        if (reluIn) {
            v.x = fmaxf(v.x, 0.f); v.y = fmaxf(v.y, 0.f);
            v.z = fmaxf(v.z, 0.f); v.w = fmaxf(v.w, 0.f);
        }
        *(float4*)&Xs[k*PADN + n4] = v;
    }
    __syncthreads();
    const int tx = tid & 15, ty = tid >> 4;
    u64 acc[4][4] = {};
#pragma unroll 8
    for (int k = 0; k < 64; k++) {
        const float* mrow = &Ms[k*PADN + ty*8];
        ulonglong2 av0 = *(const ulonglong2*)(mrow);
        ulonglong2 av1 = *(const ulonglong2*)(mrow + 4);
        float4 xv = *(const float4*)&Xs[k*PADN + tx*4];
        u64 gs0 = splat2(xv.x), gs1 = splat2(xv.y), gs2 = splat2(xv.z), gs3 = splat2(xv.w);
        ffma2(acc[0][0], av0.x, gs0); ffma2(acc[0][1], av0.x, gs1);
        ffma2(acc[0][2], av0.x, gs2); ffma2(acc[0][3], av0.x, gs3);
        ffma2(acc[1][0], av0.y, gs0); ffma2(acc[1][1], av0.y, gs1);
        ffma2(acc[1][2], av0.y, gs2); ffma2(acc[1][3], av0.y, gs3);
        ffma2(acc[2][0], av1.x, gs0); ffma2(acc[2][1], av1.x, gs1);
        ffma2(acc[2][2], av1.x, gs2); ffma2(acc[2][3], av1.x, gs3);
        ffma2(acc[3][0], av1.y, gs0); ffma2(acc[3][1], av1.y, gs1);
        ffma2(acc[3][2], av1.y, gs2); ffma2(acc[3][3], av1.y, gs3);
    }
    float* outb = out + (size_t)b*outBstride + (size_t)z*CC*NN + n0;
    float* outb2 = out2 ? out2 + (size_t)b*outBstride + (size_t)z*CC*NN + n0 : nullptr;
    float4 sc = {1.f,1.f,1.f,1.f};
    if (outb2) sc = *(const float4*)(nScale + (size_t)b*NN + n0 + tx*4);
#pragma unroll
    for (int i = 0; i < 4; i++) {
        int o = ty*8 + 2*i;
        float b0 = bias ? bias[o]   : 0.f;
        float b1 = bias ? bias[o+1] : 0.f;
        float2 v0 = unpack2(acc[i][0]), v1 = unpack2(acc[i][1]);
        float2 v2 = unpack2(acc[i][2]), v3 = unpack2(acc[i][3]);
        float4 lo = {v0.x + b0, v1.x + b0, v2.x + b0, v3.x + b0};
        float4 hi = {v0.y + b1, v1.y + b1, v2.y + b1, v3.y + b1};
        if (roundOut) {
            lo.x = rnd_tf32(lo.x); lo.y = rnd_tf32(lo.y);
            lo.z = rnd_tf32(lo.z); lo.w = rnd_tf32(lo.w);
            hi.x = rnd_tf32(hi.x); hi.y = rnd_tf32(hi.y);
            hi.z = rnd_tf32(hi.z); hi.w = rnd_tf32(hi.w);
        }
        *(float4*)(outb + (size_t)o*NN + tx*4) = lo;
        *(float4*)(outb + (size_t)(o+1)*NN + tx*4) = hi;
        if (outb2) {
            float4 lo2 = {rnd_tf32(lo.x*sc.x), rnd_tf32(lo.y*sc.y),
                          rnd_tf32(lo.z*sc.z), rnd_tf32(lo.w*sc.w)};
            float4 hi2 = {rnd_tf32(hi.x*sc.x), rnd_tf32(hi.y*sc.y),
                          rnd_tf32(hi.z*sc.z), rnd_tf32(hi.w*sc.w)};
            *(float4*)(outb2 + (size_t)o*NN + tx*4) = lo2;
            *(float4*)(outb2 + (size_t)(o+1)*NN + tx*4) = hi2;
        }
    }
}

// ---------------- attention scores ----------------
__global__ void k_s12(const float* __restrict__ att_a) {
    __shared__ float a1[64], a2[64];
    int t = threadIdx.x;
    if (t < 64) a1[t] = att_a[t];
    else if (t < 128) a2[t-64] = att_a[t];
    __syncthreads();
    int b = blockIdx.x;
    int i = blockIdx.y * 256 + t;
    const float* h = g_hT + (size_t)b*CC*NN + i;
    float v1 = 0.f, v2 = 0.f;
#pragma unroll 8
    for (int c = 0; c < 64; c++) {
        float hv = h[(size_t)c*NN];
        v1 = fmaf(hv, a1[c], v1);
        v2 = fmaf(hv, a2[c], v2);
    }
    g_s1[b*NN + i] = v1;
    g_s2[b*NN + i] = v2;
}

__global__ void k_s2max() {
    int b = blockIdx.x, t = threadIdx.x;
    const float* s2 = g_s2 + b*NN;
    float mx = -1e30f;
    for (int j = t; j < NN; j += 256) mx = fmaxf(mx, s2[j]);
    __shared__ float sh[256];
    sh[t] = mx; __syncthreads();
    for (int o = 128; o > 0; o >>= 1) { if (t < o) sh[t] = fmaxf(sh[t], sh[t+o]); __syncthreads(); }
    if (t == 0) g_mxs2[b] = sh[0];
}

__global__ void k_attinv() {
    int b = blockIdx.y;
    int row = blockIdx.x * 8 + (threadIdx.x >> 5);
    int lane = threadIdx.x & 31;
    float s1v = g_s1[b*NN + row];
    float m = s1v + g_mxs2[b];
    m = (m > 0.f) ? m : 0.01f * m;
    const float* s2 = g_s2 + b*NN;
    float sum = 0.f;
    for (int j = lane; j < NN; j += 32) {
        float e = s1v + s2[j];
        e = (e > 0.f) ? e : 0.01f * e;
        sum += __expf(e - m);
    }
#pragma unroll
    for (int o = 16; o > 0; o >>= 1) sum += __shfl_down_sync(0xffffffffu, sum, o);
    if (lane == 0) {
        g_amx [b*NN + row] = m;
        g_ainv[b*NN + row] = 1.f / sum;
    }
}

// ---------------- learned adjacency helpers ----------------
__global__ void k_sq() {
    int b = blockIdx.x, n = blockIdx.y * 256 + threadIdx.x;
    const float* xp = g_xuai + (size_t)b*CC*NN + n;
    float s = 0.f;
#pragma unroll 8
    for (int c = 0; c < CC; c++) { float v = xp[(size_t)c*NN]; s = fmaf(v, v, s); }
    g_sq[b*NN + n] = s;
}

__global__ void k_rsfin() {
    int b = blockIdx.x, i = threadIdx.x;
    float s = 0.f;
#pragma unroll
    for (int j = 0; j < 8; j++) s += g_part[((size_t)b*8 + j)*NN + i];
    g_rsinv[b*NN + i] = 1.f / s;
}

// ---------------- layernorm stats + final fuse ----------------
__global__ void k_lnstats() {
    int b = blockIdx.x, path = blockIdx.y, t = threadIdx.x;
    size_t base = (size_t)b*(2*CC)*NN + (size_t)path*CC*NN;
    float s = 0.f, ss = 0.f;
    for (int i = t; i < CC*NN; i += 1024) {
        float v = g_sxa[base + i] + g_sxb[base + i];
        s += v; ss = fmaf(v, v, ss);
    }
    __shared__ float shs[1024], shq[1024];
    shs[t] = s; shq[t] = ss; __syncthreads();
    for (int o = 512; o > 0; o >>= 1) {
        if (t < o) { shs[t] += shs[t+o]; shq[t] += shq[t+o]; }
        __syncthreads();
    }
    if (t == 0) {
        float mean = shs[0] * (1.f/65536.f);
        float var  = shq[0] * (1.f/65536.f) - mean*mean;
        g_stats[(path*BB + b)*2 + 0] = mean;
        g_stats[(path*BB + b)*2 + 1] = rsqrtf(var + 1e-5f);
    }
}

__global__ void k_final(const float* __restrict__ ct, const float* __restrict__ ln_w,
                        const float* __restrict__ ln_b, float* __restrict__ out) {
    size_t idx = (size_t)blockIdx.x * 256 + threadIdx.x;
    int b  = (int)(idx / (CC*NN));
    int cn = (int)(idx % (CC*NN));
    float m1 = g_stats[b*2 + 0],            r1 = g_stats[b*2 + 1];
    float m2 = g_stats[(BB + b)*2 + 0],     r2 = g_stats[(BB + b)*2 + 1];
    float w = ln_w[cn], bb = ln_b[cn];
    size_t base = (size_t)b*(2*CC)*NN + cn;
    float z1v = g_sxa[base] + g_sxb[base];
    float z2v = g_sxa[base + (size_t)CC*NN] + g_sxb[base + (size_t)CC*NN];
    float xnew = (z1v - m1) * r1 * w + bb;
    float z2   = (z2v - m2) * r2 * w + bb;
    float ft = 0.5f * z2 * (1.f + erff(z2 * 0.70710678118654752f));
    float ctv = ct[idx];
    float ctn = xnew + ft * (ctv - xnew);
    float el  = (ctn > 0.f) ? ctn : expm1f(ctn);
    float xu  = g_xuai[idx];
    float ht  = xu + ft * (el - xu);
    out[idx] = ht;
    out[(size_t)BB*CC*NN + idx] = ctn;
}

// ---------------- host launch ----------------
struct DevPtrs {
    float *gl, *g1, *g2, *wr, *h0a, *hT, *xuai;
    float *pa, *pb, *pc, *pd;
    float *l12, *l12s, *t12a, *t12b, *u12, *a12a, *a12b, *sxa, *sxb, *rsinv;
    bool init;
};
static DevPtrs P = {};
static const int GRAM_SMEM = 2 * 128 * GSTRIDE_W * 4;   // 69632

static void init_ptrs() {
    if (P.init) return;
    void* p;
#define GET(sym, field) cudaGetSymbolAddress(&p, sym); P.field = (float*)p;
    GET(g_gl, gl)   GET(g_g1, g1)   GET(g_g2, g2)
    GET(g_wr, wr)    GET(g_h0a, h0a) GET(g_hT, hT)   GET(g_xuai, xuai)
    GET(g_pa, pa)    GET(g_pb, pb)   GET(g_pc, pc)   GET(g_pd, pd)
    GET(g_l12, l12)  GET(g_l12s, l12s)
    GET(g_t12a, t12a) GET(g_t12b, t12b) GET(g_u12, u12)
    GET(g_a12a, a12a) GET(g_a12b, a12b) GET(g_sxa, sxa) GET(g_sxb, sxb)
    GET(g_rsinv, rsinv)
#undef GET
    cudaFuncSetAttribute(k_gram_mma, cudaFuncAttributeMaxDynamicSharedMemorySize, GRAM_SMEM);
    P.init = true;
}

extern "C" void kernel_launch(void* const* d_in, const int* in_sizes, int n_in,
                              void* d_out, int out_size) {
    const float* x      = (const float*)d_in[0];
    const float* ct     = (const float*)d_in[1];
    const float* graph  = (const float*)d_in[2];
    const float* emb_w  = (const float*)d_in[3];
    const float* emb_b  = (const float*)d_in[4];
    const float* emb2_w = (const float*)d_in[5];
    const float* emb2_b = (const float*)d_in[6];
    const float* att_W  = (const float*)d_in[7];
    const float* att_a  = (const float*)d_in[8];
    // d_in[9] = att_GL : unused (softmax output strictly positive => mask no-op)
    const float* uai_w  = (const float*)d_in[10];
    const float* uai_b  = (const float*)d_in[11];
    const float* lin1_w = (const float*)d_in[12];
    const float* lin2_w = (const float*)d_in[13];
    const float* lin2_b = (const float*)d_in[14];
    const float* ln_w   = (const float*)d_in[15];
    const float* ln_b   = (const float*)d_in[16];
    float* out = (float*)d_out;

    init_ptrs();

    const size_t GLSTRIDE = (size_t)NN * NN;
    const size_t SB = (size_t)CC * NN;
    const size_t DB = (size_t)2 * CC * NN;
    const dim3 gridC1(NN/64, BB, 1);
    const dim3 gridC2(NN/64, BB, 2);

    // graph laplacians (K-major, tf32-rounded) + rounded emb2 weights
    k_lap_d <<<dim3(NN, 2), 256>>>(graph);
    k_lapT  <<<dim3(NN, 2), 256>>>(graph);
    k_wround<<<NN*NN/1024, 256>>>(emb2_w);

    // embedding
    k_emb1  <<<dim3(BB, NN/256, 4), 256>>>(x, emb_w, emb_b);
    mma_gemm<<<dim3(8, BB/2, 4), 256>>>(P.h0a, DB, 128, P.wr, 0, 4,
                                        nullptr, nullptr, emb2_b,
                                        P.pa, P.pb, P.pc, P.pd, DB);

    // attention
    chanmixD<<<gridC1, 128>>>(P.pa, P.pb, P.pc, P.pd, 0, SB, 0,
                              att_W, nullptr, att_W, nullptr, 1, 1, P.hT, SB,
                              nullptr, nullptr);
    k_s12   <<<dim3(BB, NN/256), 256>>>(att_a);
    k_s2max <<<BB, 256>>>();
    k_attinv<<<dim3(NN/8, BB), 256>>>();
    mma_gemm_att<<<dim3(8, BB, 2), 256>>>(P.hT, SB, P.pa, P.pb, SB);

    // UAI
    chanmixD<<<gridC1, 128>>>(P.pa, P.pb, nullptr, nullptr, 1, SB, 0,
                              uai_w, uai_b, uai_w, uai_b, 0, 0, P.xuai, SB,
                              nullptr, nullptr);

    // learned adjacency: transpose, sq, tensor-core gram + fused row partials
    k_xT   <<<dim3(NN/32, 2, BB), dim3(32, 8)>>>();
    k_sq   <<<dim3(BB, NN/256), 256>>>();
    k_gram_mma<<<dim3(8, 8, BB), 256, GRAM_SMEM>>>();
    k_rsfin<<<BB, 1024>>>();

    // l1/l2 stacked propagation
    chanmixD<<<gridC2, 128>>>(P.xuai, nullptr, nullptr, nullptr, 0, SB, 0,
                              lin1_w, nullptr, lin2_w, lin2_b, 0, 1, P.l12, DB,
                              P.l12s, P.rsinv);

    mma_gemm<<<dim3(8, BB, 2), 256>>>(P.l12s, DB, 128, P.gl, GLSTRIDE, 2,
                                      nullptr, nullptr, nullptr,
                                      P.a12a, P.a12b, nullptr, nullptr, DB);
    mma_gemm<<<dim3(8, BB, 2), 256>>>(P.l12, DB, 128, P.g1, 0, 2,
                                      nullptr, nullptr, nullptr,
                                      P.t12a, P.t12b, nullptr, nullptr, DB);

    chanmixD<<<gridC2, 128>>>(P.t12a, P.t12b, nullptr, nullptr, 0, DB, SB,
                              lin1_w, nullptr, lin2_w, lin2_b, 0, 1, P.u12, DB,
                              nullptr, nullptr);

    mma_gemm<<<dim3(8, BB, 2), 256>>>(P.u12, DB, 128, P.g2, 0, 2,
                                      P.a12a, P.a12b, nullptr,
                                      P.sxa, P.sxb, nullptr, nullptr, DB);

    // layernorm + gates + output
    k_lnstats<<<dim3(BB, 2), 1024>>>();
    k_final  <<<(BB*CC*NN)/256, 256>>>(ct, ln_w, ln_b, out);
}

// round 12
// speedup vs baseline: 2.5611x; 1.0340x over previous
#include <cuda_runtime.h>
#include <math.h>
#include <stdint.h>

#define BB 16
#define NN 1024
#define CC 64
#define CIN 16
#define PADN 68

typedef unsigned long long u64;

// ---------------- fp32x2 helpers (chanmix) ----------------
__device__ __forceinline__ u64 splat2(float v) {
    u64 r; asm("mov.b64 %0, {%1, %1};" : "=l"(r) : "f"(v)); return r;
}
__device__ __forceinline__ void ffma2(u64& d, u64 a, u64 b) {
    asm("fma.rn.f32x2 %0, %1, %2, %0;" : "+l"(d) : "l"(a), "l"(b));
}
__device__ __forceinline__ float2 unpack2(u64 v) {
    float2 r; asm("mov.b64 {%0, %1}, %2;" : "=f"(r.x), "=f"(r.y) : "l"(v)); return r;
}

// ---------------- mma.sync tf32 + cp.async helpers ----------------
__device__ __forceinline__ uint32_t smem_u32(const void* p) {
    uint32_t a;
    asm("{ .reg .u64 t; cvta.to.shared.u64 t, %1; cvt.u32.u64 %0, t; }" : "=r"(a) : "l"(p));
    return a;
}
__device__ __forceinline__ float rnd_tf32(float f) {
    uint32_t r; asm("cvt.rna.tf32.f32 %0, %1;" : "=r"(r) : "f"(f));
    return __uint_as_float(r);
}
#define LDSM4(r0, r1, r2, r3, addr)                                            \
    asm volatile("ldmatrix.sync.aligned.m8n8.x4.shared.b16 {%0,%1,%2,%3}, [%4];" \
        : "=r"(r0), "=r"(r1), "=r"(r2), "=r"(r3) : "r"(addr))
#define MMA_TF32(c, a0, a1, a2, a3, b0, b1)                                    \
    asm volatile("mma.sync.aligned.m16n8k8.row.col.f32.tf32.tf32.f32 "         \
        "{%0,%1,%2,%3}, {%4,%5,%6,%7}, {%8,%9}, {%0,%1,%2,%3};"                \
        : "+f"((c)[0]), "+f"((c)[1]), "+f"((c)[2]), "+f"((c)[3])               \
        : "r"(a0), "r"(a1), "r"(a2), "r"(a3), "r"(b0), "r"(b1))
__device__ __forceinline__ void cp16(uint32_t dst, const void* src) {
    asm volatile("cp.async.cg.shared.global [%0], [%1], 16;" :: "r"(dst), "l"(src));
}
#define CP_COMMIT()  asm volatile("cp.async.commit_group;" ::: "memory")
#define CP_WAIT1()   asm volatile("cp.async.wait_group 1;" ::: "memory")
#define CP_WAIT0()   asm volatile("cp.async.wait_group 0;" ::: "memory")

// ---------------- static device scratch ----------------
__device__ float g_gl  [BB*NN*NN];
__device__ float g_g1  [NN*NN];
__device__ float g_g2  [NN*NN];
__device__ float g_wr  [NN*NN];
__device__ float g_d   [2*NN];
__device__ float g_h0a [BB*CC*NN];
__device__ float g_hT  [BB*CC*NN];
__device__ float g_xuai[BB*CC*NN];
__device__ float g_xuaiT[BB*NN*CC];
__device__ float g_pa  [BB*CC*NN];
__device__ float g_pb  [BB*CC*NN];
__device__ float g_pc  [BB*CC*NN];
__device__ float g_pd  [BB*CC*NN];
__device__ float g_l12 [BB*2*CC*NN];
__device__ float g_l12s[BB*2*CC*NN];
__device__ float g_t12a[BB*2*CC*NN];
__device__ float g_t12b[BB*2*CC*NN];
__device__ float g_u12 [BB*2*CC*NN];
__device__ float g_a12a[BB*2*CC*NN];
__device__ float g_a12b[BB*2*CC*NN];
__device__ float g_sxa [BB*2*CC*NN];
__device__ float g_sxb [BB*2*CC*NN];
__device__ float g_s1  [BB*NN];
__device__ float g_s2  [BB*NN];
__device__ float g_amx [BB*NN];
__device__ float g_ainv[BB*NN];
__device__ float g_sq  [BB*NN];
__device__ float g_part[BB*8*NN];
__device__ float g_rsinv[BB*NN];
__device__ float g_stats[2*BB*2];

// =========================================================================
// mma_gemm (tf32): C_ks[b,c,n] = sum_{k in split ks} A[b,c,k] * B[b,n,k]
// =========================================================================
#define TPAD 20
__global__ void __launch_bounds__(256, 2)
mma_gemm(const float* __restrict__ A, size_t aBatch, int mvalid,
         const float* __restrict__ B, size_t bBatch, int nsplit,
         const float* __restrict__ add0, const float* __restrict__ add1,
         const float* __restrict__ biasN,
         float* __restrict__ C0, float* __restrict__ C1,
         float* __restrict__ C2, float* __restrict__ C3, size_t cBatch)
{
    __shared__ uint32_t As[2][128*TPAD];
    __shared__ uint32_t Bs[2][128*TPAD];

    const int tid  = threadIdx.x;
    const int lane = tid & 31;
    const int wid  = tid >> 5;
    const int bidx = blockIdx.y;
    const int n0   = blockIdx.x * 128;
    const int ks   = blockIdx.z;
    const int kPer = NN / nsplit;
    const int T    = kPer / 16;
    const int k0b  = ks * kPer;

    const float* Ab = A + (size_t)bidx * aBatch + k0b;
    const float* Bb = B + (size_t)bidx * bBatch + (size_t)n0 * NN + k0b;

    const int frow0 = tid >> 2;
    const int frow1 = 64 + (tid >> 2);
    const int fkq   = (tid & 3) * 4;

    const float* aP0 = Ab + (size_t)frow0 * NN + fkq;
    const float* aP1 = Ab + (size_t)((frow1 < mvalid) ? frow1 : 0) * NN + fkq;
    const float* bP0 = Bb + (size_t)frow0 * NN + fkq;
    const float* bP1 = Bb + (size_t)frow1 * NN + fkq;

    const uint32_t aSm = smem_u32(&As[0][0]);
    const uint32_t bSm = smem_u32(&Bs[0][0]);
    const uint32_t aFill  = aSm + (frow0*TPAD + fkq) * 4;
    const uint32_t aFill1 = aSm + (frow1*TPAD + fkq) * 4;
    const uint32_t bFill  = bSm + (frow0*TPAD + fkq) * 4;
    const uint32_t bFill1 = bSm + (frow1*TPAD + fkq) * 4;
    const uint32_t bufStride = 128*TPAD*4;

    const int aRowOff = (lane & 15) * TPAD + (lane >> 4) * 4;
    const int bRowOff = ((lane >> 4) * 8 + (lane & 7)) * TPAD + ((lane >> 3) & 1) * 4;

    const int mbase = (wid >> 2) * 64;
    const int nbase = (wid & 3) * 32;

    float c[4][4][4];
#pragma unroll
    for (int i = 0; i < 4; i++)
#pragma unroll
        for (int j = 0; j < 4; j++)
#pragma unroll
            for (int q = 0; q < 4; q++) c[i][j][q] = 0.f;

    cp16(aFill,  aP0); cp16(aFill1, aP1);
    cp16(bFill,  bP0); cp16(bFill1, bP1);
    CP_COMMIT();

    for (int t = 0; t < T; ++t) {
        const int cur = t & 1;
        if (t + 1 < T) {
            const uint32_t off = (uint32_t)((t+1) & 1) * bufStride;
            const int ko = (t + 1) * 16;
            cp16(aFill  + off, aP0 + ko);
            cp16(aFill1 + off, aP1 + ko);
            cp16(bFill  + off, bP0 + ko);
            cp16(bFill1 + off, bP1 + ko);
            CP_COMMIT();
            CP_WAIT1();
        } else {
            CP_WAIT0();
        }
        __syncthreads();
        {
            const uint32_t aCur = aSm + cur * bufStride;
            const uint32_t bCur = bSm + cur * bufStride;
#pragma unroll
            for (int kk = 0; kk < 16; kk += 8) {
                uint32_t a[4][4];
#pragma unroll
                for (int mt = 0; mt < 4; mt++) {
                    uint32_t addr = aCur + ((mbase + mt*16)*TPAD + aRowOff + kk) * 4;
                    LDSM4(a[mt][0], a[mt][1], a[mt][2], a[mt][3], addr);
                }
                uint32_t bfr[4][2];
#pragma unroll
                for (int np = 0; np < 2; np++) {
                    uint32_t addr = bCur + ((nbase + np*16)*TPAD + bRowOff + kk) * 4;
                    LDSM4(bfr[np*2][0], bfr[np*2][1], bfr[np*2+1][0], bfr[np*2+1][1], addr);
                }
#pragma unroll
                for (int mt = 0; mt < 4; mt++)
#pragma unroll
                    for (int nt = 0; nt < 4; nt++)
                        MMA_TF32(c[mt][nt], a[mt][0], a[mt][1], a[mt][2], a[mt][3],
                                 bfr[nt][0], bfr[nt][1]);
            }
        }
        __syncthreads();
    }

    if (mbase >= mvalid) return;
    float* C = (ks == 0) ? C0 : (ks == 1) ? C1 : (ks == 2) ? C2 : C3;
    const float* add = (ks == 0) ? add0 : (ks == 1) ? add1 : nullptr;
    float* Cb = C + (size_t)bidx * cBatch;
    const float* Adb = add ? add + (size_t)bidx * cBatch : nullptr;
    const int gid = lane >> 2, tq = lane & 3;
#pragma unroll
    for (int mt = 0; mt < 4; mt++) {
        const int r = mbase + mt*16 + gid;
#pragma unroll
        for (int nt = 0; nt < 4; nt++) {
            const int col = n0 + nbase + nt*8 + tq*2;
            float2 v0 = { c[mt][nt][0], c[mt][nt][1] };
            float2 v1 = { c[mt][nt][2], c[mt][nt][3] };
            if (biasN && ks == 0) {
                float b0 = biasN[col], b1 = biasN[col+1];
                v0.x += b0; v0.y += b1; v1.x += b0; v1.y += b1;
            }
            if (Adb) {
                float2 d0 = *(const float2*)(Adb + (size_t)r * NN + col);
                float2 d1 = *(const float2*)(Adb + (size_t)(r+8) * NN + col);
                v0.x += d0.x; v0.y += d0.y; v1.x += d1.x; v1.y += d1.y;
            }
            *(float2*)(Cb + (size_t)r * NN + col)     = v0;
            *(float2*)(Cb + (size_t)(r+8) * NN + col) = v1;
        }
    }
}

// =========================================================================
// mma_gemm2: two independent GEMM units in one launch (unit = z>>1, ks = z&1).
// unit0: A0 @ B0 (batched) -> C00/C01 ; unit1: A1 @ B1 (shared) -> C10/C11.
// M=128, nsplit=2, no bias/addend.
// =========================================================================
__global__ void __launch_bounds__(256, 2)
mma_gemm2(const float* __restrict__ A0, const float* __restrict__ B0, size_t bS0,
          const float* __restrict__ A1, const float* __restrict__ B1, size_t bS1,
          float* __restrict__ C00, float* __restrict__ C01,
          float* __restrict__ C10, float* __restrict__ C11, size_t cBatch)
{
    __shared__ uint32_t As[2][128*TPAD];
    __shared__ uint32_t Bs[2][128*TPAD];

    const int tid  = threadIdx.x;
    const int lane = tid & 31;
    const int wid  = tid >> 5;
    const int bidx = blockIdx.y;
    const int n0   = blockIdx.x * 128;
    const int unit = blockIdx.z >> 1;
    const int ks   = blockIdx.z & 1;
    const int k0b  = ks * 512;
    const int T    = 32;

    const float* A = unit ? A1 : A0;
    const float* B = unit ? B1 : B0;
    const size_t bBatch = unit ? bS1 : bS0;

    const float* Ab = A + (size_t)bidx * (size_t)(2*CC)*NN + k0b;
    const float* Bb = B + (size_t)bidx * bBatch + (size_t)n0 * NN + k0b;

    const int frow0 = tid >> 2;
    const int frow1 = 64 + (tid >> 2);
    const int fkq   = (tid & 3) * 4;

    const float* aP0 = Ab + (size_t)frow0 * NN + fkq;
    const float* aP1 = Ab + (size_t)frow1 * NN + fkq;
    const float* bP0 = Bb + (size_t)frow0 * NN + fkq;
    const float* bP1 = Bb + (size_t)frow1 * NN + fkq;

    const uint32_t aSm = smem_u32(&As[0][0]);
    const uint32_t bSm = smem_u32(&Bs[0][0]);
    const uint32_t aFill  = aSm + (frow0*TPAD + fkq) * 4;
    const uint32_t aFill1 = aSm + (frow1*TPAD + fkq) * 4;
    const uint32_t bFill  = bSm + (frow0*TPAD + fkq) * 4;
    const uint32_t bFill1 = bSm + (frow1*TPAD + fkq) * 4;
    const uint32_t bufStride = 128*TPAD*4;

    const int aRowOff = (lane & 15) * TPAD + (lane >> 4) * 4;
    const int bRowOff = ((lane >> 4) * 8 + (lane & 7)) * TPAD + ((lane >> 3) & 1) * 4;

    const int mbase = (wid >> 2) * 64;
    const int nbase = (wid & 3) * 32;

    float c[4][4][4];
#pragma unroll
    for (int i = 0; i < 4; i++)
#pragma unroll
        for (int j = 0; j < 4; j++)
#pragma unroll
            for (int q = 0; q < 4; q++) c[i][j][q] = 0.f;

    cp16(aFill,  aP0); cp16(aFill1, aP1);
    cp16(bFill,  bP0); cp16(bFill1, bP1);
    CP_COMMIT();

    for (int t = 0; t < T; ++t) {
        const int cur = t & 1;
        if (t + 1 < T) {
            const uint32_t off = (uint32_t)((t+1) & 1) * bufStride;
            const int ko = (t + 1) * 16;
            cp16(aFill  + off, aP0 + ko);
            cp16(aFill1 + off, aP1 + ko);
            cp16(bFill  + off, bP0 + ko);
            cp16(bFill1 + off, bP1 + ko);
            CP_COMMIT();
            CP_WAIT1();
        } else {
            CP_WAIT0();
        }
        __syncthreads();
        {
            const uint32_t aCur = aSm + cur * bufStride;
            const uint32_t bCur = bSm + cur * bufStride;
#pragma unroll
            for (int kk = 0; kk < 16; kk += 8) {
                uint32_t a[4][4];
#pragma unroll
                for (int mt = 0; mt < 4; mt++) {
                    uint32_t addr = aCur + ((mbase + mt*16)*TPAD + aRowOff + kk) * 4;
                    LDSM4(a[mt][0], a[mt][1], a[mt][2], a[mt][3], addr);
                }
                uint32_t bfr[4][2];
#pragma unroll
                for (int np = 0; np < 2; np++) {
                    uint32_t addr = bCur + ((nbase + np*16)*TPAD + bRowOff + kk) * 4;
                    LDSM4(bfr[np*2][0], bfr[np*2][1], bfr[np*2+1][0], bfr[np*2+1][1], addr);
                }
#pragma unroll
                for (int mt = 0; mt < 4; mt++)
#pragma unroll
                    for (int nt = 0; nt < 4; nt++)
                        MMA_TF32(c[mt][nt], a[mt][0], a[mt][1], a[mt][2], a[mt][3],
                                 bfr[nt][0], bfr[nt][1]);
            }
        }
        __syncthreads();
    }

    float* C = unit ? (ks ? C11 : C10) : (ks ? C01 : C00);
    float* Cb = C + (size_t)bidx * cBatch;
    const int gid = lane >> 2, tq = lane & 3;
#pragma unroll
    for (int mt = 0; mt < 4; mt++) {
        const int r = mbase + mt*16 + gid;
#pragma unroll
        for (int nt = 0; nt < 4; nt++) {
            const int col = n0 + nbase + nt*8 + tq*2;
            float2 v0 = { c[mt][nt][0], c[mt][nt][1] };
            float2 v1 = { c[mt][nt][2], c[mt][nt][3] };
            *(float2*)(Cb + (size_t)r * NN + col)     = v0;
            *(float2*)(Cb + (size_t)(r+8) * NN + col) = v1;
        }
    }
}

// =========================================================================
// mma_gemm_att: attention MMA with on-the-fly B generation.
// =========================================================================
__device__ __forceinline__ float attval(float s1v, float s2v, float m, float iv) {
    float e = s1v + s2v;
    e = (e > 0.f) ? e : 0.01f * e;
    return rnd_tf32(__expf(e - m) * iv);
}

__global__ void __launch_bounds__(256, 2)
mma_gemm_att(const float* __restrict__ A, size_t aBatch,
             float* __restrict__ C0, float* __restrict__ C1, size_t cBatch)
{
    __shared__ uint32_t As[2][128*TPAD];
    __shared__ float    Bs[2][128*TPAD];

    const int tid  = threadIdx.x;
    const int lane = tid & 31;
    const int wid  = tid >> 5;
    const int bidx = blockIdx.y;
    const int n0   = blockIdx.x * 128;
    const int ks   = blockIdx.z;
    const int k0b  = ks * 512;
    const int T    = 32;

    const float* Ab = A + (size_t)bidx * aBatch + k0b;

    const int frow0 = tid >> 2;
    const int frow1 = 64 + (tid >> 2);
    const int fkq   = (tid & 3) * 4;

    const float* aP0 = Ab + (size_t)frow0 * NN + fkq;
    const float* aP1 = Ab;

    const float s1v0 = g_s1 [bidx*NN + n0 + frow0];
    const float m0   = g_amx[bidx*NN + n0 + frow0];
    const float iv0  = g_ainv[bidx*NN + n0 + frow0];
    const float s1v1 = g_s1 [bidx*NN + n0 + frow1];
    const float m1   = g_amx[bidx*NN + n0 + frow1];
    const float iv1  = g_ainv[bidx*NN + n0 + frow1];
    const float* s2p = g_s2 + bidx*NN + k0b + fkq;

    const uint32_t aSm = smem_u32(&As[0][0]);
    const uint32_t bSm = smem_u32(&Bs[0][0]);
    const uint32_t aFill  = aSm + (frow0*TPAD + fkq) * 4;
    const uint32_t aFill1 = aSm + (frow1*TPAD + fkq) * 4;
    const uint32_t bufStride = 128*TPAD*4;

    const int aRowOff = (lane & 15) * TPAD + (lane >> 4) * 4;
    const int bRowOff = ((lane >> 4) * 8 + (lane & 7)) * TPAD + ((lane >> 3) & 1) * 4;

    const int mbase = (wid >> 2) * 64;
    const int nbase = (wid & 3) * 32;

    float c[4][4][4];
#pragma unroll
    for (int i = 0; i < 4; i++)
#pragma unroll
        for (int j = 0; j < 4; j++)
#pragma unroll
            for (int q = 0; q < 4; q++) c[i][j][q] = 0.f;

    cp16(aFill,  aP0); cp16(aFill1, aP1 + fkq);
    CP_COMMIT();
    {
        float4 s2v = *(const float4*)(s2p);
        float4 b0 = { attval(s1v0, s2v.x, m0, iv0), attval(s1v0, s2v.y, m0, iv0),
                      attval(s1v0, s2v.z, m0, iv0), attval(s1v0, s2v.w, m0, iv0) };
        float4 b1 = { attval(s1v1, s2v.x, m1, iv1), attval(s1v1, s2v.y, m1, iv1),
                      attval(s1v1, s2v.z, m1, iv1), attval(s1v1, s2v.w, m1, iv1) };
        *(float4*)&Bs[0][frow0*TPAD + fkq] = b0;
        *(float4*)&Bs[0][frow1*TPAD + fkq] = b1;
    }
    __syncthreads();

    for (int t = 0; t < T; ++t) {
        const int cur = t & 1;
        if (t + 1 < T) {
            const int nxt = (t+1) & 1;
            const uint32_t off = (uint32_t)nxt * bufStride;
            const int ko = (t + 1) * 16;
            cp16(aFill  + off, aP0 + ko);
            cp16(aFill1 + off, aP1 + ko + fkq);
            CP_COMMIT();
            float4 s2v = *(const float4*)(s2p + ko);
            float4 b0 = { attval(s1v0, s2v.x, m0, iv0), attval(s1v0, s2v.y, m0, iv0),
                          attval(s1v0, s2v.z, m0, iv0), attval(s1v0, s2v.w, m0, iv0) };
            float4 b1 = { attval(s1v1, s2v.x, m1, iv1), attval(s1v1, s2v.y, m1, iv1),
                          attval(s1v1, s2v.z, m1, iv1), attval(s1v1, s2v.w, m1, iv1) };
            *(float4*)&Bs[nxt][frow0*TPAD + fkq] = b0;
            *(float4*)&Bs[nxt][frow1*TPAD + fkq] = b1;
            CP_WAIT1();
        } else {
            CP_WAIT0();
        }
        __syncthreads();
        {
            const uint32_t aCur = aSm + cur * bufStride;
            const uint32_t bCur = bSm + cur * bufStride;
#pragma unroll
            for (int kk = 0; kk < 16; kk += 8) {
                uint32_t a[4][4];
#pragma unroll
                for (int mt = 0; mt < 4; mt++) {
                    uint32_t addr = aCur + ((mbase + mt*16)*TPAD + aRowOff + kk) * 4;
                    LDSM4(a[mt][0], a[mt][1], a[mt][2], a[mt][3], addr);
                }
                uint32_t bfr[4][2];
#pragma unroll
                for (int np = 0; np < 2; np++) {
                    uint32_t addr = bCur + ((nbase + np*16)*TPAD + bRowOff + kk) * 4;
                    LDSM4(bfr[np*2][0], bfr[np*2][1], bfr[np*2+1][0], bfr[np*2+1][1], addr);
                }
#pragma unroll
                for (int mt = 0; mt < 4; mt++)
#pragma unroll
                    for (int nt = 0; nt < 4; nt++)
                        MMA_TF32(c[mt][nt], a[mt][0], a[mt][1], a[mt][2], a[mt][3],
                                 bfr[nt][0], bfr[nt][1]);
            }
        }
        __syncthreads();
    }

    if (mbase >= 64) return;
    float* Cb = (ks ? C1 : C0) + (size_t)bidx * cBatch;
    const int gid = lane >> 2, tq = lane & 3;
#pragma unroll
    for (int mt = 0; mt < 4; mt++) {
        const int r = mbase + mt*16 + gid;
#pragma unroll
        for (int nt = 0; nt < 4; nt++) {
            const int col = n0 + nbase + nt*8 + tq*2;
            float2 v0 = { c[mt][nt][0], c[mt][nt][1] };
            float2 v1 = { c[mt][nt][2], c[mt][nt][3] };
            *(float2*)(Cb + (size_t)r * NN + col)     = v0;
            *(float2*)(Cb + (size_t)(r+8) * NN + col) = v1;
        }
    }
}

// =========================================================================
// k_gram_mma: gl = transform( XtT @ XtT^T ), row partial sums fused.
// =========================================================================
#define GSTRIDE_W 68
__global__ void __launch_bounds__(256)
k_gram_mma()
{
    extern __shared__ uint32_t gsm[];
    __shared__ float rowsW[8][64];

    const int tid  = threadIdx.x;
    const int lane = tid & 31;
    const int wid  = tid >> 5;
    const int b  = blockIdx.z;
    const int i0 = blockIdx.x * 128;
    const int jb = blockIdx.y;
    const int j0 = jb * 128;

    const float* XT = g_xuaiT + (size_t)b * NN * CC;
    const uint32_t aSm = smem_u32(&gsm[0]);
    const uint32_t bSm = aSm + 128*GSTRIDE_W*4;

#pragma unroll
    for (int q = 0; q < 8; q++) {
        int f = q * 256 + tid;
        int row = f >> 4, seg = (f & 15) * 4;
        cp16(aSm + (row*GSTRIDE_W + seg) * 4, XT + (size_t)(i0 + row) * CC + seg);
        cp16(bSm + (row*GSTRIDE_W + seg) * 4, XT + (size_t)(j0 + row) * CC + seg);
    }
    CP_COMMIT();
    CP_WAIT0();
    __syncthreads();

    const int aRowOff = (lane & 15) * GSTRIDE_W + (lane >> 4) * 4;
    const int bRowOff = ((lane >> 4) * 8 + (lane & 7)) * GSTRIDE_W + ((lane >> 3) & 1) * 4;
    const int mbase = (wid >> 2) * 64;
    const int nbase = (wid & 3) * 32;

    float c[4][4][4];
#pragma unroll
    for (int i = 0; i < 4; i++)
#pragma unroll
        for (int j = 0; j < 4; j++)
#pragma unroll
            for (int q = 0; q < 4; q++) c[i][j][q] = 0.f;

#pragma unroll
    for (int kk = 0; kk < 64; kk += 8) {
        uint32_t a[4][4];
#pragma unroll
        for (int mt = 0; mt < 4; mt++) {
            uint32_t addr = aSm + ((mbase + mt*16)*GSTRIDE_W + aRowOff + kk) * 4;
            LDSM4(a[mt][0], a[mt][1], a[mt][2], a[mt][3], addr);
        }
        uint32_t bfr[4][2];
#pragma unroll
        for (int np = 0; np < 2; np++) {
            uint32_t addr = bSm + ((nbase + np*16)*GSTRIDE_W + bRowOff + kk) * 4;
            LDSM4(bfr[np*2][0], bfr[np*2][1], bfr[np*2+1][0], bfr[np*2+1][1], addr);
        }
#pragma unroll
        for (int mt = 0; mt < 4; mt++)
#pragma unroll
            for (int nt = 0; nt < 4; nt++)
                MMA_TF32(c[mt][nt], a[mt][0], a[mt][1], a[mt][2], a[mt][3],
                         bfr[nt][0], bfr[nt][1]);
    }

    const float* sq = g_sq + b*NN;
    float* glb = g_gl + (size_t)b*NN*NN;
    const int gid = lane >> 2, tq = lane & 3;
#pragma unroll
    for (int mt = 0; mt < 4; mt++) {
        const int rl = mbase + mt*16 + gid;
        const int gi0 = i0 + rl, gi1 = gi0 + 8;
        const float sqa = sq[gi0], sqb = sq[gi1];
        float rp0 = 0.f, rp1 = 0.f;
#pragma unroll
        for (int nt = 0; nt < 4; nt++) {
            const int col = j0 + nbase + nt*8 + tq*2;
            const float sj0 = sq[col], sj1 = sq[col+1];
            float d00 = fmaxf(sqa + sj0 - 2.f*c[mt][nt][0], 0.f);
            float d01 = fmaxf(sqa + sj1 - 2.f*c[mt][nt][1], 0.f);
            float d10 = fmaxf(sqb + sj0 - 2.f*c[mt][nt][2], 0.f);
            float d11 = fmaxf(sqb + sj1 - 2.f*c[mt][nt][3], 0.f);
            float v00 = rnd_tf32(__expf(__expf(-d00*(1.f/128.f)) + ((gi0 == col)   ? 1.f : 0.f)));
            float v01 = rnd_tf32(__expf(__expf(-d01*(1.f/128.f)) + ((gi0 == col+1) ? 1.f : 0.f)));
            float v10 = rnd_tf32(__expf(__expf(-d10*(1.f/128.f)) + ((gi1 == col)   ? 1.f : 0.f)));
            float v11 = rnd_tf32(__expf(__expf(-d11*(1.f/128.f)) + ((gi1 == col+1) ? 1.f : 0.f)));
            float2 w0 = {v00, v01}, w1 = {v10, v11};
            *(float2*)(glb + (size_t)gi0 * NN + col) = w0;
            *(float2*)(glb + (size_t)gi1 * NN + col) = w1;
            rp0 += v00 + v01;
            rp1 += v10 + v11;
        }
        rp0 += __shfl_xor_sync(0xffffffffu, rp0, 1, 4);
        rp0 += __shfl_xor_sync(0xffffffffu, rp0, 2, 4);
        rp1 += __shfl_xor_sync(0xffffffffu, rp1, 1, 4);
        rp1 += __shfl_xor_sync(0xffffffffu, rp1, 2, 4);
        if (tq == 0) {
            rowsW[wid][mt*16 + gid]     = rp0;
            rowsW[wid][mt*16 + gid + 8] = rp1;
        }
    }
    __syncthreads();
    if (tid < 128) {
        int half = tid >> 6, lr = tid & 63;
        float s = rowsW[half*4 + 0][lr] + rowsW[half*4 + 1][lr]
                + rowsW[half*4 + 2][lr] + rowsW[half*4 + 3][lr];
        g_part[((size_t)b*8 + jb)*NN + i0 + tid] = s;
    }
}

// ---------------- transpose + round xuai -> xuaiT ----------------
__global__ void k_xT() {
    __shared__ float t[32][33];
    int b = blockIdx.z, n0 = blockIdx.x * 32, c0 = blockIdx.y * 32;
    const float* X = g_xuai + (size_t)b*CC*NN;
    for (int r = threadIdx.y; r < 32; r += 8)
        t[r][threadIdx.x] = X[(size_t)(c0 + r)*NN + n0 + threadIdx.x];
    __syncthreads();
    float* XT = g_xuaiT + (size_t)b*NN*CC;
    for (int r = threadIdx.y; r < 32; r += 8)
        XT[(size_t)(n0 + r)*CC + c0 + threadIdx.x] = rnd_tf32(t[threadIdx.x][r]);
}

// ---------------- tf32 rounding copy ----------------
__global__ void k_wround(const float* __restrict__ src) {
    size_t i = ((size_t)blockIdx.x * 256 + threadIdx.x) * 4;
    float4 v = *(const float4*)(src + i);
    float4 w = { rnd_tf32(v.x), rnd_tf32(v.y), rnd_tf32(v.z), rnd_tf32(v.w) };
    *(float4*)(g_wr + i) = w;
}

// ---------------- laplacian prep ----------------
__global__ void k_lap_d(const float* __restrict__ graph) {
    int i = blockIdx.x, k = blockIdx.y, t = threadIdx.x;
    const float* row = graph + (size_t)k*NN*NN + (size_t)i*NN;
    float s = 0.f;
    for (int j = t; j < NN; j += 256) s += row[j];
    __shared__ float sh[256];
    sh[t] = s; __syncthreads();
    for (int o = 128; o > 0; o >>= 1) { if (t < o) sh[t] += sh[t+o]; __syncthreads(); }
    if (t == 0) g_d[k*NN + i] = rsqrtf(sh[0] + 1.0f);
}

__global__ void k_lapT(const float* __restrict__ graph) {
    int kg = blockIdx.y, m = blockIdx.x, t = threadIdx.x;
    const float* src = graph + (size_t)kg*NN*NN + (size_t)m*NN;
    float* dst = ((kg == 0) ? g_g1 : g_g2) + (size_t)m*NN;
    const float* d = g_d + kg*NN;
    float dm = d[m];
#pragma unroll
    for (int q = 0; q < 4; q++) {
        int k = t + 256*q;
        float v = src[k] + ((m == k) ? 1.f : 0.f);
        dst[k] = rnd_tf32(v * dm * d[k]);
    }
}

// ---------------- embedding stage 1 ----------------
__global__ void k_emb1(const float* __restrict__ x, const float* __restrict__ emb_w,
                       const float* __restrict__ emb_b) {
    __shared__ float w[CC*CIN];
    __shared__ float bsm[CC];
    int t = threadIdx.x;
    for (int i = t; i < CC*CIN; i += 256) w[i] = emb_w[i];
    if (t < CC) bsm[t] = emb_b[t];
    __syncthreads();
    int b = blockIdx.x;
    int n = blockIdx.y * 256 + t;
    int e0 = blockIdx.z * 16;
    float xv[CIN];
    const float* xp = x + (size_t)b*CIN*NN + n;
#pragma unroll
    for (int c = 0; c < CIN; c++) xv[c] = xp[(size_t)c*NN];
    float* out = g_h0a + (size_t)b*CC*NN + n;
    for (int e = e0; e < e0 + 16; e++) {
        float s = bsm[e];
#pragma unroll
        for (int c = 0; c < CIN; c++) s = fmaf(w[e*CIN + c], xv[c], s);
        float lv = (s > 0.f) ? s : 0.01f*s;
        out[(size_t)e*NN] = rnd_tf32(lv);
    }
}

// ------- 64x64 channel mix; optional fused rank-1 scores (s1/s2) or sumsq (sq) ------
__global__ void __launch_bounds__(128)
chanmixD(const float* __restrict__ in, const float* __restrict__ in2,
         const float* __restrict__ in3, const float* __restrict__ in4,
         int reluIn, size_t inBstride, size_t inZoff,
         const float* __restrict__ Wa, const float* __restrict__ ba,
         const float* __restrict__ Wb, const float* __restrict__ bb_,
         int trans, int roundOut, float* __restrict__ out, size_t outBstride,
         float* __restrict__ out2, const float* __restrict__ nScale,
         const float* __restrict__ attA, float* __restrict__ s1o,
         float* __restrict__ s2o, float* __restrict__ sqo) {
    const int z = blockIdx.z;
    const float* W    = z ? Wb  : Wa;
    const float* bias = z ? bb_ : ba;
    const int b = blockIdx.y, n0 = blockIdx.x * 64;
    __shared__ float Ms[64*PADN];
    __shared__ float Xs[64*PADN];
    __shared__ float redA[8*64];
    __shared__ float redB[8*64];
    __shared__ float a1s[64], a2s[64];
    const int tid = threadIdx.x;
    for (int i = tid; i < 64*64; i += 128) {
        int o = i >> 6, k = i & 63;
        Ms[k*PADN + o] = trans ? W[k*64 + o] : W[o*64 + k];
    }
    if (attA) {
        if (tid < 64) a1s[tid] = attA[tid];
        else a2s[tid-64] = attA[tid];
    }
    const size_t boff = (size_t)b*inBstride + (size_t)z*inZoff + n0;
    for (int i = tid; i < 64*16; i += 128) {
        int k = i >> 4, n4 = (i & 15) * 4;
        size_t off = boff + (size_t)k*NN + n4;
        float4 v = *(const float4*)(in + off);
        if (in2) { float4 w2 = *(const float4*)(in2 + off); v.x+=w2.x; v.y+=w2.y; v.z+=w2.z; v.w+=w2.w; }
        if (in3) { float4 w3 = *(const float4*)(in3 + off); v.x+=w3.x; v.y+=w3.y; v.z+=w3.z; v.w+=w3.w; }
        if (in4) { float4 w4 = *(const float4*)(in4 + off); v.x+=w4.x; v.y+=w4.y; v.z+=w4.z; v.w+=w4.w; }
        if (reluIn) {
            v.x = fmaxf(v.x, 0.f); v.y = fmaxf(v.y, 0.f);
            v.z = fmaxf(v.z, 0.f); v.w = fmaxf(v.w, 0.f);
        }
        *(float4*)&Xs[k*PADN + n4] = v;
    }
    __syncthreads();
    const int tx = tid & 15, ty = tid >> 4;
    u64 acc[4][4] = {};
#pragma unroll 8
    for (int k = 0; k < 64; k++) {
        const float* mrow = &Ms[k*PADN + ty*8];
        ulonglong2 av0 = *(const ulonglong2*)(mrow);
        ulonglong2 av1 = *(const ulonglong2*)(mrow + 4);
        float4 xv = *(const float4*)&Xs[k*PADN + tx*4];
        u64 gs0 = splat2(xv.x), gs1 = splat2(xv.y), gs2 = splat2(xv.z), gs3 = splat2(xv.w);
        ffma2(acc[0][0], av0.x, gs0); ffma2(acc[0][1], av0.x, gs1);
        ffma2(acc[0][2], av0.x, gs2); ffma2(acc[0][3], av0.x, gs3);
        ffma2(acc[1][0], av0.y, gs0); ffma2(acc[1][1], av0.y, gs1);
        ffma2(acc[1][2], av0.y, gs2); ffma2(acc[1][3], av0.y, gs3);
        ffma2(acc[2][0], av1.x, gs0); ffma2(acc[2][1], av1.x, gs1);
        ffma2(acc[2][2], av1.x, gs2); ffma2(acc[2][3], av1.x, gs3);
        ffma2(acc[3][0], av1.y, gs0); ffma2(acc[3][1], av1.y, gs1);
        ffma2(acc[3][2], av1.y, gs2); ffma2(acc[3][3], av1.y, gs3);
    }
    float* outb = out + (size_t)b*outBstride + (size_t)z*CC*NN + n0;
    float* outb2 = out2 ? out2 + (size_t)b*outBstride + (size_t)z*CC*NN + n0 : nullptr;
    float4 sc = {1.f,1.f,1.f,1.f};
    if (outb2) sc = *(const float4*)(nScale + (size_t)b*NN + n0 + tx*4);
    float4 ps1 = {0.f,0.f,0.f,0.f};
    float4 ps2 = {0.f,0.f,0.f,0.f};
#pragma unroll
    for (int i = 0; i < 4; i++) {
        int o = ty*8 + 2*i;
        float b0 = bias ? bias[o]   : 0.f;
        float b1 = bias ? bias[o+1] : 0.f;
        float2 v0 = unpack2(acc[i][0]), v1 = unpack2(acc[i][1]);
        float2 v2 = unpack2(acc[i][2]), v3 = unpack2(acc[i][3]);
        float4 lo = {v0.x + b0, v1.x + b0, v2.x + b0, v3.x + b0};
        float4 hi = {v0.y + b1, v1.y + b1, v2.y + b1, v3.y + b1};
        if (roundOut) {
            lo.x = rnd_tf32(lo.x); lo.y = rnd_tf32(lo.y);
            lo.z = rnd_tf32(lo.z); lo.w = rnd_tf32(lo.w);
            hi.x = rnd_tf32(hi.x); hi.y = rnd_tf32(hi.y);
            hi.z = rnd_tf32(hi.z); hi.w = rnd_tf32(hi.w);
        }
        if (attA) {
            float a1o = a1s[o], a1o1 = a1s[o+1];
            float a2o = a2s[o], a2o1 = a2s[o+1];
            ps1.x = fmaf(lo.x, a1o, fmaf(hi.x, a1o1, ps1.x));
            ps1.y = fmaf(lo.y, a1o, fmaf(hi.y, a1o1, ps1.y));
            ps1.z = fmaf(lo.z, a1o, fmaf(hi.z, a1o1, ps1.z));
            ps1.w = fmaf(lo.w, a1o, fmaf(hi.w, a1o1, ps1.w));
            ps2.x = fmaf(lo.x, a2o, fmaf(hi.x, a2o1, ps2.x));
            ps2.y = fmaf(lo.y, a2o, fmaf(hi.y, a2o1, ps2.y));
            ps2.z = fmaf(lo.z, a2o, fmaf(hi.z, a2o1, ps2.z));
            ps2.w = fmaf(lo.w, a2o, fmaf(hi.w, a2o1, ps2.w));
        }
        if (sqo) {
            ps1.x = fmaf(lo.x, lo.x, fmaf(hi.x, hi.x, ps1.x));
            ps1.y = fmaf(lo.y, lo.y, fmaf(hi.y, hi.y, ps1.y));
            ps1.z = fmaf(lo.z, lo.z, fmaf(hi.z, hi.z, ps1.z));
            ps1.w = fmaf(lo.w, lo.w, fmaf(hi.w, hi.w, ps1.w));
        }
        *(float4*)(outb + (size_t)o*NN + tx*4) = lo;
        *(float4*)(outb + (size_t)(o+1)*NN + tx*4) = hi;
        if (outb2) {
            float4 lo2 = {rnd_tf32(lo.x*sc.x), rnd_tf32(lo.y*sc.y),
                          rnd_tf32(lo.z*sc.z), rnd_tf32(lo.w*sc.w)};
            float4 hi2 = {rnd_tf32(hi.x*sc.x), rnd_tf32(hi.y*sc.y),
                          rnd_tf32(hi.z*sc.z), rnd_tf32(hi.w*sc.w)};
            *(float4*)(outb2 + (size_t)o*NN + tx*4) = lo2;
            *(float4*)(outb2 + (size_t)(o+1)*NN + tx*4) = hi2;
        }
    }
    if (attA || sqo) {
        *(float4*)&redA[ty*64 + tx*4] = ps1;
        if (attA) *(float4*)&redB[ty*64 + tx*4] = ps2;
        __syncthreads();
        if (tid < 64) {
            float sa = 0.f, sb = 0.f;
#pragma unroll
            for (int r = 0; r < 8; r++) {
                sa += redA[r*64 + tid];
                if (attA) sb += redB[r*64 + tid];
            }
            if (attA) {
                s1o[b*NN + n0 + tid] = sa;
                s2o[b*NN + n0 + tid] = sb;
            } else {
                sqo[b*NN + n0 + tid] = sa;
            }
        }
    }
}

// ---------------- attention row max + inv-sum (batch max inlined) ----------------
__global__ void k_attinv() {
    int b = blockIdx.y, t = threadIdx.x;
    const float* s2 = g_s2 + b*NN;
    __shared__ float sh[256];
    float mx = fmaxf(fmaxf(s2[t], s2[t+256]), fmaxf(s2[t+512], s2[t+768]));
    sh[t] = mx; __syncthreads();
    for (int o = 128; o > 0; o >>= 1) { if (t < o) sh[t] = fmaxf(sh[t], sh[t+o]); __syncthreads(); }
    float mxs2 = sh[0];

    int row = blockIdx.x * 8 + (t >> 5);
    int lane = t & 31;
    float s1v = g_s1[b*NN + row];
    float m = s1v + mxs2;
    m = (m > 0.f) ? m : 0.01f * m;
    float sum = 0.f;
    for (int j = lane; j < NN; j += 32) {
        float e = s1v + s2[j];
        e = (e > 0.f) ? e : 0.01f * e;
        sum += __expf(e - m);
    }
#pragma unroll
    for (int o = 16; o > 0; o >>= 1) sum += __shfl_down_sync(0xffffffffu, sum, o);
    if (lane == 0) {
        g_amx [b*NN + row] = m;
        g_ainv[b*NN + row] = 1.f / sum;
    }
}

// ---------------- gl row-sum finish ----------------
__global__ void k_rsfin() {
    int b = blockIdx.x, i = threadIdx.x;
    float s = 0.f;
#pragma unroll
    for (int j = 0; j < 8; j++) s += g_part[((size_t)b*8 + j)*NN + i];
    g_rsinv[b*NN + i] = 1.f / s;
}

// ---------------- layernorm stats + final fuse ----------------
__global__ void k_lnstats() {
    int b = blockIdx.x, path = blockIdx.y, t = threadIdx.x;
    size_t base = (size_t)b*(2*CC)*NN + (size_t)path*CC*NN;
    float s = 0.f, ss = 0.f;
    for (int i = t; i < CC*NN; i += 1024) {
        float v = g_sxa[base + i] + g_sxb[base + i];
        s += v; ss = fmaf(v, v, ss);
    }
    __shared__ float shs[1024], shq[1024];
    shs[t] = s; shq[t] = ss; __syncthreads();
    for (int o = 512; o > 0; o >>= 1) {
        if (t < o) { shs[t] += shs[t+o]; shq[t] += shq[t+o]; }
        __syncthreads();
    }
    if (t == 0) {
        float mean = shs[0] * (1.f/65536.f);
        float var  = shq[0] * (1.f/65536.f) - mean*mean;
        g_stats[(path*BB + b)*2 + 0] = mean;
        g_stats[(path*BB + b)*2 + 1] = rsqrtf(var + 1e-5f);
    }
}

__global__ void k_final(const float* __restrict__ ct, const float* __restrict__ ln_w,
                        const float* __restrict__ ln_b, float* __restrict__ out) {
    size_t idx = (size_t)blockIdx.x * 256 + threadIdx.x;
    int b  = (int)(idx / (CC*NN));
    int cn = (int)(idx % (CC*NN));
    float m1 = g_stats[b*2 + 0],            r1 = g_stats[b*2 + 1];
    float m2 = g_stats[(BB + b)*2 + 0],     r2 = g_stats[(BB + b)*2 + 1];
    float w = ln_w[cn], bb = ln_b[cn];
    size_t base = (size_t)b*(2*CC)*NN + cn;
    float z1v = g_sxa[base] + g_sxb[base];
    float z2v = g_sxa[base + (size_t)CC*NN] + g_sxb[base + (size_t)CC*NN];
    float xnew = (z1v - m1) * r1 * w + bb;
    float z2   = (z2v - m2) * r2 * w + bb;
    float ft = 0.5f * z2 * (1.f + erff(z2 * 0.70710678118654752f));
    float ctv = ct[idx];
    float ctn = xnew + ft * (ctv - xnew);
    float el  = (ctn > 0.f) ? ctn : expm1f(ctn);
    float xu  = g_xuai[idx];
    float ht  = xu + ft * (el - xu);
    out[idx] = ht;
    out[(size_t)BB*CC*NN + idx] = ctn;
}

// ---------------- host launch ----------------
struct DevPtrs {
    float *gl, *g1, *g2, *wr, *h0a, *hT, *xuai;
    float *pa, *pb, *pc, *pd;
    float *l12, *l12s, *t12a, *t12b, *u12, *a12a, *a12b, *sxa, *sxb, *rsinv;
    float *s1, *s2, *sq;
    bool init;
};
static DevPtrs P = {};
static const int GRAM_SMEM = 2 * 128 * GSTRIDE_W * 4;

static void init_ptrs() {
    if (P.init) return;
    void* p;
#define GET(sym, field) cudaGetSymbolAddress(&p, sym); P.field = (float*)p;
    GET(g_gl, gl)   GET(g_g1, g1)   GET(g_g2, g2)
    GET(g_wr, wr)    GET(g_h0a, h0a) GET(g_hT, hT)   GET(g_xuai, xuai)
    GET(g_pa, pa)    GET(g_pb, pb)   GET(g_pc, pc)   GET(g_pd, pd)
    GET(g_l12, l12)  GET(g_l12s, l12s)
    GET(g_t12a, t12a) GET(g_t12b, t12b) GET(g_u12, u12)
    GET(g_a12a, a12a) GET(g_a12b, a12b) GET(g_sxa, sxa) GET(g_sxb, sxb)
    GET(g_rsinv, rsinv) GET(g_s1, s1) GET(g_s2, s2) GET(g_sq, sq)
#undef GET
    cudaFuncSetAttribute(k_gram_mma, cudaFuncAttributeMaxDynamicSharedMemorySize, GRAM_SMEM);
    P.init = true;
}

extern "C" void kernel_launch(void* const* d_in, const int* in_sizes, int n_in,
                              void* d_out, int out_size) {
    const float* x      = (const float*)d_in[0];
    const float* ct     = (const float*)d_in[1];
    const float* graph  = (const float*)d_in[2];
    const float* emb_w  = (const float*)d_in[3];
    const float* emb_b  = (const float*)d_in[4];
    const float* emb2_w = (const float*)d_in[5];
    const float* emb2_b = (const float*)d_in[6];
    const float* att_W  = (const float*)d_in[7];
    const float* att_a  = (const float*)d_in[8];
    // d_in[9] = att_GL : unused (softmax output strictly positive => mask no-op)
    const float* uai_w  = (const float*)d_in[10];
    const float* uai_b  = (const float*)d_in[11];
    const float* lin1_w = (const float*)d_in[12];
    const float* lin2_w = (const float*)d_in[13];
    const float* lin2_b = (const float*)d_in[14];
    const float* ln_w   = (const float*)d_in[15];
    const float* ln_b   = (const float*)d_in[16];
    float* out = (float*)d_out;

    init_ptrs();

    const size_t GLSTRIDE = (size_t)NN * NN;
    const size_t SB = (size_t)CC * NN;
    const size_t DB = (size_t)2 * CC * NN;
    const dim3 gridC1(NN/64, BB, 1);
    const dim3 gridC2(NN/64, BB, 2);

    // graph laplacians (K-major, tf32-rounded) + rounded emb2 weights
    k_lap_d <<<dim3(NN, 2), 256>>>(graph);
    k_lapT  <<<dim3(NN, 2), 256>>>(graph);
    k_wround<<<NN*NN/1024, 256>>>(emb2_w);

    // embedding
    k_emb1  <<<dim3(BB, NN/256, 4), 256>>>(x, emb_w, emb_b);
    mma_gemm<<<dim3(8, BB/2, 4), 256>>>(P.h0a, DB, 128, P.wr, 0, 4,
                                        nullptr, nullptr, emb2_b,
                                        P.pa, P.pb, P.pc, P.pd, DB);

    // attention: hT chanmix with fused s1/s2 rank-1 scores
    chanmixD<<<gridC1, 128>>>(P.pa, P.pb, P.pc, P.pd, 0, SB, 0,
                              att_W, nullptr, att_W, nullptr, 1, 1, P.hT, SB,
                              nullptr, nullptr, att_a, P.s1, P.s2, nullptr);
    k_attinv<<<dim3(NN/8, BB), 256>>>();
    mma_gemm_att<<<dim3(8, BB, 2), 256>>>(P.hT, SB, P.pa, P.pb, SB);

    // UAI chanmix with fused sumsq
    chanmixD<<<gridC1, 128>>>(P.pa, P.pb, nullptr, nullptr, 1, SB, 0,
                              uai_w, uai_b, uai_w, uai_b, 0, 0, P.xuai, SB,
                              nullptr, nullptr, nullptr, nullptr, nullptr, P.sq);

    // learned adjacency: transpose, tensor-core gram + fused row partials
    k_xT   <<<dim3(NN/32, 2, BB), dim3(32, 8)>>>();
    k_gram_mma<<<dim3(8, 8, BB), 256, GRAM_SMEM>>>();
    k_rsfin<<<BB, 1024>>>();

    // l1/l2 stacked propagation
    chanmixD<<<gridC2, 128>>>(P.xuai, nullptr, nullptr, nullptr, 0, SB, 0,
                              lin1_w, nullptr, lin2_w, lin2_b, 0, 1, P.l12, DB,
                              P.l12s, P.rsinv, nullptr, nullptr, nullptr, nullptr);

    // merged: unit0 l12s@gl -> a12a/b ; unit1 l12@g1 -> t12a/b
    mma_gemm2<<<dim3(8, BB, 4), 256>>>(P.l12s, P.gl, GLSTRIDE,
                                       P.l12, P.g1, 0,
                                       P.a12a, P.a12b, P.t12a, P.t12b, DB);

    chanmixD<<<gridC2, 128>>>(P.t12a, P.t12b, nullptr, nullptr, 0, DB, SB,
                              lin1_w, nullptr, lin2_w, lin2_b, 0, 1, P.u12, DB,
                              nullptr, nullptr, nullptr, nullptr, nullptr, nullptr);

    mma_gemm<<<dim3(8, BB, 2), 256>>>(P.u12, DB, 128, P.g2, 0, 2,
                                      P.a12a, P.a12b, nullptr,
                                      P.sxa, P.sxb, nullptr, nullptr, DB);

    // layernorm + gates + output
    k_lnstats<<<dim3(BB, 2), 1024>>>();
    k_final  <<<(BB*CC*NN)/256, 256>>>(ct, ln_w, ln_b, out);
}

// round 13
// speedup vs baseline: 2.5974x; 1.0142x over previous
#include <cuda_runtime.h>
#include <math.h>
#include <stdint.h>

#define BB 16
#define NN 1024
#define CC 64
#define CIN 16
#define PADN 68

typedef unsigned long long u64;

// ---------------- fp32x2 helpers (chanmix) ----------------
__device__ __forceinline__ u64 splat2(float v) {
    u64 r; asm("mov.b64 %0, {%1, %1};" : "=l"(r) : "f"(v)); return r;
}
__device__ __forceinline__ void ffma2(u64& d, u64 a, u64 b) {
    asm("fma.rn.f32x2 %0, %1, %2, %0;" : "+l"(d) : "l"(a), "l"(b));
}
__device__ __forceinline__ float2 unpack2(u64 v) {
    float2 r; asm("mov.b64 {%0, %1}, %2;" : "=f"(r.x), "=f"(r.y) : "l"(v)); return r;
}

// ---------------- mma.sync tf32 + cp.async helpers ----------------
__device__ __forceinline__ uint32_t smem_u32(const void* p) {
    uint32_t a;
    asm("{ .reg .u64 t; cvta.to.shared.u64 t, %1; cvt.u32.u64 %0, t; }" : "=r"(a) : "l"(p));
    return a;
}
__device__ __forceinline__ float rnd_tf32(float f) {
    uint32_t r; asm("cvt.rna.tf32.f32 %0, %1;" : "=r"(r) : "f"(f));
    return __uint_as_float(r);
}
#define LDSM4(r0, r1, r2, r3, addr)                                            \
    asm volatile("ldmatrix.sync.aligned.m8n8.x4.shared.b16 {%0,%1,%2,%3}, [%4];" \
        : "=r"(r0), "=r"(r1), "=r"(r2), "=r"(r3) : "r"(addr))
#define MMA_TF32(c, a0, a1, a2, a3, b0, b1)                                    \
    asm volatile("mma.sync.aligned.m16n8k8.row.col.f32.tf32.tf32.f32 "         \
        "{%0,%1,%2,%3}, {%4,%5,%6,%7}, {%8,%9}, {%0,%1,%2,%3};"                \
        : "+f"((c)[0]), "+f"((c)[1]), "+f"((c)[2]), "+f"((c)[3])               \
        : "r"(a0), "r"(a1), "r"(a2), "r"(a3), "r"(b0), "r"(b1))
__device__ __forceinline__ void cp16(uint32_t dst, const void* src) {
    asm volatile("cp.async.cg.shared.global [%0], [%1], 16;" :: "r"(dst), "l"(src));
}
#define CP_COMMIT()  asm volatile("cp.async.commit_group;" ::: "memory")
#define CP_WAIT1()   asm volatile("cp.async.wait_group 1;" ::: "memory")
#define CP_WAIT0()   asm volatile("cp.async.wait_group 0;" ::: "memory")

// ---------------- static device scratch ----------------
__device__ float g_gl  [BB*NN*NN];
__device__ float g_g1  [NN*NN];
__device__ float g_g2  [NN*NN];
__device__ float g_wr  [NN*NN];
__device__ float g_d   [2*NN];
__device__ float g_h0a [BB*CC*NN];
__device__ float g_hT  [BB*CC*NN];
__device__ float g_xuai[BB*CC*NN];
__device__ float g_xuaiT[BB*NN*CC];
__device__ float g_pa  [BB*CC*NN];
__device__ float g_pb  [BB*CC*NN];
__device__ float g_pc  [BB*CC*NN];
__device__ float g_pd  [BB*CC*NN];
__device__ float g_l12 [BB*2*CC*NN];
__device__ float g_l12s[BB*2*CC*NN];
__device__ float g_t12a[BB*2*CC*NN];
__device__ float g_t12b[BB*2*CC*NN];
__device__ float g_u12 [BB*2*CC*NN];
__device__ float g_a12a[BB*2*CC*NN];
__device__ float g_a12b[BB*2*CC*NN];
__device__ float g_sxa [BB*2*CC*NN];
__device__ float g_sxb [BB*2*CC*NN];
__device__ float g_s1  [BB*NN];
__device__ float g_s2  [BB*NN];
__device__ float g_amx [BB*NN];
__device__ float g_ainv[BB*NN];
__device__ float g_sq  [BB*NN];
__device__ float g_part[BB*8*NN];
__device__ float g_stats[2*BB*2];

// =========================================================================
// mma_gemm (tf32): C_ks[b,c,n] = sum_{k in split ks} A[b,c,k] * B[b,n,k]
// =========================================================================
#define TPAD 20
__global__ void __launch_bounds__(256, 2)
mma_gemm(const float* __restrict__ A, size_t aBatch, int mvalid,
         const float* __restrict__ B, size_t bBatch, int nsplit,
         const float* __restrict__ add0, const float* __restrict__ add1,
         const float* __restrict__ biasN,
         float* __restrict__ C0, float* __restrict__ C1,
         float* __restrict__ C2, float* __restrict__ C3, size_t cBatch)
{
    __shared__ uint32_t As[2][128*TPAD];
    __shared__ uint32_t Bs[2][128*TPAD];

    const int tid  = threadIdx.x;
    const int lane = tid & 31;
    const int wid  = tid >> 5;
    const int bidx = blockIdx.y;
    const int n0   = blockIdx.x * 128;
    const int ks   = blockIdx.z;
    const int kPer = NN / nsplit;
    const int T    = kPer / 16;
    const int k0b  = ks * kPer;

    const float* Ab = A + (size_t)bidx * aBatch + k0b;
    const float* Bb = B + (size_t)bidx * bBatch + (size_t)n0 * NN + k0b;

    const int frow0 = tid >> 2;
    const int frow1 = 64 + (tid >> 2);
    const int fkq   = (tid & 3) * 4;

    const float* aP0 = Ab + (size_t)frow0 * NN + fkq;
    const float* aP1 = Ab + (size_t)((frow1 < mvalid) ? frow1 : 0) * NN + fkq;
    const float* bP0 = Bb + (size_t)frow0 * NN + fkq;
    const float* bP1 = Bb + (size_t)frow1 * NN + fkq;

    const uint32_t aSm = smem_u32(&As[0][0]);
    const uint32_t bSm = smem_u32(&Bs[0][0]);
    const uint32_t aFill  = aSm + (frow0*TPAD + fkq) * 4;
    const uint32_t aFill1 = aSm + (frow1*TPAD + fkq) * 4;
    const uint32_t bFill  = bSm + (frow0*TPAD + fkq) * 4;
    const uint32_t bFill1 = bSm + (frow1*TPAD + fkq) * 4;
    const uint32_t bufStride = 128*TPAD*4;

    const int aRowOff = (lane & 15) * TPAD + (lane >> 4) * 4;
    const int bRowOff = ((lane >> 4) * 8 + (lane & 7)) * TPAD + ((lane >> 3) & 1) * 4;

    const int mbase = (wid >> 2) * 64;
    const int nbase = (wid & 3) * 32;

    float c[4][4][4];
#pragma unroll
    for (int i = 0; i < 4; i++)
#pragma unroll
        for (int j = 0; j < 4; j++)
#pragma unroll
            for (int q = 0; q < 4; q++) c[i][j][q] = 0.f;

    cp16(aFill,  aP0); cp16(aFill1, aP1);
    cp16(bFill,  bP0); cp16(bFill1, bP1);
    CP_COMMIT();

    for (int t = 0; t < T; ++t) {
        const int cur = t & 1;
        if (t + 1 < T) {
            const uint32_t off = (uint32_t)((t+1) & 1) * bufStride;
            const int ko = (t + 1) * 16;
            cp16(aFill  + off, aP0 + ko);
            cp16(aFill1 + off, aP1 + ko);
            cp16(bFill  + off, bP0 + ko);
            cp16(bFill1 + off, bP1 + ko);
            CP_COMMIT();
            CP_WAIT1();
        } else {
            CP_WAIT0();
        }
        __syncthreads();
        {
            const uint32_t aCur = aSm + cur * bufStride;
            const uint32_t bCur = bSm + cur * bufStride;
#pragma unroll
            for (int kk = 0; kk < 16; kk += 8) {
                uint32_t a[4][4];
#pragma unroll
                for (int mt = 0; mt < 4; mt++) {
                    uint32_t addr = aCur + ((mbase + mt*16)*TPAD + aRowOff + kk) * 4;
                    LDSM4(a[mt][0], a[mt][1], a[mt][2], a[mt][3], addr);
                }
                uint32_t bfr[4][2];
#pragma unroll
                for (int np = 0; np < 2; np++) {
                    uint32_t addr = bCur + ((nbase + np*16)*TPAD + bRowOff + kk) * 4;
                    LDSM4(bfr[np*2][0], bfr[np*2][1], bfr[np*2+1][0], bfr[np*2+1][1], addr);
                }
#pragma unroll
                for (int mt = 0; mt < 4; mt++)
#pragma unroll
                    for (int nt = 0; nt < 4; nt++)
                        MMA_TF32(c[mt][nt], a[mt][0], a[mt][1], a[mt][2], a[mt][3],
                                 bfr[nt][0], bfr[nt][1]);
            }
        }
        __syncthreads();
    }

    if (mbase >= mvalid) return;
    float* C = (ks == 0) ? C0 : (ks == 1) ? C1 : (ks == 2) ? C2 : C3;
    const float* add = (ks == 0) ? add0 : (ks == 1) ? add1 : nullptr;
    float* Cb = C + (size_t)bidx * cBatch;
    const float* Adb = add ? add + (size_t)bidx * cBatch : nullptr;
    const int gid = lane >> 2, tq = lane & 3;
#pragma unroll
    for (int mt = 0; mt < 4; mt++) {
        const int r = mbase + mt*16 + gid;
#pragma unroll
        for (int nt = 0; nt < 4; nt++) {
            const int col = n0 + nbase + nt*8 + tq*2;
            float2 v0 = { c[mt][nt][0], c[mt][nt][1] };
            float2 v1 = { c[mt][nt][2], c[mt][nt][3] };
            if (biasN && ks == 0) {
                float b0 = biasN[col], b1 = biasN[col+1];
                v0.x += b0; v0.y += b1; v1.x += b0; v1.y += b1;
            }
            if (Adb) {
                float2 d0 = *(const float2*)(Adb + (size_t)r * NN + col);
                float2 d1 = *(const float2*)(Adb + (size_t)(r+8) * NN + col);
                v0.x += d0.x; v0.y += d0.y; v1.x += d1.x; v1.y += d1.y;
            }
            *(float2*)(Cb + (size_t)r * NN + col)     = v0;
            *(float2*)(Cb + (size_t)(r+8) * NN + col) = v1;
        }
    }
}

// =========================================================================
// mma_gemm2: two independent GEMM units in one launch (unit = z>>1, ks = z&1).
// =========================================================================
__global__ void __launch_bounds__(256, 2)
mma_gemm2(const float* __restrict__ A0, const float* __restrict__ B0, size_t bS0,
          const float* __restrict__ A1, const float* __restrict__ B1, size_t bS1,
          float* __restrict__ C00, float* __restrict__ C01,
          float* __restrict__ C10, float* __restrict__ C11, size_t cBatch)
{
    __shared__ uint32_t As[2][128*TPAD];
    __shared__ uint32_t Bs[2][128*TPAD];

    const int tid  = threadIdx.x;
    const int lane = tid & 31;
    const int wid  = tid >> 5;
    const int bidx = blockIdx.y;
    const int n0   = blockIdx.x * 128;
    const int unit = blockIdx.z >> 1;
    const int ks   = blockIdx.z & 1;
    const int k0b  = ks * 512;
    const int T    = 32;

    const float* A = unit ? A1 : A0;
    const float* B = unit ? B1 : B0;
    const size_t bBatch = unit ? bS1 : bS0;

    const float* Ab = A + (size_t)bidx * (size_t)(2*CC)*NN + k0b;
    const float* Bb = B + (size_t)bidx * bBatch + (size_t)n0 * NN + k0b;

    const int frow0 = tid >> 2;
    const int frow1 = 64 + (tid >> 2);
    const int fkq   = (tid & 3) * 4;

    const float* aP0 = Ab + (size_t)frow0 * NN + fkq;
    const float* aP1 = Ab + (size_t)frow1 * NN + fkq;
    const float* bP0 = Bb + (size_t)frow0 * NN + fkq;
    const float* bP1 = Bb + (size_t)frow1 * NN + fkq;

    const uint32_t aSm = smem_u32(&As[0][0]);
    const uint32_t bSm = smem_u32(&Bs[0][0]);
    const uint32_t aFill  = aSm + (frow0*TPAD + fkq) * 4;
    const uint32_t aFill1 = aSm + (frow1*TPAD + fkq) * 4;
    const uint32_t bFill  = bSm + (frow0*TPAD + fkq) * 4;
    const uint32_t bFill1 = bSm + (frow1*TPAD + fkq) * 4;
    const uint32_t bufStride = 128*TPAD*4;

    const int aRowOff = (lane & 15) * TPAD + (lane >> 4) * 4;
    const int bRowOff = ((lane >> 4) * 8 + (lane & 7)) * TPAD + ((lane >> 3) & 1) * 4;

    const int mbase = (wid >> 2) * 64;
    const int nbase = (wid & 3) * 32;

    float c[4][4][4];
#pragma unroll
    for (int i = 0; i < 4; i++)
#pragma unroll
        for (int j = 0; j < 4; j++)
#pragma unroll
            for (int q = 0; q < 4; q++) c[i][j][q] = 0.f;

    cp16(aFill,  aP0); cp16(aFill1, aP1);
    cp16(bFill,  bP0); cp16(bFill1, bP1);
    CP_COMMIT();

    for (int t = 0; t < T; ++t) {
        const int cur = t & 1;
        if (t + 1 < T) {
            const uint32_t off = (uint32_t)((t+1) & 1) * bufStride;
            const int ko = (t + 1) * 16;
            cp16(aFill  + off, aP0 + ko);
            cp16(aFill1 + off, aP1 + ko);
            cp16(bFill  + off, bP0 + ko);
            cp16(bFill1 + off, bP1 + ko);
            CP_COMMIT();
            CP_WAIT1();
        } else {
            CP_WAIT0();
        }
        __syncthreads();
        {
            const uint32_t aCur = aSm + cur * bufStride;
            const uint32_t bCur = bSm + cur * bufStride;
#pragma unroll
            for (int kk = 0; kk < 16; kk += 8) {
                uint32_t a[4][4];
#pragma unroll
                for (int mt = 0; mt < 4; mt++) {
                    uint32_t addr = aCur + ((mbase + mt*16)*TPAD + aRowOff + kk) * 4;
                    LDSM4(a[mt][0], a[mt][1], a[mt][2], a[mt][3], addr);
                }
                uint32_t bfr[4][2];
#pragma unroll
                for (int np = 0; np < 2; np++) {
                    uint32_t addr = bCur + ((nbase + np*16)*TPAD + bRowOff + kk) * 4;
                    LDSM4(bfr[np*2][0], bfr[np*2][1], bfr[np*2+1][0], bfr[np*2+1][1], addr);
                }
#pragma unroll
                for (int mt = 0; mt < 4; mt++)
#pragma unroll
                    for (int nt = 0; nt < 4; nt++)
                        MMA_TF32(c[mt][nt], a[mt][0], a[mt][1], a[mt][2], a[mt][3],
                                 bfr[nt][0], bfr[nt][1]);
            }
        }
        __syncthreads();
    }

    float* C = unit ? (ks ? C11 : C10) : (ks ? C01 : C00);
    float* Cb = C + (size_t)bidx * cBatch;
    const int gid = lane >> 2, tq = lane & 3;
#pragma unroll
    for (int mt = 0; mt < 4; mt++) {
        const int r = mbase + mt*16 + gid;
#pragma unroll
        for (int nt = 0; nt < 4; nt++) {
            const int col = n0 + nbase + nt*8 + tq*2;
            float2 v0 = { c[mt][nt][0], c[mt][nt][1] };
            float2 v1 = { c[mt][nt][2], c[mt][nt][3] };
            *(float2*)(Cb + (size_t)r * NN + col)     = v0;
            *(float2*)(Cb + (size_t)(r+8) * NN + col) = v1;
        }
    }
}

// =========================================================================
// mma_gemm_att: attention MMA with on-the-fly B generation.
// =========================================================================
__device__ __forceinline__ float attval(float s1v, float s2v, float m, float iv) {
    float e = s1v + s2v;
    e = (e > 0.f) ? e : 0.01f * e;
    return rnd_tf32(__expf(e - m) * iv);
}

__global__ void __launch_bounds__(256, 2)
mma_gemm_att(const float* __restrict__ A, size_t aBatch,
             float* __restrict__ C0, float* __restrict__ C1, size_t cBatch)
{
    __shared__ uint32_t As[2][128*TPAD];
    __shared__ float    Bs[2][128*TPAD];

    const int tid  = threadIdx.x;
    const int lane = tid & 31;
    const int wid  = tid >> 5;
    const int bidx = blockIdx.y;
    const int n0   = blockIdx.x * 128;
    const int ks   = blockIdx.z;
    const int k0b  = ks * 512;
    const int T    = 32;

    const float* Ab = A + (size_t)bidx * aBatch + k0b;

    const int frow0 = tid >> 2;
    const int frow1 = 64 + (tid >> 2);
    const int fkq   = (tid & 3) * 4;

    const float* aP0 = Ab + (size_t)frow0 * NN + fkq;
    const float* aP1 = Ab;

    const float s1v0 = g_s1 [bidx*NN + n0 + frow0];
    const float m0   = g_amx[bidx*NN + n0 + frow0];
    const float iv0  = g_ainv[bidx*NN + n0 + frow0];
    const float s1v1 = g_s1 [bidx*NN + n0 + frow1];
    const float m1   = g_amx[bidx*NN + n0 + frow1];
    const float iv1  = g_ainv[bidx*NN + n0 + frow1];
    const float* s2p = g_s2 + bidx*NN + k0b + fkq;

    const uint32_t aSm = smem_u32(&As[0][0]);
    const uint32_t bSm = smem_u32(&Bs[0][0]);
    const uint32_t aFill  = aSm + (frow0*TPAD + fkq) * 4;
    const uint32_t aFill1 = aSm + (frow1*TPAD + fkq) * 4;
    const uint32_t bufStride = 128*TPAD*4;

    const int aRowOff = (lane & 15) * TPAD + (lane >> 4) * 4;
    const int bRowOff = ((lane >> 4) * 8 + (lane & 7)) * TPAD + ((lane >> 3) & 1) * 4;

    const int mbase = (wid >> 2) * 64;
    const int nbase = (wid & 3) * 32;

    float c[4][4][4];
#pragma unroll
    for (int i = 0; i < 4; i++)
#pragma unroll
        for (int j = 0; j < 4; j++)
#pragma unroll
            for (int q = 0; q < 4; q++) c[i][j][q] = 0.f;

    cp16(aFill,  aP0); cp16(aFill1, aP1 + fkq);
    CP_COMMIT();
    {
        float4 s2v = *(const float4*)(s2p);
        float4 b0 = { attval(s1v0, s2v.x, m0, iv0), attval(s1v0, s2v.y, m0, iv0),
                      attval(s1v0, s2v.z, m0, iv0), attval(s1v0, s2v.w, m0, iv0) };
        float4 b1 = { attval(s1v1, s2v.x, m1, iv1), attval(s1v1, s2v.y, m1, iv1),
                      attval(s1v1, s2v.z, m1, iv1), attval(s1v1, s2v.w, m1, iv1) };
        *(float4*)&Bs[0][frow0*TPAD + fkq] = b0;
        *(float4*)&Bs[0][frow1*TPAD + fkq] = b1;
    }
    __syncthreads();

    for (int t = 0; t < T; ++t) {
        const int cur = t & 1;
        if (t + 1 < T) {
            const int nxt = (t+1) & 1;
            const uint32_t off = (uint32_t)nxt * bufStride;
            const int ko = (t + 1) * 16;
            cp16(aFill  + off, aP0 + ko);
            cp16(aFill1 + off, aP1 + ko + fkq);
            CP_COMMIT();
            float4 s2v = *(const float4*)(s2p + ko);
            float4 b0 = { attval(s1v0, s2v.x, m0, iv0), attval(s1v0, s2v.y, m0, iv0),
                          attval(s1v0, s2v.z, m0, iv0), attval(s1v0, s2v.w, m0, iv0) };
            float4 b1 = { attval(s1v1, s2v.x, m1, iv1), attval(s1v1, s2v.y, m1, iv1),
                          attval(s1v1, s2v.z, m1, iv1), attval(s1v1, s2v.w, m1, iv1) };
            *(float4*)&Bs[nxt][frow0*TPAD + fkq] = b0;
            *(float4*)&Bs[nxt][frow1*TPAD + fkq] = b1;
            CP_WAIT1();
        } else {
            CP_WAIT0();
        }
        __syncthreads();
        {
            const uint32_t aCur = aSm + cur * bufStride;
            const uint32_t bCur = bSm + cur * bufStride;
#pragma unroll
            for (int kk = 0; kk < 16; kk += 8) {
                uint32_t a[4][4];
#pragma unroll
                for (int mt = 0; mt < 4; mt++) {
                    uint32_t addr = aCur + ((mbase + mt*16)*TPAD + aRowOff + kk) * 4;
                    LDSM4(a[mt][0], a[mt][1], a[mt][2], a[mt][3], addr);
                }
                uint32_t bfr[4][2];
#pragma unroll
                for (int np = 0; np < 2; np++) {
                    uint32_t addr = bCur + ((nbase + np*16)*TPAD + bRowOff + kk) * 4;
                    LDSM4(bfr[np*2][0], bfr[np*2][1], bfr[np*2+1][0], bfr[np*2+1][1], addr);
                }
#pragma unroll
                for (int mt = 0; mt < 4; mt++)
#pragma unroll
                    for (int nt = 0; nt < 4; nt++)
                        MMA_TF32(c[mt][nt], a[mt][0], a[mt][1], a[mt][2], a[mt][3],
                                 bfr[nt][0], bfr[nt][1]);
            }
        }
        __syncthreads();
    }

    if (mbase >= 64) return;
    float* Cb = (ks ? C1 : C0) + (size_t)bidx * cBatch;
    const int gid = lane >> 2, tq = lane & 3;
#pragma unroll
    for (int mt = 0; mt < 4; mt++) {
        const int r = mbase + mt*16 + gid;
#pragma unroll
        for (int nt = 0; nt < 4; nt++) {
            const int col = n0 + nbase + nt*8 + tq*2;
            float2 v0 = { c[mt][nt][0], c[mt][nt][1] };
            float2 v1 = { c[mt][nt][2], c[mt][nt][3] };
            *(float2*)(Cb + (size_t)r * NN + col)     = v0;
            *(float2*)(Cb + (size_t)(r+8) * NN + col) = v1;
        }
    }
}

// =========================================================================
// k_gram_mma: gl = transform( XtT @ XtT^T ), row partial sums fused.
// =========================================================================
#define GSTRIDE_W 68
__global__ void __launch_bounds__(256)
k_gram_mma()
{
    extern __shared__ uint32_t gsm[];
    __shared__ float rowsW[8][64];

    const int tid  = threadIdx.x;
    const int lane = tid & 31;
    const int wid  = tid >> 5;
    const int b  = blockIdx.z;
    const int i0 = blockIdx.x * 128;
    const int jb = blockIdx.y;
    const int j0 = jb * 128;

    const float* XT = g_xuaiT + (size_t)b * NN * CC;
    const uint32_t aSm = smem_u32(&gsm[0]);
    const uint32_t bSm = aSm + 128*GSTRIDE_W*4;

#pragma unroll
    for (int q = 0; q < 8; q++) {
        int f = q * 256 + tid;
        int row = f >> 4, seg = (f & 15) * 4;
        cp16(aSm + (row*GSTRIDE_W + seg) * 4, XT + (size_t)(i0 + row) * CC + seg);
        cp16(bSm + (row*GSTRIDE_W + seg) * 4, XT + (size_t)(j0 + row) * CC + seg);
    }
    CP_COMMIT();
    CP_WAIT0();
    __syncthreads();

    const int aRowOff = (lane & 15) * GSTRIDE_W + (lane >> 4) * 4;
    const int bRowOff = ((lane >> 4) * 8 + (lane & 7)) * GSTRIDE_W + ((lane >> 3) & 1) * 4;
    const int mbase = (wid >> 2) * 64;
    const int nbase = (wid & 3) * 32;

    float c[4][4][4];
#pragma unroll
    for (int i = 0; i < 4; i++)
#pragma unroll
        for (int j = 0; j < 4; j++)
#pragma unroll
            for (int q = 0; q < 4; q++) c[i][j][q] = 0.f;

#pragma unroll
    for (int kk = 0; kk < 64; kk += 8) {
        uint32_t a[4][4];
#pragma unroll
        for (int mt = 0; mt < 4; mt++) {
            uint32_t addr = aSm + ((mbase + mt*16)*GSTRIDE_W + aRowOff + kk) * 4;
            LDSM4(a[mt][0], a[mt][1], a[mt][2], a[mt][3], addr);
        }
        uint32_t bfr[4][2];
#pragma unroll
        for (int np = 0; np < 2; np++) {
            uint32_t addr = bSm + ((nbase + np*16)*GSTRIDE_W + bRowOff + kk) * 4;
            LDSM4(bfr[np*2][0], bfr[np*2][1], bfr[np*2+1][0], bfr[np*2+1][1], addr);
        }
#pragma unroll
        for (int mt = 0; mt < 4; mt++)
#pragma unroll
            for (int nt = 0; nt < 4; nt++)
                MMA_TF32(c[mt][nt], a[mt][0], a[mt][1], a[mt][2], a[mt][3],
                         bfr[nt][0], bfr[nt][1]);
    }

    const float* sq = g_sq + b*NN;
    float* glb = g_gl + (size_t)b*NN*NN;
    const int gid = lane >> 2, tq = lane & 3;
#pragma unroll
    for (int mt = 0; mt < 4; mt++) {
        const int rl = mbase + mt*16 + gid;
        const int gi0 = i0 + rl, gi1 = gi0 + 8;
        const float sqa = sq[gi0], sqb = sq[gi1];
        float rp0 = 0.f, rp1 = 0.f;
#pragma unroll
        for (int nt = 0; nt < 4; nt++) {
            const int col = j0 + nbase + nt*8 + tq*2;
            const float sj0 = sq[col], sj1 = sq[col+1];
            float d00 = fmaxf(sqa + sj0 - 2.f*c[mt][nt][0], 0.f);
            float d01 = fmaxf(sqa + sj1 - 2.f*c[mt][nt][1], 0.f);
            float d10 = fmaxf(sqb + sj0 - 2.f*c[mt][nt][2], 0.f);
            float d11 = fmaxf(sqb + sj1 - 2.f*c[mt][nt][3], 0.f);
            float v00 = rnd_tf32(__expf(__expf(-d00*(1.f/128.f)) + ((gi0 == col)   ? 1.f : 0.f)));
            float v01 = rnd_tf32(__expf(__expf(-d01*(1.f/128.f)) + ((gi0 == col+1) ? 1.f : 0.f)));
            float v10 = rnd_tf32(__expf(__expf(-d10*(1.f/128.f)) + ((gi1 == col)   ? 1.f : 0.f)));
            float v11 = rnd_tf32(__expf(__expf(-d11*(1.f/128.f)) + ((gi1 == col+1) ? 1.f : 0.f)));
            float2 w0 = {v00, v01}, w1 = {v10, v11};
            *(float2*)(glb + (size_t)gi0 * NN + col) = w0;
            *(float2*)(glb + (size_t)gi1 * NN + col) = w1;
            rp0 += v00 + v01;
            rp1 += v10 + v11;
        }
        rp0 += __shfl_xor_sync(0xffffffffu, rp0, 1, 4);
        rp0 += __shfl_xor_sync(0xffffffffu, rp0, 2, 4);
        rp1 += __shfl_xor_sync(0xffffffffu, rp1, 1, 4);
        rp1 += __shfl_xor_sync(0xffffffffu, rp1, 2, 4);
        if (tq == 0) {
            rowsW[wid][mt*16 + gid]     = rp0;
            rowsW[wid][mt*16 + gid + 8] = rp1;
        }
    }
    __syncthreads();
    if (tid < 128) {
        int half = tid >> 6, lr = tid & 63;
        float s = rowsW[half*4 + 0][lr] + rowsW[half*4 + 1][lr]
                + rowsW[half*4 + 2][lr] + rowsW[half*4 + 3][lr];
        g_part[((size_t)b*8 + jb)*NN + i0 + tid] = s;
    }
}

// ---------------- k_prep: lapT (y=0,1) + wround (y=2) + emb1 (y=3) ----------------
__global__ void k_prep(const float* __restrict__ graph, const float* __restrict__ emb2_w,
                       const float* __restrict__ x, const float* __restrict__ emb_w,
                       const float* __restrict__ emb_b) {
    __shared__ float w[CC*CIN];
    __shared__ float bsm[CC];
    const int plane = blockIdx.y;
    const int t = threadIdx.x;
    if (plane < 2) {
        int kg = plane, m = blockIdx.x;
        const float* src = graph + (size_t)kg*NN*NN + (size_t)m*NN;
        float* dst = ((kg == 0) ? g_g1 : g_g2) + (size_t)m*NN;
        const float* d = g_d + kg*NN;
        float dm = d[m];
#pragma unroll
        for (int q = 0; q < 4; q++) {
            int k = t + 256*q;
            float v = src[k] + ((m == k) ? 1.f : 0.f);
            dst[k] = rnd_tf32(v * dm * d[k]);
        }
    } else if (plane == 2) {
        size_t i = ((size_t)blockIdx.x * 256 + t) * 4;
        float4 v = *(const float4*)(emb2_w + i);
        float4 ww = { rnd_tf32(v.x), rnd_tf32(v.y), rnd_tf32(v.z), rnd_tf32(v.w) };
        *(float4*)(g_wr + i) = ww;
    } else {
        for (int i = t; i < CC*CIN; i += 256) w[i] = emb_w[i];
        if (t < CC) bsm[t] = emb_b[t];
        __syncthreads();
        int idx = blockIdx.x;
        int b = idx & 15;
        int n = ((idx >> 4) & 3) * 256 + t;
        int e0 = (idx >> 6) * 4;
        float xv[CIN];
        const float* xp = x + (size_t)b*CIN*NN + n;
#pragma unroll
        for (int c = 0; c < CIN; c++) xv[c] = xp[(size_t)c*NN];
        float* out = g_h0a + (size_t)b*CC*NN + n;
#pragma unroll
        for (int e = e0; e < e0 + 4; e++) {
            float s = bsm[e];
#pragma unroll
            for (int c = 0; c < CIN; c++) s = fmaf(w[e*CIN + c], xv[c], s);
            float lv = (s > 0.f) ? s : 0.01f*s;
            out[(size_t)e*NN] = rnd_tf32(lv);
        }
    }
}

// ---------------- laplacian d ----------------
__global__ void k_lap_d(const float* __restrict__ graph) {
    int i = blockIdx.x, k = blockIdx.y, t = threadIdx.x;
    const float* row = graph + (size_t)k*NN*NN + (size_t)i*NN;
    float s = 0.f;
    for (int j = t; j < NN; j += 256) s += row[j];
    __shared__ float sh[256];
    sh[t] = s; __syncthreads();
    for (int o = 128; o > 0; o >>= 1) { if (t < o) sh[t] += sh[t+o]; __syncthreads(); }
    if (t == 0) g_d[k*NN + i] = rsqrtf(sh[0] + 1.0f);
}

// ------- 64x64 channel mix; optional fused s1/s2, sq, transposed output,
//         2nd output with row-sum-derived scale (from g_part) -------
__global__ void __launch_bounds__(128)
chanmixD(const float* __restrict__ in, const float* __restrict__ in2,
         const float* __restrict__ in3, const float* __restrict__ in4,
         int reluIn, size_t inBstride, size_t inZoff,
         const float* __restrict__ Wa, const float* __restrict__ ba,
         const float* __restrict__ Wb, const float* __restrict__ bb_,
         int trans, int roundOut, float* __restrict__ out, size_t outBstride,
         float* __restrict__ out2, int scaleFromPart,
         const float* __restrict__ attA, float* __restrict__ s1o,
         float* __restrict__ s2o, float* __restrict__ sqo,
         float* __restrict__ xTo) {
    const int z = blockIdx.z;
    const float* W    = z ? Wb  : Wa;
    const float* bias = z ? bb_ : ba;
    const int b = blockIdx.y, n0 = blockIdx.x * 64;
    __shared__ float Ms[64*PADN];
    __shared__ float Xs[64*PADN];
    __shared__ float redA[8*64];
    __shared__ float redB[8*64];
    __shared__ float a1s[64], a2s[64];
    __shared__ float scInv[64];
    const int tid = threadIdx.x;
    for (int i = tid; i < 64*64; i += 128) {
        int o = i >> 6, k = i & 63;
        Ms[k*PADN + o] = trans ? W[k*64 + o] : W[o*64 + k];
    }
    if (attA) {
        if (tid < 64) a1s[tid] = attA[tid];
        else a2s[tid-64] = attA[tid];
    }
    if (scaleFromPart && tid < 64) {
        float s = 0.f;
#pragma unroll
        for (int j = 0; j < 8; j++) s += g_part[((size_t)b*8 + j)*NN + n0 + tid];
        scInv[tid] = 1.f / s;
    }
    const size_t boff = (size_t)b*inBstride + (size_t)z*inZoff + n0;
    for (int i = tid; i < 64*16; i += 128) {
        int k = i >> 4, n4 = (i & 15) * 4;
        size_t off = boff + (size_t)k*NN + n4;
        float4 v = *(const float4*)(in + off);
        if (in2) { float4 w2 = *(const float4*)(in2 + off); v.x+=w2.x; v.y+=w2.y; v.z+=w2.z; v.w+=w2.w; }
        if (in3) { float4 w3 = *(const float4*)(in3 + off); v.x+=w3.x; v.y+=w3.y; v.z+=w3.z; v.w+=w3.w; }
        if (in4) { float4 w4 = *(const float4*)(in4 + off); v.x+=w4.x; v.y+=w4.y; v.z+=w4.z; v.w+=w4.w; }
        if (reluIn) {
            v.x = fmaxf(v.x, 0.f); v.y = fmaxf(v.y, 0.f);
            v.z = fmaxf(v.z, 0.f); v.w = fmaxf(v.w, 0.f);
        }
        *(float4*)&Xs[k*PADN + n4] = v;
    }
    __syncthreads();
    const int tx = tid & 15, ty = tid >> 4;
    u64 acc[4][4] = {};
#pragma unroll 8
    for (int k = 0; k < 64; k++) {
        const float* mrow = &Ms[k*PADN + ty*8];
        ulonglong2 av0 = *(const ulonglong2*)(mrow);
        ulonglong2 av1 = *(const ulonglong2*)(mrow + 4);
        float4 xv = *(const float4*)&Xs[k*PADN + tx*4];
        u64 gs0 = splat2(xv.x), gs1 = splat2(xv.y), gs2 = splat2(xv.z), gs3 = splat2(xv.w);
        ffma2(acc[0][0], av0.x, gs0); ffma2(acc[0][1], av0.x, gs1);
        ffma2(acc[0][2], av0.x, gs2); ffma2(acc[0][3], av0.x, gs3);
        ffma2(acc[1][0], av0.y, gs0); ffma2(acc[1][1], av0.y, gs1);
        ffma2(acc[1][2], av0.y, gs2); ffma2(acc[1][3], av0.y, gs3);
        ffma2(acc[2][0], av1.x, gs0); ffma2(acc[2][1], av1.x, gs1);
        ffma2(acc[2][2], av1.x, gs2); ffma2(acc[2][3], av1.x, gs3);
        ffma2(acc[3][0], av1.y, gs0); ffma2(acc[3][1], av1.y, gs1);
        ffma2(acc[3][2], av1.y, gs2); ffma2(acc[3][3], av1.y, gs3);
    }
    float* outb = out + (size_t)b*outBstride + (size_t)z*CC*NN + n0;
    float* outb2 = out2 ? out2 + (size_t)b*outBstride + (size_t)z*CC*NN + n0 : nullptr;
    float4 sc = {1.f,1.f,1.f,1.f};
    if (outb2) {
        sc.x = scInv[tx*4]; sc.y = scInv[tx*4+1];
        sc.z = scInv[tx*4+2]; sc.w = scInv[tx*4+3];
    }
    float* xTb = xTo ? xTo + ((size_t)b*NN + n0) * CC : nullptr;
    float4 ps1 = {0.f,0.f,0.f,0.f};
    float4 ps2 = {0.f,0.f,0.f,0.f};
#pragma unroll
    for (int i = 0; i < 4; i++) {
        int o = ty*8 + 2*i;
        float b0 = bias ? bias[o]   : 0.f;
        float b1 = bias ? bias[o+1] : 0.f;
        float2 v0 = unpack2(acc[i][0]), v1 = unpack2(acc[i][1]);
        float2 v2 = unpack2(acc[i][2]), v3 = unpack2(acc[i][3]);
        float4 lo = {v0.x + b0, v1.x + b0, v2.x + b0, v3.x + b0};
        float4 hi = {v0.y + b1, v1.y + b1, v2.y + b1, v3.y + b1};
        if (roundOut) {
            lo.x = rnd_tf32(lo.x); lo.y = rnd_tf32(lo.y);
            lo.z = rnd_tf32(lo.z); lo.w = rnd_tf32(lo.w);
            hi.x = rnd_tf32(hi.x); hi.y = rnd_tf32(hi.y);
            hi.z = rnd_tf32(hi.z); hi.w = rnd_tf32(hi.w);
        }
        if (attA) {
            float a1o = a1s[o], a1o1 = a1s[o+1];
            float a2o = a2s[o], a2o1 = a2s[o+1];
            ps1.x = fmaf(lo.x, a1o, fmaf(hi.x, a1o1, ps1.x));
            ps1.y = fmaf(lo.y, a1o, fmaf(hi.y, a1o1, ps1.y));
            ps1.z = fmaf(lo.z, a1o, fmaf(hi.z, a1o1, ps1.z));
            ps1.w = fmaf(lo.w, a1o, fmaf(hi.w, a1o1, ps1.w));
            ps2.x = fmaf(lo.x, a2o, fmaf(hi.x, a2o1, ps2.x));
            ps2.y = fmaf(lo.y, a2o, fmaf(hi.y, a2o1, ps2.y));
            ps2.z = fmaf(lo.z, a2o, fmaf(hi.z, a2o1, ps2.z));
            ps2.w = fmaf(lo.w, a2o, fmaf(hi.w, a2o1, ps2.w));
        }
        if (sqo) {
            ps1.x = fmaf(lo.x, lo.x, fmaf(hi.x, hi.x, ps1.x));
            ps1.y = fmaf(lo.y, lo.y, fmaf(hi.y, hi.y, ps1.y));
            ps1.z = fmaf(lo.z, lo.z, fmaf(hi.z, hi.z, ps1.z));
            ps1.w = fmaf(lo.w, lo.w, fmaf(hi.w, hi.w, ps1.w));
        }
        *(float4*)(outb + (size_t)o*NN + tx*4) = lo;
        *(float4*)(outb + (size_t)(o+1)*NN + tx*4) = hi;
        if (outb2) {
            float4 lo2 = {rnd_tf32(lo.x*sc.x), rnd_tf32(lo.y*sc.y),
                          rnd_tf32(lo.z*sc.z), rnd_tf32(lo.w*sc.w)};
            float4 hi2 = {rnd_tf32(hi.x*sc.x), rnd_tf32(hi.y*sc.y),
                          rnd_tf32(hi.z*sc.z), rnd_tf32(hi.w*sc.w)};
            *(float4*)(outb2 + (size_t)o*NN + tx*4) = lo2;
            *(float4*)(outb2 + (size_t)(o+1)*NN + tx*4) = hi2;
        }
        if (xTb) {
            const float* plo = &lo.x;
            const float* phi = &hi.x;
#pragma unroll
            for (int q = 0; q < 4; q++) {
                float* row = xTb + (size_t)(tx*4 + q) * CC;
                row[o]   = rnd_tf32(plo[q]);
                row[o+1] = rnd_tf32(phi[q]);
            }
        }
    }
    if (attA || sqo) {
        *(float4*)&redA[ty*64 + tx*4] = ps1;
        if (attA) *(float4*)&redB[ty*64 + tx*4] = ps2;
        __syncthreads();
        if (tid < 64) {
            float sa = 0.f, sb = 0.f;
#pragma unroll
            for (int r = 0; r < 8; r++) {
                sa += redA[r*64 + tid];
                if (attA) sb += redB[r*64 + tid];
            }
            if (attA) {
                s1o[b*NN + n0 + tid] = sa;
                s2o[b*NN + n0 + tid] = sb;
            } else {
                sqo[b*NN + n0 + tid] = sa;
            }
        }
    }
}

// ---------------- attention row max + inv-sum ----------------
__global__ void k_attinv() {
    int b = blockIdx.y, t = threadIdx.x;
    const float* s2 = g_s2 + b*NN;
    __shared__ float sh[256];
    float mx = fmaxf(fmaxf(s2[t], s2[t+256]), fmaxf(s2[t+512], s2[t+768]));
    sh[t] = mx; __syncthreads();
    for (int o = 128; o > 0; o >>= 1) { if (t < o) sh[t] = fmaxf(sh[t], sh[t+o]); __syncthreads(); }
    float mxs2 = sh[0];

    int row = blockIdx.x * 8 + (t >> 5);
    int lane = t & 31;
    float s1v = g_s1[b*NN + row];
    float m = s1v + mxs2;
    m = (m > 0.f) ? m : 0.01f * m;
    float sum = 0.f;
    for (int j = lane; j < NN; j += 32) {
        float e = s1v + s2[j];
        e = (e > 0.f) ? e : 0.01f * e;
        sum += __expf(e - m);
    }
#pragma unroll
    for (int o = 16; o > 0; o >>= 1) sum += __shfl_down_sync(0xffffffffu, sum, o);
    if (lane == 0) {
        g_amx [b*NN + row] = m;
        g_ainv[b*NN + row] = 1.f / sum;
    }
}

// ---------------- layernorm stats + final fuse ----------------
__global__ void k_lnstats() {
    int b = blockIdx.x, path = blockIdx.y, t = threadIdx.x;
    size_t base = (size_t)b*(2*CC)*NN + (size_t)path*CC*NN;
    float s = 0.f, ss = 0.f;
    for (int i = t; i < CC*NN; i += 1024) {
        float v = g_sxa[base + i] + g_sxb[base + i];
        s += v; ss = fmaf(v, v, ss);
    }
    __shared__ float shs[1024], shq[1024];
    shs[t] = s; shq[t] = ss; __syncthreads();
    for (int o = 512; o > 0; o >>= 1) {
        if (t < o) { shs[t] += shs[t+o]; shq[t] += shq[t+o]; }
        __syncthreads();
    }
    if (t == 0) {
        float mean = shs[0] * (1.f/65536.f);
        float var  = shq[0] * (1.f/65536.f) - mean*mean;
        g_stats[(path*BB + b)*2 + 0] = mean;
        g_stats[(path*BB + b)*2 + 1] = rsqrtf(var + 1e-5f);
    }
}

__global__ void k_final(const float* __restrict__ ct, const float* __restrict__ ln_w,
                        const float* __restrict__ ln_b, float* __restrict__ out) {
    size_t idx = (size_t)blockIdx.x * 256 + threadIdx.x;
    int b  = (int)(idx / (CC*NN));
    int cn = (int)(idx % (CC*NN));
    float m1 = g_stats[b*2 + 0],            r1 = g_stats[b*2 + 1];
    float m2 = g_stats[(BB + b)*2 + 0],     r2 = g_stats[(BB + b)*2 + 1];
    float w = ln_w[cn], bb = ln_b[cn];
    size_t base = (size_t)b*(2*CC)*NN + cn;
    float z1v = g_sxa[base] + g_sxb[base];
    float z2v = g_sxa[base + (size_t)CC*NN] + g_sxb[base + (size_t)CC*NN];
    float xnew = (z1v - m1) * r1 * w + bb;
    float z2   = (z2v - m2) * r2 * w + bb;
    float ft = 0.5f * z2 * (1.f + erff(z2 * 0.70710678118654752f));
    float ctv = ct[idx];
    float ctn = xnew + ft * (ctv - xnew);
    float el  = (ctn > 0.f) ? ctn : expm1f(ctn);
    float xu  = g_xuai[idx];
    float ht  = xu + ft * (el - xu);
    out[idx] = ht;
    out[(size_t)BB*CC*NN + idx] = ctn;
}

// ---------------- host launch ----------------
struct DevPtrs {
    float *gl, *g1, *g2, *wr, *h0a, *hT, *xuai, *xuaiT;
    float *pa, *pb, *pc, *pd;
    float *l12, *l12s, *t12a, *t12b, *u12, *a12a, *a12b, *sxa, *sxb;
    float *s1, *s2, *sq;
    bool init;
};
static DevPtrs P = {};
static const int GRAM_SMEM = 2 * 128 * GSTRIDE_W * 4;

static void init_ptrs() {
    if (P.init) return;
    void* p;
#define GET(sym, field) cudaGetSymbolAddress(&p, sym); P.field = (float*)p;
    GET(g_gl, gl)   GET(g_g1, g1)   GET(g_g2, g2)
    GET(g_wr, wr)    GET(g_h0a, h0a) GET(g_hT, hT)
    GET(g_xuai, xuai) GET(g_xuaiT, xuaiT)
    GET(g_pa, pa)    GET(g_pb, pb)   GET(g_pc, pc)   GET(g_pd, pd)
    GET(g_l12, l12)  GET(g_l12s, l12s)
    GET(g_t12a, t12a) GET(g_t12b, t12b) GET(g_u12, u12)
    GET(g_a12a, a12a) GET(g_a12b, a12b) GET(g_sxa, sxa) GET(g_sxb, sxb)
    GET(g_s1, s1) GET(g_s2, s2) GET(g_sq, sq)
#undef GET
    cudaFuncSetAttribute(k_gram_mma, cudaFuncAttributeMaxDynamicSharedMemorySize, GRAM_SMEM);
    P.init = true;
}

extern "C" void kernel_launch(void* const* d_in, const int* in_sizes, int n_in,
                              void* d_out, int out_size) {
    const float* x      = (const float*)d_in[0];
    const float* ct     = (const float*)d_in[1];
    const float* graph  = (const float*)d_in[2];
    const float* emb_w  = (const float*)d_in[3];
    const float* emb_b  = (const float*)d_in[4];
    const float* emb2_w = (const float*)d_in[5];
    const float* emb2_b = (const float*)d_in[6];
    const float* att_W  = (const float*)d_in[7];
    const float* att_a  = (const float*)d_in[8];
    // d_in[9] = att_GL : unused (softmax output strictly positive => mask no-op)
    const float* uai_w  = (const float*)d_in[10];
    const float* uai_b  = (const float*)d_in[11];
    const float* lin1_w = (const float*)d_in[12];
    const float* lin2_w = (const float*)d_in[13];
    const float* lin2_b = (const float*)d_in[14];
    const float* ln_w   = (const float*)d_in[15];
    const float* ln_b   = (const float*)d_in[16];
    float* out = (float*)d_out;

    init_ptrs();

    const size_t GLSTRIDE = (size_t)NN * NN;
    const size_t SB = (size_t)CC * NN;
    const size_t DB = (size_t)2 * CC * NN;
    const dim3 gridC1(NN/64, BB, 1);
    const dim3 gridC2(NN/64, BB, 2);

    // laplacian d, then combined prep (lapT + wround + emb1)
    k_lap_d<<<dim3(NN, 2), 256>>>(graph);
    k_prep <<<dim3(1024, 4), 256>>>(graph, emb2_w, x, emb_w, emb_b);

    // embedding GEMM
    mma_gemm<<<dim3(8, BB/2, 4), 256>>>(P.h0a, DB, 128, P.wr, 0, 4,
                                        nullptr, nullptr, emb2_b,
                                        P.pa, P.pb, P.pc, P.pd, DB);

    // attention: hT chanmix with fused s1/s2 rank-1 scores
    chanmixD<<<gridC1, 128>>>(P.pa, P.pb, P.pc, P.pd, 0, SB, 0,
                              att_W, nullptr, att_W, nullptr, 1, 1, P.hT, SB,
                              nullptr, 0, att_a, P.s1, P.s2, nullptr, nullptr);
    k_attinv<<<dim3(NN/8, BB), 256>>>();
    mma_gemm_att<<<dim3(8, BB, 2), 256>>>(P.hT, SB, P.pa, P.pb, SB);

    // UAI chanmix with fused sumsq + transposed/rounded copy for gram
    chanmixD<<<gridC1, 128>>>(P.pa, P.pb, nullptr, nullptr, 1, SB, 0,
                              uai_w, uai_b, uai_w, uai_b, 0, 0, P.xuai, SB,
                              nullptr, 0, nullptr, nullptr, nullptr, P.sq, P.xuaiT);

    // learned adjacency: tensor-core gram + fused row partials
    k_gram_mma<<<dim3(8, 8, BB), 256, GRAM_SMEM>>>();

    // l1/l2 stacked propagation; rsinv derived from g_part in-block
    chanmixD<<<gridC2, 128>>>(P.xuai, nullptr, nullptr, nullptr, 0, SB, 0,
                              lin1_w, nullptr, lin2_w, lin2_b, 0, 1, P.l12, DB,
                              P.l12s, 1, nullptr, nullptr, nullptr, nullptr, nullptr);

    // merged: unit0 l12s@gl -> a12a/b ; unit1 l12@g1 -> t12a/b
    mma_gemm2<<<dim3(8, BB, 4), 256>>>(P.l12s, P.gl, GLSTRIDE,
                                       P.l12, P.g1, 0,
                                       P.a12a, P.a12b, P.t12a, P.t12b, DB);

    chanmixD<<<gridC2, 128>>>(P.t12a, P.t12b, nullptr, nullptr, 0, DB, SB,
                              lin1_w, nullptr, lin2_w, lin2_b, 0, 1, P.u12, DB,
                              nullptr, 0, nullptr, nullptr, nullptr, nullptr, nullptr);

    mma_gemm<<<dim3(8, BB, 2), 256>>>(P.u12, DB, 128, P.g2, 0, 2,
                                      P.a12a, P.a12b, nullptr,
                                      P.sxa, P.sxb, nullptr, nullptr, DB);

    // layernorm + gates + output
    k_lnstats<<<dim3(BB, 2), 1024>>>();
    k_final  <<<(BB*CC*NN)/256, 256>>>(ct, ln_w, ln_b, out);
}